// round 2
// baseline (speedup 1.0000x reference)
#include <cuda_runtime.h>

#define SQ  2048
#define NB  2
#define DM  1024
#define NH  16
#define DKH 64
#define MR  (SQ*NB)   // 4096 rows for [S,B,*] matrices

// ---------------- scratch (device globals: allocation-free) ----------------
__device__ float g_Q[(size_t)NB*NH*SQ*DKH];     // [B,H,S,dk] 16.8 MB
__device__ float g_K[(size_t)NB*NH*SQ*DKH];
__device__ float g_V[(size_t)NB*NH*SQ*DKH];
__device__ float g_P[(size_t)NB*NH*SQ*SQ];      // [B,H,S,S]  536.9 MB
__device__ float g_ctx[(size_t)MR*DM];          // [S,B,D]    16.8 MB

// ============================================================================
// TN SGEMM: C = alpha * A(MxK) * B(NxK)^T, both row-major K-contiguous.
// 128x128 block tile, BK=16, 256 threads, 8x8 per thread, double-buffered smem.
// SCATTER=0: C row-major [M,N] (plus batch stride sC)
// SCATTER=1: scatter n->(h,dk), m->(s,b) into [B,H,S,dk]  (QKV projections)
// ============================================================================
template<int SCATTER>
__global__ void __launch_bounds__(256)
gemm_tn(const float* __restrict__ A, const float* __restrict__ Bm,
        float* __restrict__ C, int K, int N, float alpha,
        size_t sA, size_t sB, size_t sC)
{
    __shared__ __align__(16) float As[2][16][132];
    __shared__ __align__(16) float Bs[2][16][132];

    const int t  = threadIdx.x;
    const int z  = blockIdx.z;
    A  += (size_t)z * sA;
    Bm += (size_t)z * sB;
    C  += (size_t)z * sC;

    const int m0 = blockIdx.y * 128;
    const int n0 = blockIdx.x * 128;
    const int lrow = t >> 1;          // 0..127 tile row loaded by this thread
    const int lc8  = (t & 1) * 8;     // 0 or 8: which 8 k's of the 16-wide tile
    const int ty   = t >> 4;          // 0..15 -> output rows ty*8..+7
    const int tx   = t & 15;          // 0..15 -> output cols tx*8..+7

    const float* Ag = A  + (size_t)(m0 + lrow) * K + lc8;
    const float* Bg = Bm + (size_t)(n0 + lrow) * K + lc8;

    float acc[8][8];
    #pragma unroll
    for (int i = 0; i < 8; i++)
        #pragma unroll
        for (int j = 0; j < 8; j++) acc[i][j] = 0.f;

    const int nk = K >> 4;

    // prologue: tile 0 -> buffer 0
    {
        float4 a0 = *(const float4*)(Ag + 0);
        float4 a1 = *(const float4*)(Ag + 4);
        float4 b0 = *(const float4*)(Bg + 0);
        float4 b1 = *(const float4*)(Bg + 4);
        #pragma unroll
        for (int j = 0; j < 4; j++) {
            As[0][lc8 + j    ][lrow] = ((const float*)&a0)[j];
            As[0][lc8 + 4 + j][lrow] = ((const float*)&a1)[j];
            Bs[0][lc8 + j    ][lrow] = ((const float*)&b0)[j];
            Bs[0][lc8 + 4 + j][lrow] = ((const float*)&b1)[j];
        }
    }
    __syncthreads();

    for (int kt = 0; kt < nk; kt++) {
        const int  cur = kt & 1;
        const bool hasnext = (kt + 1 < nk);
        float4 a0, a1, b0, b1;
        if (hasnext) {
            const float* ap = Ag + (kt + 1) * 16;
            const float* bp = Bg + (kt + 1) * 16;
            a0 = *(const float4*)(ap);
            a1 = *(const float4*)(ap + 4);
            b0 = *(const float4*)(bp);
            b1 = *(const float4*)(bp + 4);
        }
        #pragma unroll
        for (int k = 0; k < 16; k++) {
            float4 xa0 = *(const float4*)&As[cur][k][ty * 8];
            float4 xa1 = *(const float4*)&As[cur][k][ty * 8 + 4];
            float4 xb0 = *(const float4*)&Bs[cur][k][tx * 8];
            float4 xb1 = *(const float4*)&Bs[cur][k][tx * 8 + 4];
            float av[8] = {xa0.x, xa0.y, xa0.z, xa0.w, xa1.x, xa1.y, xa1.z, xa1.w};
            float bv[8] = {xb0.x, xb0.y, xb0.z, xb0.w, xb1.x, xb1.y, xb1.z, xb1.w};
            #pragma unroll
            for (int i = 0; i < 8; i++)
                #pragma unroll
                for (int j = 0; j < 8; j++)
                    acc[i][j] = fmaf(av[i], bv[j], acc[i][j]);
        }
        if (hasnext) {
            const int nb2 = cur ^ 1;
            #pragma unroll
            for (int j = 0; j < 4; j++) {
                As[nb2][lc8 + j    ][lrow] = ((const float*)&a0)[j];
                As[nb2][lc8 + 4 + j][lrow] = ((const float*)&a1)[j];
                Bs[nb2][lc8 + j    ][lrow] = ((const float*)&b0)[j];
                Bs[nb2][lc8 + 4 + j][lrow] = ((const float*)&b1)[j];
            }
        }
        __syncthreads();
    }

    // epilogue
    if (SCATTER == 0) {
        #pragma unroll
        for (int i = 0; i < 8; i++) {
            const int m = m0 + ty * 8 + i;
            float* cp = C + (size_t)m * N + n0 + tx * 8;
            float4 r0, r1;
            r0.x = acc[i][0]*alpha; r0.y = acc[i][1]*alpha;
            r0.z = acc[i][2]*alpha; r0.w = acc[i][3]*alpha;
            r1.x = acc[i][4]*alpha; r1.y = acc[i][5]*alpha;
            r1.z = acc[i][6]*alpha; r1.w = acc[i][7]*alpha;
            *(float4*)(cp)     = r0;
            *(float4*)(cp + 4) = r1;
        }
    } else {
        // n -> (h, dk), m -> (s, b); write to [B,H,S,dk]
        const int n  = n0 + tx * 8;
        const int h  = n >> 6;
        const int dk = n & 63;
        #pragma unroll
        for (int i = 0; i < 8; i++) {
            const int m = m0 + ty * 8 + i;
            const int s = m >> 1;
            const int b = m & 1;
            float* cp = C + (((size_t)(b * NH + h) * SQ + s) * DKH + dk);
            float4 r0, r1;
            r0.x = acc[i][0]*alpha; r0.y = acc[i][1]*alpha;
            r0.z = acc[i][2]*alpha; r0.w = acc[i][3]*alpha;
            r1.x = acc[i][4]*alpha; r1.y = acc[i][5]*alpha;
            r1.z = acc[i][6]*alpha; r1.w = acc[i][7]*alpha;
            *(float4*)(cp)     = r0;
            *(float4*)(cp + 4) = r1;
        }
    }
}

// ============================================================================
// Row softmax in-place over last dim (SQ=2048). One block (256 thr) per row.
// ============================================================================
__global__ void __launch_bounds__(256)
softmax_kernel(float* __restrict__ P)
{
    const size_t base = (size_t)blockIdx.x * SQ;
    const int t = threadIdx.x;
    float v[8];
    float mx = -3.4e38f;
    #pragma unroll
    for (int i = 0; i < 8; i++) {
        v[i] = P[base + t + i * 256];
        mx = fmaxf(mx, v[i]);
    }
    __shared__ float red[256];
    red[t] = mx;
    __syncthreads();
    #pragma unroll
    for (int s2 = 128; s2 > 0; s2 >>= 1) {
        if (t < s2) red[t] = fmaxf(red[t], red[t + s2]);
        __syncthreads();
    }
    mx = red[0];
    __syncthreads();
    float sum = 0.f;
    #pragma unroll
    for (int i = 0; i < 8; i++) {
        v[i] = __expf(v[i] - mx);
        sum += v[i];
    }
    red[t] = sum;
    __syncthreads();
    #pragma unroll
    for (int s2 = 128; s2 > 0; s2 >>= 1) {
        if (t < s2) red[t] += red[t + s2];
        __syncthreads();
    }
    const float inv = 1.0f / red[0];
    #pragma unroll
    for (int i = 0; i < 8; i++)
        P[base + t + i * 256] = v[i] * inv;
}

// ============================================================================
// ctx = P(SxS) @ V(Sxdk) per (b,h); writes ctx as [S,B,D] at [s][b][h*64+dk].
// 128x64 block tile, BK=16, 256 threads, 8x4 per thread, double buffered.
// ============================================================================
__global__ void __launch_bounds__(256)
pv_gemm(const float* __restrict__ P, const float* __restrict__ V,
        float* __restrict__ C)
{
    __shared__ __align__(16) float Ps[2][16][132];
    __shared__ __align__(16) float Vs[2][16][64];

    const int t = threadIdx.x;
    const int z = blockIdx.z;
    const int b = z >> 4;
    const int h = z & 15;
    P += (size_t)z * SQ * SQ;
    V += (size_t)z * SQ * DKH;

    const int q0   = blockIdx.y * 128;
    const int lrow = t >> 1;
    const int lc8  = (t & 1) * 8;
    const int vrow = t >> 4;          // 0..15 (k row of V tile)
    const int vc4  = (t & 15) * 4;    // 0..60
    const int ty   = t >> 4;          // output rows ty*8..+7
    const int tx   = t & 15;          // output cols tx*4..+3

    const float* Pg = P + (size_t)(q0 + lrow) * SQ + lc8;
    const float* Vg = V + (size_t)vrow * DKH + vc4;

    float acc[8][4];
    #pragma unroll
    for (int i = 0; i < 8; i++)
        #pragma unroll
        for (int j = 0; j < 4; j++) acc[i][j] = 0.f;

    const int nk = SQ >> 4;   // 128 k-tiles

    {
        float4 a0 = *(const float4*)(Pg + 0);
        float4 a1 = *(const float4*)(Pg + 4);
        float4 v0 = *(const float4*)(Vg);
        #pragma unroll
        for (int j = 0; j < 4; j++) {
            Ps[0][lc8 + j    ][lrow] = ((const float*)&a0)[j];
            Ps[0][lc8 + 4 + j][lrow] = ((const float*)&a1)[j];
        }
        *(float4*)&Vs[0][vrow][vc4] = v0;
    }
    __syncthreads();

    for (int kt = 0; kt < nk; kt++) {
        const int  cur = kt & 1;
        const bool hasnext = (kt + 1 < nk);
        float4 a0, a1, v0;
        if (hasnext) {
            const float* ap = Pg + (kt + 1) * 16;
            const float* vp = Vg + (size_t)(kt + 1) * 16 * DKH;
            a0 = *(const float4*)(ap);
            a1 = *(const float4*)(ap + 4);
            v0 = *(const float4*)(vp);
        }
        #pragma unroll
        for (int k = 0; k < 16; k++) {
            float4 xa0 = *(const float4*)&Ps[cur][k][ty * 8];
            float4 xa1 = *(const float4*)&Ps[cur][k][ty * 8 + 4];
            float4 xb  = *(const float4*)&Vs[cur][k][tx * 4];
            float av[8] = {xa0.x, xa0.y, xa0.z, xa0.w, xa1.x, xa1.y, xa1.z, xa1.w};
            float bv[4] = {xb.x, xb.y, xb.z, xb.w};
            #pragma unroll
            for (int i = 0; i < 8; i++)
                #pragma unroll
                for (int j = 0; j < 4; j++)
                    acc[i][j] = fmaf(av[i], bv[j], acc[i][j]);
        }
        if (hasnext) {
            const int nb2 = cur ^ 1;
            #pragma unroll
            for (int j = 0; j < 4; j++) {
                Ps[nb2][lc8 + j    ][lrow] = ((const float*)&a0)[j];
                Ps[nb2][lc8 + 4 + j][lrow] = ((const float*)&a1)[j];
            }
            *(float4*)&Vs[nb2][vrow][vc4] = v0;
        }
        __syncthreads();
    }

    #pragma unroll
    for (int i = 0; i < 8; i++) {
        const int q = q0 + ty * 8 + i;
        float4 r;
        r.x = acc[i][0]; r.y = acc[i][1]; r.z = acc[i][2]; r.w = acc[i][3];
        *(float4*)(C + ((size_t)q * NB + b) * DM + h * DKH + tx * 4) = r;
    }
}

// ============================================================================
// mean over heads: out[b,q,k] = (1/H) * sum_h P[b,h,q,k]. One block per (b,q).
// ============================================================================
__global__ void __launch_bounds__(256)
mean_kernel(const float* __restrict__ P, float* __restrict__ outMean)
{
    const int bq = blockIdx.x;       // 0 .. NB*SQ-1
    const int b  = bq >> 11;         // / SQ
    const int q  = bq & (SQ - 1);
    const int t  = threadIdx.x;
    float acc[8];
    #pragma unroll
    for (int i = 0; i < 8; i++) acc[i] = 0.f;
    for (int h = 0; h < NH; h++) {
        const float* p = P + (((size_t)(b * NH + h) * SQ + q) * SQ);
        #pragma unroll
        for (int i = 0; i < 8; i++) acc[i] += p[t + i * 256];
    }
    float* o = outMean + (size_t)bq * SQ;
    #pragma unroll
    for (int i = 0; i < 8; i++) o[t + i * 256] = acc[i] * (1.0f / NH);
}

// ============================================================================
extern "C" void kernel_launch(void* const* d_in, const int* in_sizes, int n_in,
                              void* d_out, int out_size)
{
    (void)in_sizes; (void)n_in; (void)out_size;
    const float* q  = (const float*)d_in[0];
    const float* k  = (const float*)d_in[1];
    const float* v  = (const float*)d_in[2];
    const float* Wq = (const float*)d_in[3];
    const float* Wk = (const float*)d_in[4];
    const float* Wv = (const float*)d_in[5];
    const float* Wo = (const float*)d_in[6];
    float* out     = (float*)d_out;
    float* outMean = out + (size_t)MR * DM;

    void *pQ, *pK, *pV, *pP, *pC;
    cudaGetSymbolAddress(&pQ, g_Q);
    cudaGetSymbolAddress(&pK, g_K);
    cudaGetSymbolAddress(&pV, g_V);
    cudaGetSymbolAddress(&pP, g_P);
    cudaGetSymbolAddress(&pC, g_ctx);

    const dim3 thr(256);

    // 1) QKV projections: [4096,1024] x [1024,1024]^T -> scatter [B,H,S,dk]
    const dim3 gproj(DM / 128, MR / 128, 1);
    gemm_tn<1><<<gproj, thr>>>(q, Wq, (float*)pQ, DM, DM, 1.0f, 0, 0, 0);
    gemm_tn<1><<<gproj, thr>>>(k, Wk, (float*)pK, DM, DM, 1.0f, 0, 0, 0);
    gemm_tn<1><<<gproj, thr>>>(v, Wv, (float*)pV, DM, DM, 1.0f, 0, 0, 0);

    // 2) scores: per (b,h)  P = (Q K^T) / sqrt(dk)
    const dim3 gsc(SQ / 128, SQ / 128, NB * NH);
    gemm_tn<0><<<gsc, thr>>>((const float*)pQ, (const float*)pK, (float*)pP,
                             DKH, SQ, 0.125f,
                             (size_t)SQ * DKH, (size_t)SQ * DKH,
                             (size_t)SQ * SQ);

    // 3) softmax rows in place
    softmax_kernel<<<NB * NH * SQ, thr>>>((float*)pP);

    // 4) ctx = P @ V  -> [S,B,D]
    const dim3 gpv(1, SQ / 128, NB * NH);
    pv_gemm<<<gpv, thr>>>((const float*)pP, (const float*)pV, (float*)pC);

    // 5) mean over heads -> second output region
    mean_kernel<<<NB * SQ, thr>>>((const float*)pP, outMean);

    // 6) out = ctx @ Wo^T  -> [S,B,D] row-major == [4096,1024]
    gemm_tn<0><<<gproj, thr>>>((const float*)pC, Wo, out, DM, DM, 1.0f, 0, 0, 0);
}

// round 5
// speedup vs baseline: 2.0199x; 2.0199x over previous
#include <cuda_runtime.h>
#include <cuda_bf16.h>
#include <cstdint>

#define SQ  2048
#define NB  2
#define DM  1024
#define NH  16
#define DKH 64
#define MR  4096              // S*B rows
#define NZ  (NB*NH)           // 32 batch*head slices

// ---------------------------------------------------------------------------
// Scratch (__device__ globals: allocation-free)
// ---------------------------------------------------------------------------
__device__ __nv_bfloat16 g_qh[(size_t)MR*DM], g_ql[(size_t)MR*DM];
__device__ __nv_bfloat16 g_kh[(size_t)MR*DM], g_kl[(size_t)MR*DM];
__device__ __nv_bfloat16 g_vh[(size_t)MR*DM], g_vl[(size_t)MR*DM];
__device__ __nv_bfloat16 g_wqh[(size_t)DM*DM], g_wql[(size_t)DM*DM];
__device__ __nv_bfloat16 g_wkh[(size_t)DM*DM], g_wkl[(size_t)DM*DM];
__device__ __nv_bfloat16 g_wvh[(size_t)DM*DM], g_wvl[(size_t)DM*DM];
__device__ __nv_bfloat16 g_woh[(size_t)DM*DM], g_wol[(size_t)DM*DM];
__device__ __nv_bfloat16 g_Qh[(size_t)NZ*SQ*DKH], g_Ql[(size_t)NZ*SQ*DKH];
__device__ __nv_bfloat16 g_Kh[(size_t)NZ*SQ*DKH], g_Kl[(size_t)NZ*SQ*DKH];
__device__ __nv_bfloat16 g_Vsh[(size_t)NZ*SQ*DKH], g_Vsl[(size_t)NZ*SQ*DKH]; // [Z,S,dk]
__device__ __nv_bfloat16 g_Vth[(size_t)NZ*DKH*SQ], g_Vtl[(size_t)NZ*DKH*SQ]; // [Z,dk,S]
__device__ float         g_P [(size_t)NZ*SQ*SQ];                              // 537 MB
__device__ __nv_bfloat16 g_Ph[(size_t)NZ*SQ*SQ], g_Pl[(size_t)NZ*SQ*SQ];      // 268+268 MB
__device__ __nv_bfloat16 g_ch[(size_t)MR*DM],    g_cl[(size_t)MR*DM];

// ---------------------------------------------------------------------------
// PTX helpers (base-arch only: mma.sync / ldmatrix / cp.async)
// ---------------------------------------------------------------------------
__device__ __forceinline__ uint32_t smem_u32(const void* p) {
    uint32_t a;
    asm("{ .reg .u64 t; cvta.to.shared.u64 t, %1; cvt.u32.u64 %0, t; }" : "=r"(a) : "l"(p));
    return a;
}
__device__ __forceinline__ void cp16(uint32_t d, const void* s) {
    asm volatile("cp.async.cg.shared.global [%0], [%1], 16;" :: "r"(d), "l"(s));
}
__device__ __forceinline__ void cp_commit() {
    asm volatile("cp.async.commit_group;" ::: "memory");
}
__device__ __forceinline__ void cp_wait1() {
    asm volatile("cp.async.wait_group 1;" ::: "memory");
}
__device__ __forceinline__ void cp_wait0() {
    asm volatile("cp.async.wait_group 0;" ::: "memory");
}
#define LDMX4(r, a) \
    asm volatile("ldmatrix.sync.aligned.m8n8.x4.shared.b16 {%0,%1,%2,%3}, [%4];" \
        : "=r"((r)[0]), "=r"((r)[1]), "=r"((r)[2]), "=r"((r)[3]) : "r"(a))

__device__ __forceinline__ void mma_bf16(float* c, const uint32_t* a, const uint32_t* b) {
    asm volatile(
        "mma.sync.aligned.m16n8k16.row.col.f32.bf16.bf16.f32 "
        "{%0,%1,%2,%3},{%4,%5,%6,%7},{%8,%9},{%0,%1,%2,%3};"
        : "+f"(c[0]), "+f"(c[1]), "+f"(c[2]), "+f"(c[3])
        : "r"(a[0]), "r"(a[1]), "r"(a[2]), "r"(a[3]), "r"(b[0]), "r"(b[1]));
}

// ---------------------------------------------------------------------------
// Split-bf16 HMMA GEMM: C = alpha * A(MxK) * B(NxK)^T
// A,B row-major K-contiguous, (hi, lo) bf16 pairs; 3 MMAs per pair (drop lo*lo).
// EPI: 0 = fp32 row-major (ldc, z*sC)
//      2 = split scatter to [B,H,S,dk]  (projections: m->(s,b), n->(h,dk))
//      3 = split ctx write to [S,B,D]   (PV: row m, col h*64+n, b from z)
// Layout: 256 thr = 8 warps. Smem tiles padded to 72 bf16/row (144B, conflict-free).
// Double-buffered K-chunks of 64 via cp.async.
// ---------------------------------------------------------------------------
template<int BM, int BN, int EPI>
__global__ void __launch_bounds__(256)
hm_gemm(const __nv_bfloat16* __restrict__ Ah, const __nv_bfloat16* __restrict__ Al,
        const __nv_bfloat16* __restrict__ Bh, const __nv_bfloat16* __restrict__ Bl,
        float* __restrict__ Cf, __nv_bfloat16* __restrict__ Ch, __nv_bfloat16* __restrict__ Cl,
        int K, int ldc, float alpha, size_t sA, size_t sB, size_t sC)
{
    extern __shared__ __align__(16) char smem[];
    const uint32_t sb = smem_u32(smem);
    const int tid  = threadIdx.x;
    const int lane = tid & 31;
    const int wid  = tid >> 5;
    const int z    = blockIdx.z;
    const int m0   = blockIdx.y * BM;
    const int n0   = blockIdx.x * BN;

    constexpr int WGM = (BN == 128) ? 2 : 4;       // warps along M
    constexpr int TM  = BM / WGM;                  // 64 or 32
    constexpr int TN  = BN / (8 / WGM);            // 32
    constexpr int MT  = TM / 16;                   // 4 or 2
    constexpr int NT  = TN / 8;                    // 4
    constexpr int STAGE = (2 * BM + 2 * BN) * 144; // bytes per stage (hi+lo, A+B)

    const int wm = wid % WGM, wn = wid / WGM;
    const int mbase = wm * TM, nbase = wn * TN;

    Ah += (size_t)z * sA + (size_t)m0 * K;
    Al += (size_t)z * sA + (size_t)m0 * K;
    Bh += (size_t)z * sB + (size_t)n0 * K;
    Bl += (size_t)z * sB + (size_t)n0 * K;

    float acc[MT][NT][4];
    #pragma unroll
    for (int i = 0; i < MT; i++)
        #pragma unroll
        for (int j = 0; j < NT; j++)
            #pragma unroll
            for (int r = 0; r < 4; r++) acc[i][j][r] = 0.f;

    // ldmatrix per-lane address components
    const int a_r = lane & 15;                 // row within 16-row tile
    const int a_c = ((lane >> 4) & 1) << 3;    // k half
    const int b_r = (lane & 7) + (((lane >> 4) & 1) << 3);  // n row within 16
    const int b_c = ((lane >> 3) & 1) << 3;    // k half

    auto load_stage = [&](int kc, int stg) {
        const uint32_t base = sb + (uint32_t)stg * STAGE;
        #pragma unroll
        for (int idx = tid; idx < BM * 8; idx += 256) {
            const int r = idx >> 3, ch = idx & 7;
            const uint32_t d = base + (uint32_t)r * 144 + ch * 16;
            cp16(d,            Ah + (size_t)r * K + kc + ch * 8);
            cp16(d + BM * 144, Al + (size_t)r * K + kc + ch * 8);
        }
        #pragma unroll
        for (int idx = tid; idx < BN * 8; idx += 256) {
            const int r = idx >> 3, ch = idx & 7;
            const uint32_t d = base + 2 * BM * 144 + (uint32_t)r * 144 + ch * 16;
            cp16(d,            Bh + (size_t)r * K + kc + ch * 8);
            cp16(d + BN * 144, Bl + (size_t)r * K + kc + ch * 8);
        }
    };

    auto compute = [&](int stg) {
        const uint32_t sA0 = sb + (uint32_t)stg * STAGE;
        const uint32_t sAl = sA0 + BM * 144;
        const uint32_t sB0 = sA0 + 2 * BM * 144;
        const uint32_t sBl = sB0 + BN * 144;
        #pragma unroll
        for (int ks = 0; ks < 4; ks++) {
            uint32_t ah[MT][4], al2[MT][4], bh[NT][2], bl2[NT][2];
            #pragma unroll
            for (int mt = 0; mt < MT; mt++) {
                const uint32_t off = ((uint32_t)(mbase + mt * 16 + a_r) * 72 + ks * 16 + a_c) * 2;
                LDMX4(ah[mt],  sA0 + off);
                LDMX4(al2[mt], sAl + off);
            }
            #pragma unroll
            for (int np = 0; np < NT / 2; np++) {
                const uint32_t off = ((uint32_t)(nbase + np * 16 + b_r) * 72 + ks * 16 + b_c) * 2;
                uint32_t r4[4];
                LDMX4(r4, sB0 + off);
                bh[np*2][0] = r4[0]; bh[np*2][1] = r4[1];
                bh[np*2+1][0] = r4[2]; bh[np*2+1][1] = r4[3];
                LDMX4(r4, sBl + off);
                bl2[np*2][0] = r4[0]; bl2[np*2][1] = r4[1];
                bl2[np*2+1][0] = r4[2]; bl2[np*2+1][1] = r4[3];
            }
            #pragma unroll
            for (int mt = 0; mt < MT; mt++)
                #pragma unroll
                for (int nt = 0; nt < NT; nt++) {
                    mma_bf16(acc[mt][nt], ah[mt],  bh[nt]);
                    mma_bf16(acc[mt][nt], ah[mt],  bl2[nt]);
                    mma_bf16(acc[mt][nt], al2[mt], bh[nt]);
                }
        }
    };

    const int NC = K >> 6;
    load_stage(0, 0);
    cp_commit();

    for (int c = 0; c < NC; c++) {
        const int buf = c & 1;
        if (c + 1 < NC) {
            load_stage((c + 1) << 6, buf ^ 1);
            cp_commit();
            cp_wait1();
        } else {
            cp_wait0();
        }
        __syncthreads();
        compute(buf);
        __syncthreads();
    }

    // ---- epilogue: frags -> smem (coalesce) -> gmem ----
    constexpr int CP = BN + 4;           // fp32 pitch
    float* Cs = (float*)smem;
    const int g = lane >> 2, tg = lane & 3;
    #pragma unroll
    for (int mt = 0; mt < MT; mt++)
        #pragma unroll
        for (int nt = 0; nt < NT; nt++) {
            const int row = mbase + mt * 16 + g;
            const int col = nbase + nt * 8 + tg * 2;
            *(float2*)&Cs[(size_t)row * CP + col]       = make_float2(acc[mt][nt][0], acc[mt][nt][1]);
            *(float2*)&Cs[(size_t)(row + 8) * CP + col] = make_float2(acc[mt][nt][2], acc[mt][nt][3]);
        }
    __syncthreads();

    for (int i4 = tid * 4; i4 < BM * BN; i4 += 1024) {
        const int row = i4 / BN, col = i4 % BN;
        float4 v = *(const float4*)&Cs[(size_t)row * CP + col];
        v.x *= alpha; v.y *= alpha; v.z *= alpha; v.w *= alpha;
        const int m = m0 + row, n = n0 + col;
        if (EPI == 0) {
            *(float4*)&Cf[(size_t)z * sC + (size_t)m * ldc + n] = v;
        } else {
            __nv_bfloat16 h0 = __float2bfloat16(v.x), h1 = __float2bfloat16(v.y);
            __nv_bfloat16 h2 = __float2bfloat16(v.z), h3 = __float2bfloat16(v.w);
            __nv_bfloat16 l0 = __float2bfloat16(v.x - __bfloat162float(h0));
            __nv_bfloat16 l1 = __float2bfloat16(v.y - __bfloat162float(h1));
            __nv_bfloat16 l2 = __float2bfloat16(v.z - __bfloat162float(h2));
            __nv_bfloat16 l3 = __float2bfloat16(v.w - __bfloat162float(h3));
            __nv_bfloat162 ph0 = {h0, h1}, ph1 = {h2, h3};
            __nv_bfloat162 pl0 = {l0, l1}, pl1 = {l2, l3};
            uint2 uh = {*(uint32_t*)&ph0, *(uint32_t*)&ph1};
            uint2 ul = {*(uint32_t*)&pl0, *(uint32_t*)&pl1};
            size_t addr;
            if (EPI == 2) {
                const int s2 = m >> 1, b = m & 1, hh = n >> 6, dk = n & 63;
                addr = ((size_t)(b * NH + hh) * SQ + s2) * DKH + dk;
            } else { // EPI == 3
                const int b = z >> 4, hh = z & 15;
                addr = ((size_t)m * NB + b) * DM + (size_t)hh * DKH + n;
            }
            *(uint2*)(Ch + addr) = uh;
            *(uint2*)(Cl + addr) = ul;
        }
    }
}

// ---------------------------------------------------------------------------
// fp32 -> (bf16 hi, bf16 lo) split conversion
// ---------------------------------------------------------------------------
__global__ void __launch_bounds__(256)
cvt_split(const float* __restrict__ x, __nv_bfloat16* __restrict__ h,
          __nv_bfloat16* __restrict__ l, int n)
{
    const int i = (blockIdx.x * 256 + threadIdx.x) * 4;
    if (i >= n) return;
    float4 v = *(const float4*)(x + i);
    __nv_bfloat16 h0 = __float2bfloat16(v.x), h1 = __float2bfloat16(v.y);
    __nv_bfloat16 h2 = __float2bfloat16(v.z), h3 = __float2bfloat16(v.w);
    __nv_bfloat16 l0 = __float2bfloat16(v.x - __bfloat162float(h0));
    __nv_bfloat16 l1 = __float2bfloat16(v.y - __bfloat162float(h1));
    __nv_bfloat16 l2 = __float2bfloat16(v.z - __bfloat162float(h2));
    __nv_bfloat16 l3 = __float2bfloat16(v.w - __bfloat162float(h3));
    __nv_bfloat162 ph0 = {h0, h1}, ph1 = {h2, h3};
    __nv_bfloat162 pl0 = {l0, l1}, pl1 = {l2, l3};
    uint2 uh = {*(uint32_t*)&ph0, *(uint32_t*)&ph1};
    uint2 ul = {*(uint32_t*)&pl0, *(uint32_t*)&pl1};
    *(uint2*)(h + i) = uh;
    *(uint2*)(l + i) = ul;
}

// ---------------------------------------------------------------------------
// V transpose: [Z, S, 64] -> [Z, 64, S] for hi and lo
// ---------------------------------------------------------------------------
__global__ void __launch_bounds__(256)
v_transpose(const __nv_bfloat16* __restrict__ sh, const __nv_bfloat16* __restrict__ sl,
            __nv_bfloat16* __restrict__ dh, __nv_bfloat16* __restrict__ dl)
{
    __shared__ __nv_bfloat16 t0[32][33], t1[32][33];
    const int z  = blockIdx.z;
    const int s0 = blockIdx.y * 32;
    const int d0 = blockIdx.x * 32;
    const int tx = threadIdx.x, ty = threadIdx.y;
    const size_t zin = (size_t)z * SQ * DKH;
    #pragma unroll
    for (int j = 0; j < 4; j++) {
        const int rs = ty + j * 8;
        t0[rs][tx] = sh[zin + (size_t)(s0 + rs) * DKH + d0 + tx];
        t1[rs][tx] = sl[zin + (size_t)(s0 + rs) * DKH + d0 + tx];
    }
    __syncthreads();
    const size_t zo = (size_t)z * DKH * SQ;
    #pragma unroll
    for (int j = 0; j < 4; j++) {
        const int rd = ty + j * 8;
        dh[zo + (size_t)(d0 + rd) * SQ + s0 + tx] = t0[tx][rd];
        dl[zo + (size_t)(d0 + rd) * SQ + s0 + tx] = t1[tx][rd];
    }
}

// ---------------------------------------------------------------------------
// Fused softmax + head-mean. One block per (b,q): loops 16 heads.
// Reads fp32 scores, writes bf16 hi/lo probs + fp32 mean row.
// ---------------------------------------------------------------------------
__global__ void __launch_bounds__(256)
softmax_mean(const float* __restrict__ P, __nv_bfloat16* __restrict__ Ph,
             __nv_bfloat16* __restrict__ Pl, float* __restrict__ outMean)
{
    __shared__ float sred[8];
    const int bq = blockIdx.x;
    const int b  = bq >> 11;
    const int q  = bq & (SQ - 1);
    const int t  = threadIdx.x;
    const int w  = t >> 5, lane = t & 31;

    float macc[8];
    #pragma unroll
    for (int i = 0; i < 8; i++) macc[i] = 0.f;

    for (int h = 0; h < NH; h++) {
        const size_t base = ((size_t)(b * NH + h) * SQ + q) * SQ;
        float v[8];
        float mx = -3.4e38f;
        #pragma unroll
        for (int i = 0; i < 8; i++) { v[i] = P[base + t + i * 256]; mx = fmaxf(mx, v[i]); }
        #pragma unroll
        for (int off = 16; off > 0; off >>= 1)
            mx = fmaxf(mx, __shfl_xor_sync(0xFFFFFFFFu, mx, off));
        if (lane == 0) sred[w] = mx;
        __syncthreads();
        #pragma unroll
        for (int i = 0; i < 8; i++) mx = fmaxf(mx, sred[i]);
        __syncthreads();

        float s = 0.f;
        #pragma unroll
        for (int i = 0; i < 8; i++) { v[i] = __expf(v[i] - mx); s += v[i]; }
        #pragma unroll
        for (int off = 16; off > 0; off >>= 1)
            s += __shfl_xor_sync(0xFFFFFFFFu, s, off);
        if (lane == 0) sred[w] = s;
        __syncthreads();
        s = 0.f;
        #pragma unroll
        for (int i = 0; i < 8; i++) s += sred[i];
        __syncthreads();

        const float inv = 1.0f / s;
        #pragma unroll
        for (int i = 0; i < 8; i++) {
            const float p = v[i] * inv;
            macc[i] += p;
            const __nv_bfloat16 hv = __float2bfloat16(p);
            const __nv_bfloat16 lv = __float2bfloat16(p - __bfloat162float(hv));
            Ph[base + t + i * 256] = hv;
            Pl[base + t + i * 256] = lv;
        }
    }
    float* om = outMean + (size_t)bq * SQ;
    #pragma unroll
    for (int i = 0; i < 8; i++) om[t + i * 256] = macc[i] * (1.0f / NH);
}

// ---------------------------------------------------------------------------
extern "C" void kernel_launch(void* const* d_in, const int* in_sizes, int n_in,
                              void* d_out, int out_size)
{
    (void)in_sizes; (void)n_in; (void)out_size;
    const float* q  = (const float*)d_in[0];
    const float* k  = (const float*)d_in[1];
    const float* v  = (const float*)d_in[2];
    const float* Wq = (const float*)d_in[3];
    const float* Wk = (const float*)d_in[4];
    const float* Wv = (const float*)d_in[5];
    const float* Wo = (const float*)d_in[6];
    float* out     = (float*)d_out;
    float* outMean = out + (size_t)MR * DM;

    #define SYM(p, s) void* p; cudaGetSymbolAddress(&p, s)
    SYM(pqh, g_qh); SYM(pql, g_ql); SYM(pkh, g_kh); SYM(pkl, g_kl);
    SYM(pvh, g_vh); SYM(pvl, g_vl);
    SYM(pwqh, g_wqh); SYM(pwql, g_wql); SYM(pwkh, g_wkh); SYM(pwkl, g_wkl);
    SYM(pwvh, g_wvh); SYM(pwvl, g_wvl); SYM(pwoh, g_woh); SYM(pwol, g_wol);
    SYM(pQh, g_Qh); SYM(pQl, g_Ql); SYM(pKh, g_Kh); SYM(pKl, g_Kl);
    SYM(pVsh, g_Vsh); SYM(pVsl, g_Vsl); SYM(pVth, g_Vth); SYM(pVtl, g_Vtl);
    SYM(pP, g_P); SYM(pPh, g_Ph); SYM(pPl, g_Pl);
    SYM(pch, g_ch); SYM(pcl, g_cl);
    #undef SYM

    // dynamic smem: 2 stages of (2*BM + 2*BN) * 144 bytes
    const int SMEM_128 = 2 * (2 * 128 + 2 * 128) * 144;  // 147456
    const int SMEM_64  = 2 * (2 * 128 + 2 * 64) * 144;   // 110592
    cudaFuncSetAttribute(hm_gemm<128, 128, 0>, cudaFuncAttributeMaxDynamicSharedMemorySize, SMEM_128);
    cudaFuncSetAttribute(hm_gemm<128, 128, 2>, cudaFuncAttributeMaxDynamicSharedMemorySize, SMEM_128);
    cudaFuncSetAttribute(hm_gemm<128, 64, 3>,  cudaFuncAttributeMaxDynamicSharedMemorySize, SMEM_64);

    // 1) split-convert inputs + weights
    cvt_split<<<MR * DM / 1024, 256>>>(q,  (__nv_bfloat16*)pqh, (__nv_bfloat16*)pql, MR * DM);
    cvt_split<<<MR * DM / 1024, 256>>>(k,  (__nv_bfloat16*)pkh, (__nv_bfloat16*)pkl, MR * DM);
    cvt_split<<<MR * DM / 1024, 256>>>(v,  (__nv_bfloat16*)pvh, (__nv_bfloat16*)pvl, MR * DM);
    cvt_split<<<DM * DM / 1024, 256>>>(Wq, (__nv_bfloat16*)pwqh, (__nv_bfloat16*)pwql, DM * DM);
    cvt_split<<<DM * DM / 1024, 256>>>(Wk, (__nv_bfloat16*)pwkh, (__nv_bfloat16*)pwkl, DM * DM);
    cvt_split<<<DM * DM / 1024, 256>>>(Wv, (__nv_bfloat16*)pwvh, (__nv_bfloat16*)pwvl, DM * DM);
    cvt_split<<<DM * DM / 1024, 256>>>(Wo, (__nv_bfloat16*)pwoh, (__nv_bfloat16*)pwol, DM * DM);

    // 2) projections -> scatter split to [B,H,S,dk]
    const dim3 gproj(DM / 128, MR / 128, 1);
    hm_gemm<128, 128, 2><<<gproj, 256, SMEM_128>>>(
        (const __nv_bfloat16*)pqh, (const __nv_bfloat16*)pql,
        (const __nv_bfloat16*)pwqh, (const __nv_bfloat16*)pwql,
        nullptr, (__nv_bfloat16*)pQh, (__nv_bfloat16*)pQl, DM, 0, 1.0f, 0, 0, 0);
    hm_gemm<128, 128, 2><<<gproj, 256, SMEM_128>>>(
        (const __nv_bfloat16*)pkh, (const __nv_bfloat16*)pkl,
        (const __nv_bfloat16*)pwkh, (const __nv_bfloat16*)pwkl,
        nullptr, (__nv_bfloat16*)pKh, (__nv_bfloat16*)pKl, DM, 0, 1.0f, 0, 0, 0);
    hm_gemm<128, 128, 2><<<gproj, 256, SMEM_128>>>(
        (const __nv_bfloat16*)pvh, (const __nv_bfloat16*)pvl,
        (const __nv_bfloat16*)pwvh, (const __nv_bfloat16*)pwvl,
        nullptr, (__nv_bfloat16*)pVsh, (__nv_bfloat16*)pVsl, DM, 0, 1.0f, 0, 0, 0);

    // 3) V transpose [Z,S,64] -> [Z,64,S]
    v_transpose<<<dim3(DKH / 32, SQ / 32, NZ), dim3(32, 8)>>>(
        (const __nv_bfloat16*)pVsh, (const __nv_bfloat16*)pVsl,
        (__nv_bfloat16*)pVth, (__nv_bfloat16*)pVtl);

    // 4) scores: P = (Q K^T) / 8   fp32
    hm_gemm<128, 128, 0><<<dim3(SQ / 128, SQ / 128, NZ), 256, SMEM_128>>>(
        (const __nv_bfloat16*)pQh, (const __nv_bfloat16*)pQl,
        (const __nv_bfloat16*)pKh, (const __nv_bfloat16*)pKl,
        (float*)pP, nullptr, nullptr, DKH, SQ, 0.125f,
        (size_t)SQ * DKH, (size_t)SQ * DKH, (size_t)SQ * SQ);

    // 5) softmax + head-mean (writes split P + outMean)
    softmax_mean<<<NB * SQ, 256>>>((const float*)pP, (__nv_bfloat16*)pPh,
                                   (__nv_bfloat16*)pPl, outMean);

    // 6) ctx = P @ V  -> split [S,B,D]
    hm_gemm<128, 64, 3><<<dim3(1, SQ / 128, NZ), 256, SMEM_64>>>(
        (const __nv_bfloat16*)pPh, (const __nv_bfloat16*)pPl,
        (const __nv_bfloat16*)pVth, (const __nv_bfloat16*)pVtl,
        nullptr, (__nv_bfloat16*)pch, (__nv_bfloat16*)pcl, SQ, 0, 1.0f,
        (size_t)SQ * SQ, (size_t)DKH * SQ, 0);

    // 7) out = ctx @ Wo^T  fp32
    hm_gemm<128, 128, 0><<<gproj, 256, SMEM_128>>>(
        (const __nv_bfloat16*)pch, (const __nv_bfloat16*)pcl,
        (const __nv_bfloat16*)pwoh, (const __nv_bfloat16*)pwol,
        out, nullptr, nullptr, DM, DM, 1.0f, 0, 0, 0);
}

// round 6
// speedup vs baseline: 3.9742x; 1.9675x over previous
#include <cuda_runtime.h>
#include <cuda_fp16.h>
#include <cstdint>

#define SQ  2048
#define NB  2
#define DM  1024
#define NH  16
#define DKH 64
#define MR  4096              // S*B rows
#define NZ  (NB*NH)           // 32 batch*head slices

// ---------------------------------------------------------------------------
// Scratch (__device__ globals: allocation-free)
// ---------------------------------------------------------------------------
__device__ __half g_qx[(size_t)MR*DM], g_kx[(size_t)MR*DM], g_vx[(size_t)MR*DM];
__device__ __half g_wq[(size_t)DM*DM], g_wk[(size_t)DM*DM];
__device__ __half g_wv[(size_t)DM*DM], g_wo[(size_t)DM*DM];
__device__ __half g_Q[(size_t)NZ*SQ*DKH], g_K[(size_t)NZ*SQ*DKH];
__device__ __half g_Vs[(size_t)NZ*SQ*DKH];          // [Z,S,dk]
__device__ __half g_Vt[(size_t)NZ*DKH*SQ];          // [Z,dk,S]
__device__ float  g_P [(size_t)NZ*SQ*SQ];           // 537 MB fp32 scores
__device__ __half g_Ph[(size_t)NZ*SQ*SQ];           // 268 MB fp16 probs
__device__ __half g_c [(size_t)MR*DM];              // ctx [S,B,D]

// ---------------------------------------------------------------------------
// PTX helpers (base-arch: mma.sync / ldmatrix / cp.async)
// ---------------------------------------------------------------------------
__device__ __forceinline__ uint32_t smem_u32(const void* p) {
    uint32_t a;
    asm("{ .reg .u64 t; cvta.to.shared.u64 t, %1; cvt.u32.u64 %0, t; }" : "=r"(a) : "l"(p));
    return a;
}
__device__ __forceinline__ void cp16(uint32_t d, const void* s) {
    asm volatile("cp.async.cg.shared.global [%0], [%1], 16;" :: "r"(d), "l"(s));
}
__device__ __forceinline__ void cp_commit() {
    asm volatile("cp.async.commit_group;" ::: "memory");
}
__device__ __forceinline__ void cp_wait1() {
    asm volatile("cp.async.wait_group 1;" ::: "memory");
}
__device__ __forceinline__ void cp_wait0() {
    asm volatile("cp.async.wait_group 0;" ::: "memory");
}
#define LDMX4(r, a) \
    asm volatile("ldmatrix.sync.aligned.m8n8.x4.shared.b16 {%0,%1,%2,%3}, [%4];" \
        : "=r"((r)[0]), "=r"((r)[1]), "=r"((r)[2]), "=r"((r)[3]) : "r"(a))

__device__ __forceinline__ void mma_f16(float* c, const uint32_t* a, const uint32_t* b) {
    asm volatile(
        "mma.sync.aligned.m16n8k16.row.col.f32.f16.f16.f32 "
        "{%0,%1,%2,%3},{%4,%5,%6,%7},{%8,%9},{%0,%1,%2,%3};"
        : "+f"(c[0]), "+f"(c[1]), "+f"(c[2]), "+f"(c[3])
        : "r"(a[0]), "r"(a[1]), "r"(a[2]), "r"(a[3]), "r"(b[0]), "r"(b[1]));
}

// ---------------------------------------------------------------------------
// fp16 HMMA GEMM: C = alpha * A(MxK) * B(NxK)^T, A,B row-major K-contiguous.
// One mma per element (pure fp16 operands, fp32 accumulate).
// EPI: 0 = fp32 row-major (ldc, z*sC)
//      2 = fp16 scatter to [B,H,S,dk]   (projections: m->(s,b), n->(h,dk))
//      3 = fp16 ctx write to [S,B,D]    (PV: row m, col h*64+n, b from z)
// 256 thr = 8 warps; smem rows padded to 72 halves (144B, conflict-free).
// Double-buffered K-chunks of 64 via cp.async.
// ---------------------------------------------------------------------------
template<int BM, int BN, int EPI>
__global__ void __launch_bounds__(256, 2)
hm_gemm(const __half* __restrict__ A, const __half* __restrict__ B,
        float* __restrict__ Cf, __half* __restrict__ Ch,
        int K, int ldc, float alpha, size_t sA, size_t sB, size_t sC)
{
    extern __shared__ __align__(16) char smem[];
    const uint32_t sb = smem_u32(smem);
    const int tid  = threadIdx.x;
    const int lane = tid & 31;
    const int wid  = tid >> 5;
    const int z    = blockIdx.z;
    const int m0   = blockIdx.y * BM;
    const int n0   = blockIdx.x * BN;

    constexpr int WGM = (BN == 128) ? 2 : 4;       // warps along M
    constexpr int TM  = BM / WGM;                  // 64 or 32
    constexpr int TN  = BN / (8 / WGM);            // 32
    constexpr int MT  = TM / 16;                   // 4 or 2
    constexpr int NT  = TN / 8;                    // 4
    constexpr int STAGE = (BM + BN) * 144;         // bytes per stage

    const int wm = wid % WGM, wn = wid / WGM;
    const int mbase = wm * TM, nbase = wn * TN;

    A += (size_t)z * sA + (size_t)m0 * K;
    B += (size_t)z * sB + (size_t)n0 * K;

    float acc[MT][NT][4];
    #pragma unroll
    for (int i = 0; i < MT; i++)
        #pragma unroll
        for (int j = 0; j < NT; j++)
            #pragma unroll
            for (int r = 0; r < 4; r++) acc[i][j][r] = 0.f;

    const int a_r = lane & 15;
    const int a_c = ((lane >> 4) & 1) << 3;
    const int b_r = (lane & 7) + (((lane >> 4) & 1) << 3);
    const int b_c = ((lane >> 3) & 1) << 3;

    auto load_stage = [&](int kc, int stg) {
        const uint32_t base = sb + (uint32_t)stg * STAGE;
        #pragma unroll
        for (int idx = tid; idx < BM * 8; idx += 256) {
            const int r = idx >> 3, ch = idx & 7;
            cp16(base + (uint32_t)r * 144 + ch * 16, A + (size_t)r * K + kc + ch * 8);
        }
        #pragma unroll
        for (int idx = tid; idx < BN * 8; idx += 256) {
            const int r = idx >> 3, ch = idx & 7;
            cp16(base + BM * 144 + (uint32_t)r * 144 + ch * 16, B + (size_t)r * K + kc + ch * 8);
        }
    };

    auto compute = [&](int stg) {
        const uint32_t sA0 = sb + (uint32_t)stg * STAGE;
        const uint32_t sB0 = sA0 + BM * 144;
        #pragma unroll
        for (int ks = 0; ks < 4; ks++) {
            uint32_t ah[MT][4], bh[NT][2];
            #pragma unroll
            for (int mt = 0; mt < MT; mt++) {
                const uint32_t off = ((uint32_t)(mbase + mt * 16 + a_r) * 72 + ks * 16 + a_c) * 2;
                LDMX4(ah[mt], sA0 + off);
            }
            #pragma unroll
            for (int np = 0; np < NT / 2; np++) {
                const uint32_t off = ((uint32_t)(nbase + np * 16 + b_r) * 72 + ks * 16 + b_c) * 2;
                uint32_t r4[4];
                LDMX4(r4, sB0 + off);
                bh[np*2][0]   = r4[0]; bh[np*2][1]   = r4[1];
                bh[np*2+1][0] = r4[2]; bh[np*2+1][1] = r4[3];
            }
            #pragma unroll
            for (int mt = 0; mt < MT; mt++)
                #pragma unroll
                for (int nt = 0; nt < NT; nt++)
                    mma_f16(acc[mt][nt], ah[mt], bh[nt]);
        }
    };

    const int NC = K >> 6;
    load_stage(0, 0);
    cp_commit();

    for (int c = 0; c < NC; c++) {
        const int buf = c & 1;
        if (c + 1 < NC) {
            load_stage((c + 1) << 6, buf ^ 1);
            cp_commit();
            cp_wait1();
        } else {
            cp_wait0();
        }
        __syncthreads();
        compute(buf);
        __syncthreads();
    }

    // ---- epilogue: frags -> smem -> coalesced gmem ----
    constexpr int CP = BN + 4;
    float* Cs = (float*)smem;
    const int g = lane >> 2, tg = lane & 3;
    #pragma unroll
    for (int mt = 0; mt < MT; mt++)
        #pragma unroll
        for (int nt = 0; nt < NT; nt++) {
            const int row = mbase + mt * 16 + g;
            const int col = nbase + nt * 8 + tg * 2;
            *(float2*)&Cs[(size_t)row * CP + col]       = make_float2(acc[mt][nt][0], acc[mt][nt][1]);
            *(float2*)&Cs[(size_t)(row + 8) * CP + col] = make_float2(acc[mt][nt][2], acc[mt][nt][3]);
        }
    __syncthreads();

    for (int i4 = tid * 4; i4 < BM * BN; i4 += 1024) {
        const int row = i4 / BN, col = i4 % BN;
        float4 v = *(const float4*)&Cs[(size_t)row * CP + col];
        v.x *= alpha; v.y *= alpha; v.z *= alpha; v.w *= alpha;
        const int m = m0 + row, n = n0 + col;
        if (EPI == 0) {
            *(float4*)&Cf[(size_t)z * sC + (size_t)m * ldc + n] = v;
        } else {
            __half2 p0 = __halves2half2(__float2half_rn(v.x), __float2half_rn(v.y));
            __half2 p1 = __halves2half2(__float2half_rn(v.z), __float2half_rn(v.w));
            uint2 u = {*(uint32_t*)&p0, *(uint32_t*)&p1};
            size_t addr;
            if (EPI == 2) {
                const int s2 = m >> 1, b = m & 1, hh = n >> 6, dk = n & 63;
                addr = ((size_t)(b * NH + hh) * SQ + s2) * DKH + dk;
            } else { // EPI == 3
                const int b = z >> 4, hh = z & 15;
                addr = ((size_t)m * NB + b) * DM + (size_t)hh * DKH + n;
            }
            *(uint2*)(Ch + addr) = u;
        }
    }
}

// ---------------------------------------------------------------------------
// fp32 -> fp16 conversion
// ---------------------------------------------------------------------------
__global__ void __launch_bounds__(256)
cvt_h(const float* __restrict__ x, __half* __restrict__ h, int n)
{
    const int i = (blockIdx.x * 256 + threadIdx.x) * 4;
    if (i >= n) return;
    float4 v = *(const float4*)(x + i);
    __half2 p0 = __halves2half2(__float2half_rn(v.x), __float2half_rn(v.y));
    __half2 p1 = __halves2half2(__float2half_rn(v.z), __float2half_rn(v.w));
    uint2 u = {*(uint32_t*)&p0, *(uint32_t*)&p1};
    *(uint2*)(h + i) = u;
}

// ---------------------------------------------------------------------------
// V transpose: [Z, S, 64] -> [Z, 64, S]
// ---------------------------------------------------------------------------
__global__ void __launch_bounds__(256)
v_transpose(const __half* __restrict__ s, __half* __restrict__ d)
{
    __shared__ __half t0[32][33];
    const int z  = blockIdx.z;
    const int s0 = blockIdx.y * 32;
    const int d0 = blockIdx.x * 32;
    const int tx = threadIdx.x, ty = threadIdx.y;
    const size_t zin = (size_t)z * SQ * DKH;
    #pragma unroll
    for (int j = 0; j < 4; j++) {
        const int rs = ty + j * 8;
        t0[rs][tx] = s[zin + (size_t)(s0 + rs) * DKH + d0 + tx];
    }
    __syncthreads();
    const size_t zo = (size_t)z * DKH * SQ;
    #pragma unroll
    for (int j = 0; j < 4; j++) {
        const int rd = ty + j * 8;
        d[zo + (size_t)(d0 + rd) * SQ + s0 + tx] = t0[tx][rd];
    }
}

// ---------------------------------------------------------------------------
// Fused softmax + head-mean. One block per (b,q): loops 16 heads.
// Reads fp32 scores, writes fp16 probs + fp32 mean row.
// ---------------------------------------------------------------------------
__global__ void __launch_bounds__(256)
softmax_mean(const float* __restrict__ P, __half* __restrict__ Ph,
             float* __restrict__ outMean)
{
    __shared__ float sred[8];
    const int bq = blockIdx.x;
    const int b  = bq >> 11;
    const int q  = bq & (SQ - 1);
    const int t  = threadIdx.x;
    const int w  = t >> 5, lane = t & 31;

    float macc[8];
    #pragma unroll
    for (int i = 0; i < 8; i++) macc[i] = 0.f;

    for (int h = 0; h < NH; h++) {
        const size_t base = ((size_t)(b * NH + h) * SQ + q) * SQ;
        float v[8];
        float mx = -3.4e38f;
        #pragma unroll
        for (int i = 0; i < 8; i++) { v[i] = P[base + t + i * 256]; mx = fmaxf(mx, v[i]); }
        #pragma unroll
        for (int off = 16; off > 0; off >>= 1)
            mx = fmaxf(mx, __shfl_xor_sync(0xFFFFFFFFu, mx, off));
        if (lane == 0) sred[w] = mx;
        __syncthreads();
        #pragma unroll
        for (int i = 0; i < 8; i++) mx = fmaxf(mx, sred[i]);
        __syncthreads();

        float s = 0.f;
        #pragma unroll
        for (int i = 0; i < 8; i++) { v[i] = __expf(v[i] - mx); s += v[i]; }
        #pragma unroll
        for (int off = 16; off > 0; off >>= 1)
            s += __shfl_xor_sync(0xFFFFFFFFu, s, off);
        if (lane == 0) sred[w] = s;
        __syncthreads();
        s = 0.f;
        #pragma unroll
        for (int i = 0; i < 8; i++) s += sred[i];
        __syncthreads();

        const float inv = 1.0f / s;
        #pragma unroll
        for (int i = 0; i < 8; i++) {
            const float p = v[i] * inv;
            macc[i] += p;
            Ph[base + t + i * 256] = __float2half_rn(p);
        }
    }
    float* om = outMean + (size_t)bq * SQ;
    #pragma unroll
    for (int i = 0; i < 8; i++) om[t + i * 256] = macc[i] * (1.0f / NH);
}

// ---------------------------------------------------------------------------
extern "C" void kernel_launch(void* const* d_in, const int* in_sizes, int n_in,
                              void* d_out, int out_size)
{
    (void)in_sizes; (void)n_in; (void)out_size;
    const float* q  = (const float*)d_in[0];
    const float* k  = (const float*)d_in[1];
    const float* v  = (const float*)d_in[2];
    const float* Wq = (const float*)d_in[3];
    const float* Wk = (const float*)d_in[4];
    const float* Wv = (const float*)d_in[5];
    const float* Wo = (const float*)d_in[6];
    float* out     = (float*)d_out;
    float* outMean = out + (size_t)MR * DM;

    #define SYM(p, s) void* p; cudaGetSymbolAddress(&p, s)
    SYM(pqx, g_qx); SYM(pkx, g_kx); SYM(pvx, g_vx);
    SYM(pwq, g_wq); SYM(pwk, g_wk); SYM(pwv, g_wv); SYM(pwo, g_wo);
    SYM(pQ, g_Q); SYM(pK, g_K); SYM(pVs, g_Vs); SYM(pVt, g_Vt);
    SYM(pP, g_P); SYM(pPh, g_Ph); SYM(pc, g_c);
    #undef SYM

    // dynamic smem: max(2 stages of (BM+BN)*144, epilogue BM*(BN+4)*4)
    const int SMEM_128 = 2 * (128 + 128) * 144;  // 73728 >= 67584 epi
    const int SMEM_64  = 2 * (128 + 64) * 144;   // 55296 >= 34816 epi
    cudaFuncSetAttribute(hm_gemm<128, 128, 0>, cudaFuncAttributeMaxDynamicSharedMemorySize, SMEM_128);
    cudaFuncSetAttribute(hm_gemm<128, 128, 2>, cudaFuncAttributeMaxDynamicSharedMemorySize, SMEM_128);
    cudaFuncSetAttribute(hm_gemm<128, 64, 3>,  cudaFuncAttributeMaxDynamicSharedMemorySize, SMEM_64);

    // 1) fp32 -> fp16 conversions
    cvt_h<<<MR * DM / 1024, 256>>>(q,  (__half*)pqx, MR * DM);
    cvt_h<<<MR * DM / 1024, 256>>>(k,  (__half*)pkx, MR * DM);
    cvt_h<<<MR * DM / 1024, 256>>>(v,  (__half*)pvx, MR * DM);
    cvt_h<<<DM * DM / 1024, 256>>>(Wq, (__half*)pwq, DM * DM);
    cvt_h<<<DM * DM / 1024, 256>>>(Wk, (__half*)pwk, DM * DM);
    cvt_h<<<DM * DM / 1024, 256>>>(Wv, (__half*)pwv, DM * DM);
    cvt_h<<<DM * DM / 1024, 256>>>(Wo, (__half*)pwo, DM * DM);

    // 2) projections -> scatter fp16 to [B,H,S,dk]
    const dim3 gproj(DM / 128, MR / 128, 1);
    hm_gemm<128, 128, 2><<<gproj, 256, SMEM_128>>>(
        (const __half*)pqx, (const __half*)pwq, nullptr, (__half*)pQ,
        DM, 0, 1.0f, 0, 0, 0);
    hm_gemm<128, 128, 2><<<gproj, 256, SMEM_128>>>(
        (const __half*)pkx, (const __half*)pwk, nullptr, (__half*)pK,
        DM, 0, 1.0f, 0, 0, 0);
    hm_gemm<128, 128, 2><<<gproj, 256, SMEM_128>>>(
        (const __half*)pvx, (const __half*)pwv, nullptr, (__half*)pVs,
        DM, 0, 1.0f, 0, 0, 0);

    // 3) V transpose [Z,S,64] -> [Z,64,S]
    v_transpose<<<dim3(DKH / 32, SQ / 32, NZ), dim3(32, 8)>>>(
        (const __half*)pVs, (__half*)pVt);

    // 4) scores: P = (Q K^T) / 8   fp32
    hm_gemm<128, 128, 0><<<dim3(SQ / 128, SQ / 128, NZ), 256, SMEM_128>>>(
        (const __half*)pQ, (const __half*)pK, (float*)pP, nullptr,
        DKH, SQ, 0.125f, (size_t)SQ * DKH, (size_t)SQ * DKH, (size_t)SQ * SQ);

    // 5) softmax + head-mean (writes fp16 P + outMean)
    softmax_mean<<<NB * SQ, 256>>>((const float*)pP, (__half*)pPh, outMean);

    // 6) ctx = P @ V  -> fp16 [S,B,D]
    hm_gemm<128, 64, 3><<<dim3(1, SQ / 128, NZ), 256, SMEM_64>>>(
        (const __half*)pPh, (const __half*)pVt, nullptr, (__half*)pc,
        SQ, 0, 1.0f, (size_t)SQ * SQ, (size_t)DKH * SQ, 0);

    // 7) out = ctx @ Wo^T  fp32
    hm_gemm<128, 128, 0><<<gproj, 256, SMEM_128>>>(
        (const __half*)pc, (const __half*)pwo, out, nullptr,
        DM, DM, 1.0f, 0, 0, 0);
}

// round 7
// speedup vs baseline: 4.2973x; 1.0813x over previous
#include <cuda_runtime.h>
#include <cuda_fp16.h>
#include <cstdint>

#define SQ  2048
#define NB  2
#define DM  1024
#define NH  16
#define DKH 64
#define MR  4096              // S*B rows
#define NZ  (NB*NH)           // 32 batch*head slices

// ---------------------------------------------------------------------------
// Scratch (__device__ globals: allocation-free)
// ---------------------------------------------------------------------------
__device__ __half g_qx[(size_t)MR*DM], g_kx[(size_t)MR*DM], g_vx[(size_t)MR*DM];
__device__ __half g_wq[(size_t)DM*DM], g_wk[(size_t)DM*DM];
__device__ __half g_wv[(size_t)DM*DM], g_wo[(size_t)DM*DM];
__device__ __half g_Q[(size_t)NZ*SQ*DKH], g_K[(size_t)NZ*SQ*DKH];
__device__ __half g_Vs[(size_t)NZ*SQ*DKH];          // [Z,S,dk]
__device__ __half g_Vt[(size_t)NZ*DKH*SQ];          // [Z,dk,S]
__device__ float2 g_stats[(size_t)NZ*SQ];           // (row max, 1/row sum)
__device__ __half g_Ph[(size_t)NZ*SQ*SQ];           // 268 MB fp16 probs
__device__ __half g_c [(size_t)MR*DM];              // ctx [S,B,D]

// ---------------------------------------------------------------------------
// PTX helpers (base-arch: mma.sync / ldmatrix / cp.async)
// ---------------------------------------------------------------------------
__device__ __forceinline__ uint32_t smem_u32(const void* p) {
    uint32_t a;
    asm("{ .reg .u64 t; cvta.to.shared.u64 t, %1; cvt.u32.u64 %0, t; }" : "=r"(a) : "l"(p));
    return a;
}
__device__ __forceinline__ void cp16(uint32_t d, const void* s) {
    asm volatile("cp.async.cg.shared.global [%0], [%1], 16;" :: "r"(d), "l"(s));
}
__device__ __forceinline__ void cp_commit() {
    asm volatile("cp.async.commit_group;" ::: "memory");
}
__device__ __forceinline__ void cp_wait1() {
    asm volatile("cp.async.wait_group 1;" ::: "memory");
}
__device__ __forceinline__ void cp_wait0() {
    asm volatile("cp.async.wait_group 0;" ::: "memory");
}
#define LDMX4(r, a) \
    asm volatile("ldmatrix.sync.aligned.m8n8.x4.shared.b16 {%0,%1,%2,%3}, [%4];" \
        : "=r"((r)[0]), "=r"((r)[1]), "=r"((r)[2]), "=r"((r)[3]) : "r"(a))

__device__ __forceinline__ void mma_f16(float* c, const uint32_t* a, const uint32_t* b) {
    asm volatile(
        "mma.sync.aligned.m16n8k16.row.col.f32.f16.f16.f32 "
        "{%0,%1,%2,%3},{%4,%5,%6,%7},{%8,%9},{%0,%1,%2,%3};"
        : "+f"(c[0]), "+f"(c[1]), "+f"(c[2]), "+f"(c[3])
        : "r"(a[0]), "r"(a[1]), "r"(a[2]), "r"(a[3]), "r"(b[0]), "r"(b[1]));
}

// ---------------------------------------------------------------------------
// fp16 HMMA GEMM: C = alpha * A(MxK) * B(NxK)^T, A,B row-major K-contiguous.
// EPI: 0 = fp32 row-major (ldc, z*sC)
//      2 = fp16 scatter to [B,H,S,dk]   (projections: m->(s,b), n->(h,dk))
//      3 = fp16 ctx write to [S,B,D]    (PV: row m, col h*64+n, b from z)
// ---------------------------------------------------------------------------
template<int BM, int BN, int EPI>
__global__ void __launch_bounds__(256, 2)
hm_gemm(const __half* __restrict__ A, const __half* __restrict__ B,
        float* __restrict__ Cf, __half* __restrict__ Ch,
        int K, int ldc, float alpha, size_t sA, size_t sB, size_t sC)
{
    extern __shared__ __align__(16) char smem[];
    const uint32_t sb = smem_u32(smem);
    const int tid  = threadIdx.x;
    const int lane = tid & 31;
    const int wid  = tid >> 5;
    const int z    = blockIdx.z;
    const int m0   = blockIdx.y * BM;
    const int n0   = blockIdx.x * BN;

    constexpr int WGM = (BN == 128) ? 2 : 4;
    constexpr int TM  = BM / WGM;
    constexpr int TN  = BN / (8 / WGM);
    constexpr int MT  = TM / 16;
    constexpr int NT  = TN / 8;
    constexpr int STAGE = (BM + BN) * 144;

    const int wm = wid % WGM, wn = wid / WGM;
    const int mbase = wm * TM, nbase = wn * TN;

    A += (size_t)z * sA + (size_t)m0 * K;
    B += (size_t)z * sB + (size_t)n0 * K;

    float acc[MT][NT][4];
    #pragma unroll
    for (int i = 0; i < MT; i++)
        #pragma unroll
        for (int j = 0; j < NT; j++)
            #pragma unroll
            for (int r = 0; r < 4; r++) acc[i][j][r] = 0.f;

    const int a_r = lane & 15;
    const int a_c = ((lane >> 4) & 1) << 3;
    const int b_r = (lane & 7) + (((lane >> 4) & 1) << 3);
    const int b_c = ((lane >> 3) & 1) << 3;

    auto load_stage = [&](int kc, int stg) {
        const uint32_t base = sb + (uint32_t)stg * STAGE;
        #pragma unroll
        for (int idx = tid; idx < BM * 8; idx += 256) {
            const int r = idx >> 3, ch = idx & 7;
            cp16(base + (uint32_t)r * 144 + ch * 16, A + (size_t)r * K + kc + ch * 8);
        }
        #pragma unroll
        for (int idx = tid; idx < BN * 8; idx += 256) {
            const int r = idx >> 3, ch = idx & 7;
            cp16(base + BM * 144 + (uint32_t)r * 144 + ch * 16, B + (size_t)r * K + kc + ch * 8);
        }
    };

    auto compute = [&](int stg) {
        const uint32_t sA0 = sb + (uint32_t)stg * STAGE;
        const uint32_t sB0 = sA0 + BM * 144;
        #pragma unroll
        for (int ks = 0; ks < 4; ks++) {
            uint32_t ah[MT][4], bh[NT][2];
            #pragma unroll
            for (int mt = 0; mt < MT; mt++) {
                const uint32_t off = ((uint32_t)(mbase + mt * 16 + a_r) * 72 + ks * 16 + a_c) * 2;
                LDMX4(ah[mt], sA0 + off);
            }
            #pragma unroll
            for (int np = 0; np < NT / 2; np++) {
                const uint32_t off = ((uint32_t)(nbase + np * 16 + b_r) * 72 + ks * 16 + b_c) * 2;
                uint32_t r4[4];
                LDMX4(r4, sB0 + off);
                bh[np*2][0]   = r4[0]; bh[np*2][1]   = r4[1];
                bh[np*2+1][0] = r4[2]; bh[np*2+1][1] = r4[3];
            }
            #pragma unroll
            for (int mt = 0; mt < MT; mt++)
                #pragma unroll
                for (int nt = 0; nt < NT; nt++)
                    mma_f16(acc[mt][nt], ah[mt], bh[nt]);
        }
    };

    const int NC = K >> 6;
    load_stage(0, 0);
    cp_commit();

    for (int c = 0; c < NC; c++) {
        const int buf = c & 1;
        if (c + 1 < NC) {
            load_stage((c + 1) << 6, buf ^ 1);
            cp_commit();
            cp_wait1();
        } else {
            cp_wait0();
        }
        __syncthreads();
        compute(buf);
        __syncthreads();
    }

    // ---- epilogue: frags -> smem -> coalesced gmem ----
    constexpr int CP = BN + 4;
    float* Cs = (float*)smem;
    const int g = lane >> 2, tg = lane & 3;
    #pragma unroll
    for (int mt = 0; mt < MT; mt++)
        #pragma unroll
        for (int nt = 0; nt < NT; nt++) {
            const int row = mbase + mt * 16 + g;
            const int col = nbase + nt * 8 + tg * 2;
            *(float2*)&Cs[(size_t)row * CP + col]       = make_float2(acc[mt][nt][0], acc[mt][nt][1]);
            *(float2*)&Cs[(size_t)(row + 8) * CP + col] = make_float2(acc[mt][nt][2], acc[mt][nt][3]);
        }
    __syncthreads();

    for (int i4 = tid * 4; i4 < BM * BN; i4 += 1024) {
        const int row = i4 / BN, col = i4 % BN;
        float4 v = *(const float4*)&Cs[(size_t)row * CP + col];
        v.x *= alpha; v.y *= alpha; v.z *= alpha; v.w *= alpha;
        const int m = m0 + row, n = n0 + col;
        if (EPI == 0) {
            *(float4*)&Cf[(size_t)z * sC + (size_t)m * ldc + n] = v;
        } else {
            __half2 p0 = __halves2half2(__float2half_rn(v.x), __float2half_rn(v.y));
            __half2 p1 = __halves2half2(__float2half_rn(v.z), __float2half_rn(v.w));
            uint2 u = {*(uint32_t*)&p0, *(uint32_t*)&p1};
            size_t addr;
            if (EPI == 2) {
                const int s2 = m >> 1, b = m & 1, hh = n >> 6, dk = n & 63;
                addr = ((size_t)(b * NH + hh) * SQ + s2) * DKH + dk;
            } else { // EPI == 3
                const int b = z >> 4, hh = z & 15;
                addr = ((size_t)m * NB + b) * DM + (size_t)hh * DKH + n;
            }
            *(uint2*)(Ch + addr) = u;
        }
    }
}

// ---------------------------------------------------------------------------
// Phase A: per-row softmax stats. Block = (z, q-tile of 128 rows).
// Streams K in 128-col tiles; online max/sum; writes (m, 1/s) per row.
// Warp layout: warp w owns rows w*16..+15 across all 128 cols (MT=1, NT=16).
// ---------------------------------------------------------------------------
__global__ void __launch_bounds__(256, 2)
qk_stats(const __half* __restrict__ Q, const __half* __restrict__ K,
         float2* __restrict__ stats)
{
    extern __shared__ __align__(16) char smem[];
    const uint32_t sb = smem_u32(smem);
    const int tid = threadIdx.x, lane = tid & 31, wid = tid >> 5;
    const int z = blockIdx.z, q0 = blockIdx.y * 128;
    const int g = lane >> 2, tg = lane & 3;
    const int wbase = wid * 16;

    const __half* Qg = Q + ((size_t)z * SQ + q0) * DKH;
    const __half* Kg = K + (size_t)z * SQ * DKH;

    const uint32_t qs = sb;
    const uint32_t ks = sb + 128 * 144;

    auto loadK = [&](int kt, int stg) {
        const uint32_t base = ks + (uint32_t)stg * (128 * 144);
        #pragma unroll
        for (int idx = tid; idx < 128 * 8; idx += 256) {
            const int r = idx >> 3, ch = idx & 7;
            cp16(base + (uint32_t)r * 144 + ch * 16,
                 Kg + ((size_t)(kt * 128 + r)) * DKH + ch * 8);
        }
    };

    #pragma unroll
    for (int idx = tid; idx < 128 * 8; idx += 256) {
        const int r = idx >> 3, ch = idx & 7;
        cp16(qs + (uint32_t)r * 144 + ch * 16, Qg + (size_t)r * DKH + ch * 8);
    }
    loadK(0, 0);
    cp_commit();

    const int a_r = lane & 15;
    const int a_c = ((lane >> 4) & 1) << 3;
    const int b_r = (lane & 7) + (((lane >> 4) & 1) << 3);
    const int b_c = ((lane >> 3) & 1) << 3;

    float m0 = -3.4e38f, m1 = -3.4e38f, s0 = 0.f, s1 = 0.f;

    for (int kt = 0; kt < SQ / 128; kt++) {
        const int buf = kt & 1;
        if (kt + 1 < SQ / 128) { loadK(kt + 1, buf ^ 1); cp_commit(); cp_wait1(); }
        else cp_wait0();
        __syncthreads();

        float acc[16][4];
        #pragma unroll
        for (int nt = 0; nt < 16; nt++)
            acc[nt][0] = acc[nt][1] = acc[nt][2] = acc[nt][3] = 0.f;

        const uint32_t kb = ks + (uint32_t)buf * (128 * 144);
        #pragma unroll
        for (int ksx = 0; ksx < 4; ksx++) {
            uint32_t ah[4];
            LDMX4(ah, qs + ((uint32_t)(wbase + a_r) * 72 + ksx * 16 + a_c) * 2);
            uint32_t bh[16][2];
            #pragma unroll
            for (int np = 0; np < 8; np++) {
                uint32_t r4[4];
                LDMX4(r4, kb + ((uint32_t)(np * 16 + b_r) * 72 + ksx * 16 + b_c) * 2);
                bh[np*2][0]   = r4[0]; bh[np*2][1]   = r4[1];
                bh[np*2+1][0] = r4[2]; bh[np*2+1][1] = r4[3];
            }
            #pragma unroll
            for (int nt = 0; nt < 16; nt++) mma_f16(acc[nt], ah, bh[nt]);
        }

        // online stats update (rows g and g+8 of this warp's 16-row tile)
        float mx0 = -3.4e38f, mx1 = -3.4e38f;
        #pragma unroll
        for (int nt = 0; nt < 16; nt++) {
            mx0 = fmaxf(mx0, fmaxf(acc[nt][0], acc[nt][1]));
            mx1 = fmaxf(mx1, fmaxf(acc[nt][2], acc[nt][3]));
        }
        mx0 = fmaxf(mx0, __shfl_xor_sync(0xFFFFFFFFu, mx0, 1));
        mx0 = fmaxf(mx0, __shfl_xor_sync(0xFFFFFFFFu, mx0, 2));
        mx1 = fmaxf(mx1, __shfl_xor_sync(0xFFFFFFFFu, mx1, 1));
        mx1 = fmaxf(mx1, __shfl_xor_sync(0xFFFFFFFFu, mx1, 2));
        const float nm0 = fmaxf(m0, mx0 * 0.125f);
        const float nm1 = fmaxf(m1, mx1 * 0.125f);
        float t0 = 0.f, t1 = 0.f;
        #pragma unroll
        for (int nt = 0; nt < 16; nt++) {
            t0 += __expf(acc[nt][0] * 0.125f - nm0) + __expf(acc[nt][1] * 0.125f - nm0);
            t1 += __expf(acc[nt][2] * 0.125f - nm1) + __expf(acc[nt][3] * 0.125f - nm1);
        }
        t0 += __shfl_xor_sync(0xFFFFFFFFu, t0, 1);
        t0 += __shfl_xor_sync(0xFFFFFFFFu, t0, 2);
        t1 += __shfl_xor_sync(0xFFFFFFFFu, t1, 1);
        t1 += __shfl_xor_sync(0xFFFFFFFFu, t1, 2);
        s0 = s0 * __expf(m0 - nm0) + t0;
        s1 = s1 * __expf(m1 - nm1) + t1;
        m0 = nm0; m1 = nm1;

        __syncthreads();
    }

    if (tg == 0) {
        stats[(size_t)z * SQ + q0 + wbase + g]     = make_float2(m0, 1.f / s0);
        stats[(size_t)z * SQ + q0 + wbase + g + 8] = make_float2(m1, 1.f / s1);
    }
}

// ---------------------------------------------------------------------------
// Phase B: probs + head-mean. Block = (b, q-tile, k-tile); loops 16 heads
// with cp.async pipelining. Recomputes scores tile, p = exp(s-m)*is,
// writes Ph fp16, accumulates mean in regs, writes outMean once.
// ---------------------------------------------------------------------------
__global__ void __launch_bounds__(256, 1)
probs_mean(const __half* __restrict__ Q, const __half* __restrict__ K,
           const float2* __restrict__ stats, __half* __restrict__ Ph,
           float* __restrict__ outMean)
{
    extern __shared__ __align__(16) char smem[];
    const uint32_t sb = smem_u32(smem);
    const int tid = threadIdx.x, lane = tid & 31, wid = tid >> 5;
    const int b  = blockIdx.z;
    const int q0 = blockIdx.y * 128, k0 = blockIdx.x * 128;
    const int g = lane >> 2, tg = lane & 3;
    const int wm = wid & 1, wn = wid >> 1;
    const int mbase = wm * 64, nbase = wn * 32;
    constexpr int STG = 2 * 128 * 144;

    const int a_r = lane & 15;
    const int a_c = ((lane >> 4) & 1) << 3;
    const int b_r = (lane & 7) + (((lane >> 4) & 1) << 3);
    const int b_c = ((lane >> 3) & 1) << 3;

    auto load_tiles = [&](int h, int stg) {
        const int z = (b << 4) + h;
        const __half* Qg = Q + ((size_t)z * SQ + q0) * DKH;
        const __half* Kg = K + ((size_t)z * SQ + k0) * DKH;
        const uint32_t base = sb + (uint32_t)stg * STG;
        #pragma unroll
        for (int idx = tid; idx < 128 * 8; idx += 256) {
            const int r = idx >> 3, ch = idx & 7;
            cp16(base + (uint32_t)r * 144 + ch * 16, Qg + (size_t)r * DKH + ch * 8);
            cp16(base + 128 * 144 + (uint32_t)r * 144 + ch * 16, Kg + (size_t)r * DKH + ch * 8);
        }
    };

    float macc[4][4][4];
    #pragma unroll
    for (int i = 0; i < 4; i++)
        #pragma unroll
        for (int j = 0; j < 4; j++)
            #pragma unroll
            for (int r = 0; r < 4; r++) macc[i][j][r] = 0.f;

    load_tiles(0, 0);
    cp_commit();

    for (int h = 0; h < 16; h++) {
        const int st = h & 1;
        if (h + 1 < 16) { load_tiles(h + 1, st ^ 1); cp_commit(); cp_wait1(); }
        else cp_wait0();
        __syncthreads();

        const uint32_t sQ = sb + (uint32_t)st * STG;
        const uint32_t sK = sQ + 128 * 144;

        float acc[4][4][4];
        #pragma unroll
        for (int i = 0; i < 4; i++)
            #pragma unroll
            for (int j = 0; j < 4; j++)
                #pragma unroll
                for (int r = 0; r < 4; r++) acc[i][j][r] = 0.f;

        #pragma unroll
        for (int ksx = 0; ksx < 4; ksx++) {
            uint32_t ah[4][4], bh[4][2];
            #pragma unroll
            for (int mt = 0; mt < 4; mt++) {
                const uint32_t off = ((uint32_t)(mbase + mt * 16 + a_r) * 72 + ksx * 16 + a_c) * 2;
                LDMX4(ah[mt], sQ + off);
            }
            #pragma unroll
            for (int np = 0; np < 2; np++) {
                const uint32_t off = ((uint32_t)(nbase + np * 16 + b_r) * 72 + ksx * 16 + b_c) * 2;
                uint32_t r4[4];
                LDMX4(r4, sK + off);
                bh[np*2][0]   = r4[0]; bh[np*2][1]   = r4[1];
                bh[np*2+1][0] = r4[2]; bh[np*2+1][1] = r4[3];
            }
            #pragma unroll
            for (int mt = 0; mt < 4; mt++)
                #pragma unroll
                for (int nt = 0; nt < 4; nt++)
                    mma_f16(acc[mt][nt], ah[mt], bh[nt]);
        }

        const int z = (b << 4) + h;
        const float2* strow = stats + (size_t)z * SQ + q0;
        __half* PhZ = Ph + (size_t)z * SQ * SQ;
        #pragma unroll
        for (int mt = 0; mt < 4; mt++) {
            const int r0 = mbase + mt * 16 + g;
            const float2 st0 = strow[r0];
            const float2 st1 = strow[r0 + 8];
            #pragma unroll
            for (int nt = 0; nt < 4; nt++) {
                const int col = nbase + nt * 8 + tg * 2;
                const float p0 = __expf(acc[mt][nt][0] * 0.125f - st0.x) * st0.y;
                const float p1 = __expf(acc[mt][nt][1] * 0.125f - st0.x) * st0.y;
                const float p2 = __expf(acc[mt][nt][2] * 0.125f - st1.x) * st1.y;
                const float p3 = __expf(acc[mt][nt][3] * 0.125f - st1.x) * st1.y;
                macc[mt][nt][0] += p0; macc[mt][nt][1] += p1;
                macc[mt][nt][2] += p2; macc[mt][nt][3] += p3;
                __half2 u0 = __floats2half2_rn(p0, p1);
                __half2 u1 = __floats2half2_rn(p2, p3);
                *(__half2*)(PhZ + (size_t)(q0 + r0) * SQ + k0 + col)     = u0;
                *(__half2*)(PhZ + (size_t)(q0 + r0 + 8) * SQ + k0 + col) = u1;
            }
        }
        __syncthreads();
    }

    // mean write (exclusive tile ownership, no RMW)
    float* om = outMean + (size_t)b * SQ * SQ;
    #pragma unroll
    for (int mt = 0; mt < 4; mt++) {
        const int r0 = mbase + mt * 16 + g;
        #pragma unroll
        for (int nt = 0; nt < 4; nt++) {
            const int col = nbase + nt * 8 + tg * 2;
            *(float2*)&om[(size_t)(q0 + r0) * SQ + k0 + col] =
                make_float2(macc[mt][nt][0] * (1.0f / NH), macc[mt][nt][1] * (1.0f / NH));
            *(float2*)&om[(size_t)(q0 + r0 + 8) * SQ + k0 + col] =
                make_float2(macc[mt][nt][2] * (1.0f / NH), macc[mt][nt][3] * (1.0f / NH));
        }
    }
}

// ---------------------------------------------------------------------------
// fused fp32 -> fp16 conversions
// ---------------------------------------------------------------------------
__global__ void __launch_bounds__(256)
cvt_qkv(const float* __restrict__ a, const float* __restrict__ b2, const float* __restrict__ c,
        __half* __restrict__ oa, __half* __restrict__ ob, __half* __restrict__ oc)
{
    const int zi = blockIdx.z;
    const float* s = zi == 0 ? a : (zi == 1 ? b2 : c);
    __half* d = zi == 0 ? oa : (zi == 1 ? ob : oc);
    const int i = (blockIdx.x * 256 + threadIdx.x) * 4;
    float4 v = *(const float4*)(s + i);
    __half2 p0 = __halves2half2(__float2half_rn(v.x), __float2half_rn(v.y));
    __half2 p1 = __halves2half2(__float2half_rn(v.z), __float2half_rn(v.w));
    uint2 u = {*(uint32_t*)&p0, *(uint32_t*)&p1};
    *(uint2*)(d + i) = u;
}
__global__ void __launch_bounds__(256)
cvt_w(const float* __restrict__ a, const float* __restrict__ b2,
      const float* __restrict__ c, const float* __restrict__ e,
      __half* __restrict__ oa, __half* __restrict__ ob,
      __half* __restrict__ oc, __half* __restrict__ oe)
{
    const int zi = blockIdx.z;
    const float* s = zi == 0 ? a : (zi == 1 ? b2 : (zi == 2 ? c : e));
    __half* d = zi == 0 ? oa : (zi == 1 ? ob : (zi == 2 ? oc : oe));
    const int i = (blockIdx.x * 256 + threadIdx.x) * 4;
    float4 v = *(const float4*)(s + i);
    __half2 p0 = __halves2half2(__float2half_rn(v.x), __float2half_rn(v.y));
    __half2 p1 = __halves2half2(__float2half_rn(v.z), __float2half_rn(v.w));
    uint2 u = {*(uint32_t*)&p0, *(uint32_t*)&p1};
    *(uint2*)(d + i) = u;
}

// ---------------------------------------------------------------------------
// V transpose: [Z, S, 64] -> [Z, 64, S]
// ---------------------------------------------------------------------------
__global__ void __launch_bounds__(256)
v_transpose(const __half* __restrict__ s, __half* __restrict__ d)
{
    __shared__ __half t0[32][33];
    const int z  = blockIdx.z;
    const int s0 = blockIdx.y * 32;
    const int d0 = blockIdx.x * 32;
    const int tx = threadIdx.x, ty = threadIdx.y;
    const size_t zin = (size_t)z * SQ * DKH;
    #pragma unroll
    for (int j = 0; j < 4; j++) {
        const int rs = ty + j * 8;
        t0[rs][tx] = s[zin + (size_t)(s0 + rs) * DKH + d0 + tx];
    }
    __syncthreads();
    const size_t zo = (size_t)z * DKH * SQ;
    #pragma unroll
    for (int j = 0; j < 4; j++) {
        const int rd = ty + j * 8;
        d[zo + (size_t)(d0 + rd) * SQ + s0 + tx] = t0[tx][rd];
    }
}

// ---------------------------------------------------------------------------
extern "C" void kernel_launch(void* const* d_in, const int* in_sizes, int n_in,
                              void* d_out, int out_size)
{
    (void)in_sizes; (void)n_in; (void)out_size;
    const float* q  = (const float*)d_in[0];
    const float* k  = (const float*)d_in[1];
    const float* v  = (const float*)d_in[2];
    const float* Wq = (const float*)d_in[3];
    const float* Wk = (const float*)d_in[4];
    const float* Wv = (const float*)d_in[5];
    const float* Wo = (const float*)d_in[6];
    float* out     = (float*)d_out;
    float* outMean = out + (size_t)MR * DM;

    #define SYM(p, s) void* p; cudaGetSymbolAddress(&p, s)
    SYM(pqx, g_qx); SYM(pkx, g_kx); SYM(pvx, g_vx);
    SYM(pwq, g_wq); SYM(pwk, g_wk); SYM(pwv, g_wv); SYM(pwo, g_wo);
    SYM(pQ, g_Q); SYM(pK, g_K); SYM(pVs, g_Vs); SYM(pVt, g_Vt);
    SYM(pstats, g_stats); SYM(pPh, g_Ph); SYM(pc, g_c);
    #undef SYM

    const int SMEM_128  = 2 * (128 + 128) * 144;  // 73728
    const int SMEM_64   = 2 * (128 + 64) * 144;   // 55296
    const int SMEM_STAT = 3 * 128 * 144;          // 55296
    const int SMEM_PB   = 2 * 2 * 128 * 144;      // 73728
    cudaFuncSetAttribute(hm_gemm<128, 128, 0>, cudaFuncAttributeMaxDynamicSharedMemorySize, SMEM_128);
    cudaFuncSetAttribute(hm_gemm<128, 128, 2>, cudaFuncAttributeMaxDynamicSharedMemorySize, SMEM_128);
    cudaFuncSetAttribute(hm_gemm<128, 64, 3>,  cudaFuncAttributeMaxDynamicSharedMemorySize, SMEM_64);
    cudaFuncSetAttribute(qk_stats,   cudaFuncAttributeMaxDynamicSharedMemorySize, SMEM_STAT);
    cudaFuncSetAttribute(probs_mean, cudaFuncAttributeMaxDynamicSharedMemorySize, SMEM_PB);

    // 1) fp32 -> fp16 conversions (fused)
    cvt_qkv<<<dim3(MR * DM / 1024, 1, 3), 256>>>(q, k, v,
        (__half*)pqx, (__half*)pkx, (__half*)pvx);
    cvt_w<<<dim3(DM * DM / 1024, 1, 4), 256>>>(Wq, Wk, Wv, Wo,
        (__half*)pwq, (__half*)pwk, (__half*)pwv, (__half*)pwo);

    // 2) projections -> scatter fp16 to [B,H,S,dk]
    const dim3 gproj(DM / 128, MR / 128, 1);
    hm_gemm<128, 128, 2><<<gproj, 256, SMEM_128>>>(
        (const __half*)pqx, (const __half*)pwq, nullptr, (__half*)pQ,
        DM, 0, 1.0f, 0, 0, 0);
    hm_gemm<128, 128, 2><<<gproj, 256, SMEM_128>>>(
        (const __half*)pkx, (const __half*)pwk, nullptr, (__half*)pK,
        DM, 0, 1.0f, 0, 0, 0);
    hm_gemm<128, 128, 2><<<gproj, 256, SMEM_128>>>(
        (const __half*)pvx, (const __half*)pwv, nullptr, (__half*)pVs,
        DM, 0, 1.0f, 0, 0, 0);

    // 3) V transpose [Z,S,64] -> [Z,64,S]
    v_transpose<<<dim3(DKH / 32, SQ / 32, NZ), dim3(32, 8)>>>(
        (const __half*)pVs, (__half*)pVt);

    // 4) phase A: softmax row stats (m, 1/s)
    qk_stats<<<dim3(1, SQ / 128, NZ), 256, SMEM_STAT>>>(
        (const __half*)pQ, (const __half*)pK, (float2*)pstats);

    // 5) phase B: probs (fp16) + head mean (fp32, written once)
    probs_mean<<<dim3(SQ / 128, SQ / 128, NB), 256, SMEM_PB>>>(
        (const __half*)pQ, (const __half*)pK, (const float2*)pstats,
        (__half*)pPh, outMean);

    // 6) ctx = P @ V  -> fp16 [S,B,D]
    hm_gemm<128, 64, 3><<<dim3(1, SQ / 128, NZ), 256, SMEM_64>>>(
        (const __half*)pPh, (const __half*)pVt, nullptr, (__half*)pc,
        SQ, 0, 1.0f, (size_t)SQ * SQ, (size_t)DKH * SQ, 0);

    // 7) out = ctx @ Wo^T  fp32
    hm_gemm<128, 128, 0><<<gproj, 256, SMEM_128>>>(
        (const __half*)pc, (const __half*)pwo, out, nullptr,
        DM, DM, 1.0f, 0, 0, 0);
}

// round 8
// speedup vs baseline: 4.3984x; 1.0235x over previous
#include <cuda_runtime.h>
#include <cuda_fp16.h>
#include <cstdint>

#define SQ  2048
#define NB  2
#define DM  1024
#define NH  16
#define DKH 64
#define MR  4096              // S*B rows
#define NZ  (NB*NH)           // 32 batch*head slices

// ---------------------------------------------------------------------------
// Scratch (__device__ globals: allocation-free)
// ---------------------------------------------------------------------------
__device__ __half g_qx[(size_t)MR*DM], g_kx[(size_t)MR*DM], g_vx[(size_t)MR*DM];
__device__ __half g_wq[(size_t)DM*DM], g_wk[(size_t)DM*DM];
__device__ __half g_wv[(size_t)DM*DM], g_wo[(size_t)DM*DM];
__device__ __half g_Q[(size_t)NZ*SQ*DKH], g_K[(size_t)NZ*SQ*DKH];
__device__ __half g_Vs[(size_t)NZ*SQ*DKH];          // [Z,S,dk]
__device__ __half g_Vt[(size_t)NZ*DKH*SQ];          // [Z,dk,S]
__device__ float2 g_stats[(size_t)NZ*SQ];           // (row max, 1/row sum)
__device__ __half g_Ph[(size_t)NZ*SQ*SQ];           // 268 MB fp16 probs
__device__ __half g_c [(size_t)MR*DM];              // ctx [S,B,D]

// ---------------------------------------------------------------------------
// PTX helpers (base-arch: mma.sync / ldmatrix / cp.async)
// ---------------------------------------------------------------------------
__device__ __forceinline__ uint32_t smem_u32(const void* p) {
    uint32_t a;
    asm("{ .reg .u64 t; cvta.to.shared.u64 t, %1; cvt.u32.u64 %0, t; }" : "=r"(a) : "l"(p));
    return a;
}
__device__ __forceinline__ void cp16(uint32_t d, const void* s) {
    asm volatile("cp.async.cg.shared.global [%0], [%1], 16;" :: "r"(d), "l"(s));
}
__device__ __forceinline__ void cp_commit() {
    asm volatile("cp.async.commit_group;" ::: "memory");
}
__device__ __forceinline__ void cp_wait1() {
    asm volatile("cp.async.wait_group 1;" ::: "memory");
}
__device__ __forceinline__ void cp_wait0() {
    asm volatile("cp.async.wait_group 0;" ::: "memory");
}
#define LDMX4(r, a) \
    asm volatile("ldmatrix.sync.aligned.m8n8.x4.shared.b16 {%0,%1,%2,%3}, [%4];" \
        : "=r"((r)[0]), "=r"((r)[1]), "=r"((r)[2]), "=r"((r)[3]) : "r"(a))

__device__ __forceinline__ void mma_f16(float* c, const uint32_t* a, const uint32_t* b) {
    asm volatile(
        "mma.sync.aligned.m16n8k16.row.col.f32.f16.f16.f32 "
        "{%0,%1,%2,%3},{%4,%5,%6,%7},{%8,%9},{%0,%1,%2,%3};"
        : "+f"(c[0]), "+f"(c[1]), "+f"(c[2]), "+f"(c[3])
        : "r"(a[0]), "r"(a[1]), "r"(a[2]), "r"(a[3]), "r"(b[0]), "r"(b[1]));
}

// ---------------------------------------------------------------------------
// Shared GEMM body (2-stage cp.async): C = alpha * A(MxK) * B(NxK)^T
// A,B pre-offset to (m0,n0) tile origin. EPI: 0 fp32 row-major; 2 fp16
// scatter to [B,H,S,dk]; 3 fp16 ctx write to [S,B,D].
// ---------------------------------------------------------------------------
template<int BM, int BN, int EPI>
__device__ __forceinline__ void gemm_body(
    const __half* __restrict__ A, const __half* __restrict__ B,
    float* __restrict__ Cf, __half* __restrict__ Ch,
    int K, int ldc, float alpha, int z, int m0, int n0, char* smem)
{
    const uint32_t sb = smem_u32(smem);
    const int tid  = threadIdx.x;
    const int lane = tid & 31;
    const int wid  = tid >> 5;

    constexpr int WGM = (BN == 128) ? 2 : 4;
    constexpr int TM  = BM / WGM;
    constexpr int TN  = BN / (8 / WGM);
    constexpr int MT  = TM / 16;
    constexpr int NT  = TN / 8;
    constexpr int STAGE = (BM + BN) * 144;

    const int wm = wid % WGM, wn = wid / WGM;
    const int mbase = wm * TM, nbase = wn * TN;

    float acc[MT][NT][4];
    #pragma unroll
    for (int i = 0; i < MT; i++)
        #pragma unroll
        for (int j = 0; j < NT; j++)
            #pragma unroll
            for (int r = 0; r < 4; r++) acc[i][j][r] = 0.f;

    const int a_r = lane & 15;
    const int a_c = ((lane >> 4) & 1) << 3;
    const int b_r = (lane & 7) + (((lane >> 4) & 1) << 3);
    const int b_c = ((lane >> 3) & 1) << 3;

    auto load_stage = [&](int kc, int stg) {
        const uint32_t base = sb + (uint32_t)stg * STAGE;
        #pragma unroll
        for (int idx = tid; idx < BM * 8; idx += 256) {
            const int r = idx >> 3, ch = idx & 7;
            cp16(base + (uint32_t)r * 144 + ch * 16, A + (size_t)r * K + kc + ch * 8);
        }
        #pragma unroll
        for (int idx = tid; idx < BN * 8; idx += 256) {
            const int r = idx >> 3, ch = idx & 7;
            cp16(base + BM * 144 + (uint32_t)r * 144 + ch * 16, B + (size_t)r * K + kc + ch * 8);
        }
    };

    auto compute = [&](int stg) {
        const uint32_t sA0 = sb + (uint32_t)stg * STAGE;
        const uint32_t sB0 = sA0 + BM * 144;
        #pragma unroll
        for (int ks = 0; ks < 4; ks++) {
            uint32_t ah[MT][4], bh[NT][2];
            #pragma unroll
            for (int mt = 0; mt < MT; mt++) {
                const uint32_t off = ((uint32_t)(mbase + mt * 16 + a_r) * 72 + ks * 16 + a_c) * 2;
                LDMX4(ah[mt], sA0 + off);
            }
            #pragma unroll
            for (int np = 0; np < NT / 2; np++) {
                const uint32_t off = ((uint32_t)(nbase + np * 16 + b_r) * 72 + ks * 16 + b_c) * 2;
                uint32_t r4[4];
                LDMX4(r4, sB0 + off);
                bh[np*2][0]   = r4[0]; bh[np*2][1]   = r4[1];
                bh[np*2+1][0] = r4[2]; bh[np*2+1][1] = r4[3];
            }
            #pragma unroll
            for (int mt = 0; mt < MT; mt++)
                #pragma unroll
                for (int nt = 0; nt < NT; nt++)
                    mma_f16(acc[mt][nt], ah[mt], bh[nt]);
        }
    };

    const int NC = K >> 6;
    load_stage(0, 0);
    cp_commit();

    for (int c = 0; c < NC; c++) {
        const int buf = c & 1;
        if (c + 1 < NC) {
            load_stage((c + 1) << 6, buf ^ 1);
            cp_commit();
            cp_wait1();
        } else {
            cp_wait0();
        }
        __syncthreads();
        compute(buf);
        __syncthreads();
    }

    // ---- epilogue: frags -> smem -> coalesced gmem ----
    constexpr int CP = BN + 4;
    float* Cs = (float*)smem;
    const int g = lane >> 2, tg = lane & 3;
    #pragma unroll
    for (int mt = 0; mt < MT; mt++)
        #pragma unroll
        for (int nt = 0; nt < NT; nt++) {
            const int row = mbase + mt * 16 + g;
            const int col = nbase + nt * 8 + tg * 2;
            *(float2*)&Cs[(size_t)row * CP + col]       = make_float2(acc[mt][nt][0], acc[mt][nt][1]);
            *(float2*)&Cs[(size_t)(row + 8) * CP + col] = make_float2(acc[mt][nt][2], acc[mt][nt][3]);
        }
    __syncthreads();

    for (int i4 = tid * 4; i4 < BM * BN; i4 += 1024) {
        const int row = i4 / BN, col = i4 % BN;
        float4 v = *(const float4*)&Cs[(size_t)row * CP + col];
        v.x *= alpha; v.y *= alpha; v.z *= alpha; v.w *= alpha;
        const int m = m0 + row, n = n0 + col;
        if (EPI == 0) {
            *(float4*)&Cf[(size_t)m * ldc + n] = v;
        } else {
            __half2 p0 = __halves2half2(__float2half_rn(v.x), __float2half_rn(v.y));
            __half2 p1 = __halves2half2(__float2half_rn(v.z), __float2half_rn(v.w));
            uint2 u = {*(uint32_t*)&p0, *(uint32_t*)&p1};
            size_t addr;
            if (EPI == 2) {
                const int s2 = m >> 1, b = m & 1, hh = n >> 6, dk = n & 63;
                addr = ((size_t)(b * NH + hh) * SQ + s2) * DKH + dk;
            } else { // EPI == 3
                const int b = z >> 4, hh = z & 15;
                addr = ((size_t)m * NB + b) * DM + (size_t)hh * DKH + n;
            }
            *(uint2*)(Ch + addr) = u;
        }
    }
}

// ---------------------------------------------------------------------------
// Fused Q/K/V projection: grid.z selects (input, weight, output) triple.
// ---------------------------------------------------------------------------
__global__ void __launch_bounds__(256, 2)
hm_proj(const __half* __restrict__ A0, const __half* __restrict__ A1, const __half* __restrict__ A2,
        const __half* __restrict__ B0, const __half* __restrict__ B1, const __half* __restrict__ B2,
        __half* __restrict__ C0, __half* __restrict__ C1, __half* __restrict__ C2)
{
    extern __shared__ __align__(16) char smem[];
    const int zi = blockIdx.z;
    const __half* A = (zi == 0) ? A0 : (zi == 1) ? A1 : A2;
    const __half* B = (zi == 0) ? B0 : (zi == 1) ? B1 : B2;
    __half*       C = (zi == 0) ? C0 : (zi == 1) ? C1 : C2;
    const int m0 = blockIdx.y * 128, n0 = blockIdx.x * 128;
    gemm_body<128, 128, 2>(A + (size_t)m0 * DM, B + (size_t)n0 * DM,
                           nullptr, C, DM, 0, 1.0f, 0, m0, n0, smem);
}

// ---------------------------------------------------------------------------
// Output projection: out = ctx @ Wo^T (fp32 out)
// ---------------------------------------------------------------------------
__global__ void __launch_bounds__(256, 2)
hm_wo(const __half* __restrict__ A, const __half* __restrict__ B, float* __restrict__ Cf)
{
    extern __shared__ __align__(16) char smem[];
    const int m0 = blockIdx.y * 128, n0 = blockIdx.x * 128;
    gemm_body<128, 128, 0>(A + (size_t)m0 * DM, B + (size_t)n0 * DM,
                           Cf, nullptr, DM, DM, 1.0f, 0, m0, n0, smem);
}

// ---------------------------------------------------------------------------
// PV GEMM, 3-stage cp.async pipeline, one sync per K-chunk.
// ctx[128 x 64] per block; A = Ph (fp16, K=SQ), B = Vt (fp16, K-major).
// ---------------------------------------------------------------------------
__global__ void __launch_bounds__(256, 2)
pv_gemm3(const __half* __restrict__ Ph, const __half* __restrict__ Vt,
         __half* __restrict__ Ch)
{
    extern __shared__ __align__(16) char smem[];
    const uint32_t sb = smem_u32(smem);
    const int tid  = threadIdx.x;
    const int lane = tid & 31;
    const int wid  = tid >> 5;
    const int z    = blockIdx.z;
    const int m0   = blockIdx.y * 128;
    constexpr int BM = 128, BN = 64;
    constexpr int STAGE = (BM + BN) * 144;     // 27648
    constexpr int MT = 2, NT = 4;              // warp tile 32x32, WGM=4

    const int wm = wid & 3, wn = wid >> 2;
    const int mbase = wm * 32, nbase = wn * 32;

    const __half* A = Ph + ((size_t)z * SQ + m0) * SQ;
    const __half* B = Vt + (size_t)z * DKH * SQ;

    float acc[MT][NT][4];
    #pragma unroll
    for (int i = 0; i < MT; i++)
        #pragma unroll
        for (int j = 0; j < NT; j++)
            #pragma unroll
            for (int r = 0; r < 4; r++) acc[i][j][r] = 0.f;

    const int a_r = lane & 15;
    const int a_c = ((lane >> 4) & 1) << 3;
    const int b_r = (lane & 7) + (((lane >> 4) & 1) << 3);
    const int b_c = ((lane >> 3) & 1) << 3;

    auto load_stage = [&](int kc, int stg) {
        const uint32_t base = sb + (uint32_t)stg * STAGE;
        #pragma unroll
        for (int idx = tid; idx < BM * 8; idx += 256) {
            const int r = idx >> 3, ch = idx & 7;
            cp16(base + (uint32_t)r * 144 + ch * 16, A + (size_t)r * SQ + kc + ch * 8);
        }
        #pragma unroll
        for (int idx = tid; idx < BN * 8; idx += 256) {
            const int r = idx >> 3, ch = idx & 7;
            cp16(base + BM * 144 + (uint32_t)r * 144 + ch * 16, B + (size_t)r * SQ + kc + ch * 8);
        }
    };

    constexpr int NC = SQ >> 6;    // 32
    load_stage(0, 0);  cp_commit();
    load_stage(64, 1); cp_commit();

    for (int c = 0; c < NC; c++) {
        if (c + 1 < NC) cp_wait1(); else cp_wait0();
        __syncthreads();
        if (c + 2 < NC) { load_stage((c + 2) << 6, (c + 2) % 3); cp_commit(); }

        const uint32_t sA0 = sb + (uint32_t)(c % 3) * STAGE;
        const uint32_t sB0 = sA0 + BM * 144;
        #pragma unroll
        for (int ks = 0; ks < 4; ks++) {
            uint32_t ah[MT][4], bh[NT][2];
            #pragma unroll
            for (int mt = 0; mt < MT; mt++) {
                const uint32_t off = ((uint32_t)(mbase + mt * 16 + a_r) * 72 + ks * 16 + a_c) * 2;
                LDMX4(ah[mt], sA0 + off);
            }
            #pragma unroll
            for (int np = 0; np < NT / 2; np++) {
                const uint32_t off = ((uint32_t)(nbase + np * 16 + b_r) * 72 + ks * 16 + b_c) * 2;
                uint32_t r4[4];
                LDMX4(r4, sB0 + off);
                bh[np*2][0]   = r4[0]; bh[np*2][1]   = r4[1];
                bh[np*2+1][0] = r4[2]; bh[np*2+1][1] = r4[3];
            }
            #pragma unroll
            for (int mt = 0; mt < MT; mt++)
                #pragma unroll
                for (int nt = 0; nt < NT; nt++)
                    mma_f16(acc[mt][nt], ah[mt], bh[nt]);
        }
    }
    __syncthreads();

    // epilogue: stage in smem, write fp16 ctx coalesced
    constexpr int CP = BN + 4;
    float* Cs = (float*)smem;
    const int g = lane >> 2, tg = lane & 3;
    #pragma unroll
    for (int mt = 0; mt < MT; mt++)
        #pragma unroll
        for (int nt = 0; nt < NT; nt++) {
            const int row = mbase + mt * 16 + g;
            const int col = nbase + nt * 8 + tg * 2;
            *(float2*)&Cs[(size_t)row * CP + col]       = make_float2(acc[mt][nt][0], acc[mt][nt][1]);
            *(float2*)&Cs[(size_t)(row + 8) * CP + col] = make_float2(acc[mt][nt][2], acc[mt][nt][3]);
        }
    __syncthreads();

    const int b = z >> 4, hh = z & 15;
    for (int i4 = tid * 4; i4 < BM * BN; i4 += 1024) {
        const int row = i4 / BN, col = i4 % BN;
        float4 v = *(const float4*)&Cs[(size_t)row * CP + col];
        __half2 p0 = __halves2half2(__float2half_rn(v.x), __float2half_rn(v.y));
        __half2 p1 = __halves2half2(__float2half_rn(v.z), __float2half_rn(v.w));
        uint2 u = {*(uint32_t*)&p0, *(uint32_t*)&p1};
        const int m = m0 + row;
        *(uint2*)(Ch + ((size_t)m * NB + b) * DM + (size_t)hh * DKH + col) = u;
    }
}

// ---------------------------------------------------------------------------
// Phase A: per-row softmax stats (m, 1/s). Block = (z, 128-row q-tile).
// ---------------------------------------------------------------------------
__global__ void __launch_bounds__(256, 2)
qk_stats(const __half* __restrict__ Q, const __half* __restrict__ K,
         float2* __restrict__ stats)
{
    extern __shared__ __align__(16) char smem[];
    const uint32_t sb = smem_u32(smem);
    const int tid = threadIdx.x, lane = tid & 31, wid = tid >> 5;
    const int z = blockIdx.z, q0 = blockIdx.y * 128;
    const int g = lane >> 2, tg = lane & 3;
    const int wbase = wid * 16;

    const __half* Qg = Q + ((size_t)z * SQ + q0) * DKH;
    const __half* Kg = K + (size_t)z * SQ * DKH;

    const uint32_t qs = sb;
    const uint32_t ks = sb + 128 * 144;

    auto loadK = [&](int kt, int stg) {
        const uint32_t base = ks + (uint32_t)stg * (128 * 144);
        #pragma unroll
        for (int idx = tid; idx < 128 * 8; idx += 256) {
            const int r = idx >> 3, ch = idx & 7;
            cp16(base + (uint32_t)r * 144 + ch * 16,
                 Kg + ((size_t)(kt * 128 + r)) * DKH + ch * 8);
        }
    };

    #pragma unroll
    for (int idx = tid; idx < 128 * 8; idx += 256) {
        const int r = idx >> 3, ch = idx & 7;
        cp16(qs + (uint32_t)r * 144 + ch * 16, Qg + (size_t)r * DKH + ch * 8);
    }
    loadK(0, 0);
    cp_commit();

    const int a_r = lane & 15;
    const int a_c = ((lane >> 4) & 1) << 3;
    const int b_r = (lane & 7) + (((lane >> 4) & 1) << 3);
    const int b_c = ((lane >> 3) & 1) << 3;

    float m0 = -3.4e38f, m1 = -3.4e38f, s0 = 0.f, s1 = 0.f;

    for (int kt = 0; kt < SQ / 128; kt++) {
        const int buf = kt & 1;
        if (kt + 1 < SQ / 128) { loadK(kt + 1, buf ^ 1); cp_commit(); cp_wait1(); }
        else cp_wait0();
        __syncthreads();

        float acc[16][4];
        #pragma unroll
        for (int nt = 0; nt < 16; nt++)
            acc[nt][0] = acc[nt][1] = acc[nt][2] = acc[nt][3] = 0.f;

        const uint32_t kb = ks + (uint32_t)buf * (128 * 144);
        #pragma unroll
        for (int ksx = 0; ksx < 4; ksx++) {
            uint32_t ah[4];
            LDMX4(ah, qs + ((uint32_t)(wbase + a_r) * 72 + ksx * 16 + a_c) * 2);
            uint32_t bh[16][2];
            #pragma unroll
            for (int np = 0; np < 8; np++) {
                uint32_t r4[4];
                LDMX4(r4, kb + ((uint32_t)(np * 16 + b_r) * 72 + ksx * 16 + b_c) * 2);
                bh[np*2][0]   = r4[0]; bh[np*2][1]   = r4[1];
                bh[np*2+1][0] = r4[2]; bh[np*2+1][1] = r4[3];
            }
            #pragma unroll
            for (int nt = 0; nt < 16; nt++) mma_f16(acc[nt], ah, bh[nt]);
        }

        float mx0 = -3.4e38f, mx1 = -3.4e38f;
        #pragma unroll
        for (int nt = 0; nt < 16; nt++) {
            mx0 = fmaxf(mx0, fmaxf(acc[nt][0], acc[nt][1]));
            mx1 = fmaxf(mx1, fmaxf(acc[nt][2], acc[nt][3]));
        }
        mx0 = fmaxf(mx0, __shfl_xor_sync(0xFFFFFFFFu, mx0, 1));
        mx0 = fmaxf(mx0, __shfl_xor_sync(0xFFFFFFFFu, mx0, 2));
        mx1 = fmaxf(mx1, __shfl_xor_sync(0xFFFFFFFFu, mx1, 1));
        mx1 = fmaxf(mx1, __shfl_xor_sync(0xFFFFFFFFu, mx1, 2));
        const float nm0 = fmaxf(m0, mx0 * 0.125f);
        const float nm1 = fmaxf(m1, mx1 * 0.125f);
        float t0 = 0.f, t1 = 0.f;
        #pragma unroll
        for (int nt = 0; nt < 16; nt++) {
            t0 += __expf(acc[nt][0] * 0.125f - nm0) + __expf(acc[nt][1] * 0.125f - nm0);
            t1 += __expf(acc[nt][2] * 0.125f - nm1) + __expf(acc[nt][3] * 0.125f - nm1);
        }
        t0 += __shfl_xor_sync(0xFFFFFFFFu, t0, 1);
        t0 += __shfl_xor_sync(0xFFFFFFFFu, t0, 2);
        t1 += __shfl_xor_sync(0xFFFFFFFFu, t1, 1);
        t1 += __shfl_xor_sync(0xFFFFFFFFu, t1, 2);
        s0 = s0 * __expf(m0 - nm0) + t0;
        s1 = s1 * __expf(m1 - nm1) + t1;
        m0 = nm0; m1 = nm1;

        __syncthreads();
    }

    if (tg == 0) {
        stats[(size_t)z * SQ + q0 + wbase + g]     = make_float2(m0, 1.f / s0);
        stats[(size_t)z * SQ + q0 + wbase + g + 8] = make_float2(m1, 1.f / s1);
    }
}

// ---------------------------------------------------------------------------
// Phase B: probs (fp16) + head-mean (fp32, written once per tile).
// Block = (b, q-tile, k-tile); loops 16 heads with cp.async pipelining.
// ---------------------------------------------------------------------------
__global__ void __launch_bounds__(256, 1)
probs_mean(const __half* __restrict__ Q, const __half* __restrict__ K,
           const float2* __restrict__ stats, __half* __restrict__ Ph,
           float* __restrict__ outMean)
{
    extern __shared__ __align__(16) char smem[];
    const uint32_t sb = smem_u32(smem);
    const int tid = threadIdx.x, lane = tid & 31, wid = tid >> 5;
    const int b  = blockIdx.z;
    const int q0 = blockIdx.y * 128, k0 = blockIdx.x * 128;
    const int g = lane >> 2, tg = lane & 3;
    const int wm = wid & 1, wn = wid >> 1;
    const int mbase = wm * 64, nbase = wn * 32;
    constexpr int STG = 2 * 128 * 144;

    const int a_r = lane & 15;
    const int a_c = ((lane >> 4) & 1) << 3;
    const int b_r = (lane & 7) + (((lane >> 4) & 1) << 3);
    const int b_c = ((lane >> 3) & 1) << 3;

    auto load_tiles = [&](int h, int stg) {
        const int z = (b << 4) + h;
        const __half* Qg = Q + ((size_t)z * SQ + q0) * DKH;
        const __half* Kg = K + ((size_t)z * SQ + k0) * DKH;
        const uint32_t base = sb + (uint32_t)stg * STG;
        #pragma unroll
        for (int idx = tid; idx < 128 * 8; idx += 256) {
            const int r = idx >> 3, ch = idx & 7;
            cp16(base + (uint32_t)r * 144 + ch * 16, Qg + (size_t)r * DKH + ch * 8);
            cp16(base + 128 * 144 + (uint32_t)r * 144 + ch * 16, Kg + (size_t)r * DKH + ch * 8);
        }
    };

    float macc[4][4][4];
    #pragma unroll
    for (int i = 0; i < 4; i++)
        #pragma unroll
        for (int j = 0; j < 4; j++)
            #pragma unroll
            for (int r = 0; r < 4; r++) macc[i][j][r] = 0.f;

    load_tiles(0, 0);
    cp_commit();

    for (int h = 0; h < 16; h++) {
        const int st = h & 1;
        if (h + 1 < 16) { load_tiles(h + 1, st ^ 1); cp_commit(); cp_wait1(); }
        else cp_wait0();
        __syncthreads();

        const uint32_t sQ = sb + (uint32_t)st * STG;
        const uint32_t sK = sQ + 128 * 144;

        float acc[4][4][4];
        #pragma unroll
        for (int i = 0; i < 4; i++)
            #pragma unroll
            for (int j = 0; j < 4; j++)
                #pragma unroll
                for (int r = 0; r < 4; r++) acc[i][j][r] = 0.f;

        #pragma unroll
        for (int ksx = 0; ksx < 4; ksx++) {
            uint32_t ah[4][4], bh[4][2];
            #pragma unroll
            for (int mt = 0; mt < 4; mt++) {
                const uint32_t off = ((uint32_t)(mbase + mt * 16 + a_r) * 72 + ksx * 16 + a_c) * 2;
                LDMX4(ah[mt], sQ + off);
            }
            #pragma unroll
            for (int np = 0; np < 2; np++) {
                const uint32_t off = ((uint32_t)(nbase + np * 16 + b_r) * 72 + ksx * 16 + b_c) * 2;
                uint32_t r4[4];
                LDMX4(r4, sK + off);
                bh[np*2][0]   = r4[0]; bh[np*2][1]   = r4[1];
                bh[np*2+1][0] = r4[2]; bh[np*2+1][1] = r4[3];
            }
            #pragma unroll
            for (int mt = 0; mt < 4; mt++)
                #pragma unroll
                for (int nt = 0; nt < 4; nt++)
                    mma_f16(acc[mt][nt], ah[mt], bh[nt]);
        }

        const int z = (b << 4) + h;
        const float2* strow = stats + (size_t)z * SQ + q0;
        __half* PhZ = Ph + (size_t)z * SQ * SQ;
        #pragma unroll
        for (int mt = 0; mt < 4; mt++) {
            const int r0 = mbase + mt * 16 + g;
            const float2 st0 = strow[r0];
            const float2 st1 = strow[r0 + 8];
            #pragma unroll
            for (int nt = 0; nt < 4; nt++) {
                const int col = nbase + nt * 8 + tg * 2;
                const float p0 = __expf(acc[mt][nt][0] * 0.125f - st0.x) * st0.y;
                const float p1 = __expf(acc[mt][nt][1] * 0.125f - st0.x) * st0.y;
                const float p2 = __expf(acc[mt][nt][2] * 0.125f - st1.x) * st1.y;
                const float p3 = __expf(acc[mt][nt][3] * 0.125f - st1.x) * st1.y;
                macc[mt][nt][0] += p0; macc[mt][nt][1] += p1;
                macc[mt][nt][2] += p2; macc[mt][nt][3] += p3;
                __half2 u0 = __floats2half2_rn(p0, p1);
                __half2 u1 = __floats2half2_rn(p2, p3);
                *(__half2*)(PhZ + (size_t)(q0 + r0) * SQ + k0 + col)     = u0;
                *(__half2*)(PhZ + (size_t)(q0 + r0 + 8) * SQ + k0 + col) = u1;
            }
        }
        __syncthreads();
    }

    float* om = outMean + (size_t)b * SQ * SQ;
    #pragma unroll
    for (int mt = 0; mt < 4; mt++) {
        const int r0 = mbase + mt * 16 + g;
        #pragma unroll
        for (int nt = 0; nt < 4; nt++) {
            const int col = nbase + nt * 8 + tg * 2;
            *(float2*)&om[(size_t)(q0 + r0) * SQ + k0 + col] =
                make_float2(macc[mt][nt][0] * (1.0f / NH), macc[mt][nt][1] * (1.0f / NH));
            *(float2*)&om[(size_t)(q0 + r0 + 8) * SQ + k0 + col] =
                make_float2(macc[mt][nt][2] * (1.0f / NH), macc[mt][nt][3] * (1.0f / NH));
        }
    }
}

// ---------------------------------------------------------------------------
// fused fp32 -> fp16 conversions
// ---------------------------------------------------------------------------
__global__ void __launch_bounds__(256)
cvt_qkv(const float* __restrict__ a, const float* __restrict__ b2, const float* __restrict__ c,
        __half* __restrict__ oa, __half* __restrict__ ob, __half* __restrict__ oc)
{
    const int zi = blockIdx.z;
    const float* s = zi == 0 ? a : (zi == 1 ? b2 : c);
    __half* d = zi == 0 ? oa : (zi == 1 ? ob : oc);
    const int i = (blockIdx.x * 256 + threadIdx.x) * 4;
    float4 v = *(const float4*)(s + i);
    __half2 p0 = __halves2half2(__float2half_rn(v.x), __float2half_rn(v.y));
    __half2 p1 = __halves2half2(__float2half_rn(v.z), __float2half_rn(v.w));
    uint2 u = {*(uint32_t*)&p0, *(uint32_t*)&p1};
    *(uint2*)(d + i) = u;
}
__global__ void __launch_bounds__(256)
cvt_w(const float* __restrict__ a, const float* __restrict__ b2,
      const float* __restrict__ c, const float* __restrict__ e,
      __half* __restrict__ oa, __half* __restrict__ ob,
      __half* __restrict__ oc, __half* __restrict__ oe)
{
    const int zi = blockIdx.z;
    const float* s = zi == 0 ? a : (zi == 1 ? b2 : (zi == 2 ? c : e));
    __half* d = zi == 0 ? oa : (zi == 1 ? ob : (zi == 2 ? oc : oe));
    const int i = (blockIdx.x * 256 + threadIdx.x) * 4;
    float4 v = *(const float4*)(s + i);
    __half2 p0 = __halves2half2(__float2half_rn(v.x), __float2half_rn(v.y));
    __half2 p1 = __halves2half2(__float2half_rn(v.z), __float2half_rn(v.w));
    uint2 u = {*(uint32_t*)&p0, *(uint32_t*)&p1};
    *(uint2*)(d + i) = u;
}

// ---------------------------------------------------------------------------
// V transpose: [Z, S, 64] -> [Z, 64, S]
// ---------------------------------------------------------------------------
__global__ void __launch_bounds__(256)
v_transpose(const __half* __restrict__ s, __half* __restrict__ d)
{
    __shared__ __half t0[32][33];
    const int z  = blockIdx.z;
    const int s0 = blockIdx.y * 32;
    const int d0 = blockIdx.x * 32;
    const int tx = threadIdx.x, ty = threadIdx.y;
    const size_t zin = (size_t)z * SQ * DKH;
    #pragma unroll
    for (int j = 0; j < 4; j++) {
        const int rs = ty + j * 8;
        t0[rs][tx] = s[zin + (size_t)(s0 + rs) * DKH + d0 + tx];
    }
    __syncthreads();
    const size_t zo = (size_t)z * DKH * SQ;
    #pragma unroll
    for (int j = 0; j < 4; j++) {
        const int rd = ty + j * 8;
        d[zo + (size_t)(d0 + rd) * SQ + s0 + tx] = t0[tx][rd];
    }
}

// ---------------------------------------------------------------------------
extern "C" void kernel_launch(void* const* d_in, const int* in_sizes, int n_in,
                              void* d_out, int out_size)
{
    (void)in_sizes; (void)n_in; (void)out_size;
    const float* q  = (const float*)d_in[0];
    const float* k  = (const float*)d_in[1];
    const float* v  = (const float*)d_in[2];
    const float* Wq = (const float*)d_in[3];
    const float* Wk = (const float*)d_in[4];
    const float* Wv = (const float*)d_in[5];
    const float* Wo = (const float*)d_in[6];
    float* out     = (float*)d_out;
    float* outMean = out + (size_t)MR * DM;

    #define SYM(p, s) void* p; cudaGetSymbolAddress(&p, s)
    SYM(pqx, g_qx); SYM(pkx, g_kx); SYM(pvx, g_vx);
    SYM(pwq, g_wq); SYM(pwk, g_wk); SYM(pwv, g_wv); SYM(pwo, g_wo);
    SYM(pQ, g_Q); SYM(pK, g_K); SYM(pVs, g_Vs); SYM(pVt, g_Vt);
    SYM(pstats, g_stats); SYM(pPh, g_Ph); SYM(pc, g_c);
    #undef SYM

    const int SMEM_GEMM = 2 * (128 + 128) * 144;  // 73728
    const int SMEM_PV   = 3 * (128 + 64) * 144;   // 82944
    const int SMEM_STAT = 3 * 128 * 144;          // 55296
    const int SMEM_PB   = 2 * 2 * 128 * 144;      // 73728
    cudaFuncSetAttribute(hm_proj,    cudaFuncAttributeMaxDynamicSharedMemorySize, SMEM_GEMM);
    cudaFuncSetAttribute(hm_wo,      cudaFuncAttributeMaxDynamicSharedMemorySize, SMEM_GEMM);
    cudaFuncSetAttribute(pv_gemm3,   cudaFuncAttributeMaxDynamicSharedMemorySize, SMEM_PV);
    cudaFuncSetAttribute(qk_stats,   cudaFuncAttributeMaxDynamicSharedMemorySize, SMEM_STAT);
    cudaFuncSetAttribute(probs_mean, cudaFuncAttributeMaxDynamicSharedMemorySize, SMEM_PB);

    // 1) fp32 -> fp16 conversions
    cvt_qkv<<<dim3(MR * DM / 1024, 1, 3), 256>>>(q, k, v,
        (__half*)pqx, (__half*)pkx, (__half*)pvx);
    cvt_w<<<dim3(DM * DM / 1024, 1, 4), 256>>>(Wq, Wk, Wv, Wo,
        (__half*)pwq, (__half*)pwk, (__half*)pwv, (__half*)pwo);

    // 2) fused Q/K/V projections (one launch, 768 blocks)
    hm_proj<<<dim3(DM / 128, MR / 128, 3), 256, SMEM_GEMM>>>(
        (const __half*)pqx, (const __half*)pkx, (const __half*)pvx,
        (const __half*)pwq, (const __half*)pwk, (const __half*)pwv,
        (__half*)pQ, (__half*)pK, (__half*)pVs);

    // 3) V transpose [Z,S,64] -> [Z,64,S]
    v_transpose<<<dim3(DKH / 32, SQ / 32, NZ), dim3(32, 8)>>>(
        (const __half*)pVs, (__half*)pVt);

    // 4) phase A: softmax row stats (m, 1/s)
    qk_stats<<<dim3(1, SQ / 128, NZ), 256, SMEM_STAT>>>(
        (const __half*)pQ, (const __half*)pK, (float2*)pstats);

    // 5) phase B: probs (fp16) + head mean (fp32, written once)
    probs_mean<<<dim3(SQ / 128, SQ / 128, NB), 256, SMEM_PB>>>(
        (const __half*)pQ, (const __half*)pK, (const float2*)pstats,
        (__half*)pPh, outMean);

    // 6) ctx = P @ V  (3-stage pipeline)
    pv_gemm3<<<dim3(1, SQ / 128, NZ), 256, SMEM_PV>>>(
        (const __half*)pPh, (const __half*)pVt, (__half*)pc);

    // 7) out = ctx @ Wo^T
    hm_wo<<<dim3(DM / 128, MR / 128, 1), 256, SMEM_GEMM>>>(
        (const __half*)pc, (const __half*)pwo, out);
}

// round 9
// speedup vs baseline: 4.4044x; 1.0014x over previous
#include <cuda_runtime.h>
#include <cuda_fp16.h>
#include <cstdint>

#define SQ  2048
#define NB  2
#define DM  1024
#define NH  16
#define DKH 64
#define MR  4096              // S*B rows
#define NZ  (NB*NH)           // 32 batch*head slices

// ---------------------------------------------------------------------------
// Scratch (__device__ globals: allocation-free)
// ---------------------------------------------------------------------------
__device__ __half g_qx[(size_t)MR*DM], g_kx[(size_t)MR*DM], g_vx[(size_t)MR*DM];
__device__ __half g_wq[(size_t)DM*DM], g_wk[(size_t)DM*DM];
__device__ __half g_wv[(size_t)DM*DM], g_wo[(size_t)DM*DM];
__device__ __half g_Q[(size_t)NZ*SQ*DKH], g_K[(size_t)NZ*SQ*DKH];
__device__ __half g_Vs[(size_t)NZ*SQ*DKH];          // [Z,S,dk]
__device__ __half g_Vt[(size_t)NZ*DKH*SQ];          // [Z,dk,S]
__device__ float2 g_stats[(size_t)NZ*SQ];           // (row max, 1/row sum)
__device__ __half g_c [(size_t)MR*DM];              // ctx [S,B,D]

// ---------------------------------------------------------------------------
// PTX helpers (base-arch: mma.sync / ldmatrix / cp.async)
// ---------------------------------------------------------------------------
__device__ __forceinline__ uint32_t smem_u32(const void* p) {
    uint32_t a;
    asm("{ .reg .u64 t; cvta.to.shared.u64 t, %1; cvt.u32.u64 %0, t; }" : "=r"(a) : "l"(p));
    return a;
}
__device__ __forceinline__ void cp16(uint32_t d, const void* s) {
    asm volatile("cp.async.cg.shared.global [%0], [%1], 16;" :: "r"(d), "l"(s));
}
__device__ __forceinline__ void cp_commit() {
    asm volatile("cp.async.commit_group;" ::: "memory");
}
__device__ __forceinline__ void cp_wait1() {
    asm volatile("cp.async.wait_group 1;" ::: "memory");
}
__device__ __forceinline__ void cp_wait0() {
    asm volatile("cp.async.wait_group 0;" ::: "memory");
}
#define LDMX4(r, a) \
    asm volatile("ldmatrix.sync.aligned.m8n8.x4.shared.b16 {%0,%1,%2,%3}, [%4];" \
        : "=r"((r)[0]), "=r"((r)[1]), "=r"((r)[2]), "=r"((r)[3]) : "r"(a))

__device__ __forceinline__ void mma_f16(float* c, const uint32_t* a, const uint32_t* b) {
    asm volatile(
        "mma.sync.aligned.m16n8k16.row.col.f32.f16.f16.f32 "
        "{%0,%1,%2,%3},{%4,%5,%6,%7},{%8,%9},{%0,%1,%2,%3};"
        : "+f"(c[0]), "+f"(c[1]), "+f"(c[2]), "+f"(c[3])
        : "r"(a[0]), "r"(a[1]), "r"(a[2]), "r"(a[3]), "r"(b[0]), "r"(b[1]));
}

// ---------------------------------------------------------------------------
// Shared GEMM body (2-stage cp.async): C = alpha * A(MxK) * B(NxK)^T
// EPI: 0 fp32 row-major; 2 fp16 scatter to [B,H,S,dk].
// ---------------------------------------------------------------------------
template<int BM, int BN, int EPI>
__device__ __forceinline__ void gemm_body(
    const __half* __restrict__ A, const __half* __restrict__ B,
    float* __restrict__ Cf, __half* __restrict__ Ch,
    int K, int ldc, float alpha, int z, int m0, int n0, char* smem)
{
    const uint32_t sb = smem_u32(smem);
    const int tid  = threadIdx.x;
    const int lane = tid & 31;
    const int wid  = tid >> 5;

    constexpr int WGM = 2;
    constexpr int TM  = BM / WGM;
    constexpr int TN  = BN / (8 / WGM);
    constexpr int MT  = TM / 16;
    constexpr int NT  = TN / 8;
    constexpr int STAGE = (BM + BN) * 144;

    const int wm = wid % WGM, wn = wid / WGM;
    const int mbase = wm * TM, nbase = wn * TN;

    float acc[MT][NT][4];
    #pragma unroll
    for (int i = 0; i < MT; i++)
        #pragma unroll
        for (int j = 0; j < NT; j++)
            #pragma unroll
            for (int r = 0; r < 4; r++) acc[i][j][r] = 0.f;

    const int a_r = lane & 15;
    const int a_c = ((lane >> 4) & 1) << 3;
    const int b_r = (lane & 7) + (((lane >> 4) & 1) << 3);
    const int b_c = ((lane >> 3) & 1) << 3;

    auto load_stage = [&](int kc, int stg) {
        const uint32_t base = sb + (uint32_t)stg * STAGE;
        #pragma unroll
        for (int idx = tid; idx < BM * 8; idx += 256) {
            const int r = idx >> 3, ch = idx & 7;
            cp16(base + (uint32_t)r * 144 + ch * 16, A + (size_t)r * K + kc + ch * 8);
        }
        #pragma unroll
        for (int idx = tid; idx < BN * 8; idx += 256) {
            const int r = idx >> 3, ch = idx & 7;
            cp16(base + BM * 144 + (uint32_t)r * 144 + ch * 16, B + (size_t)r * K + kc + ch * 8);
        }
    };

    auto compute = [&](int stg) {
        const uint32_t sA0 = sb + (uint32_t)stg * STAGE;
        const uint32_t sB0 = sA0 + BM * 144;
        #pragma unroll
        for (int ks = 0; ks < 4; ks++) {
            uint32_t ah[MT][4], bh[NT][2];
            #pragma unroll
            for (int mt = 0; mt < MT; mt++) {
                const uint32_t off = ((uint32_t)(mbase + mt * 16 + a_r) * 72 + ks * 16 + a_c) * 2;
                LDMX4(ah[mt], sA0 + off);
            }
            #pragma unroll
            for (int np = 0; np < NT / 2; np++) {
                const uint32_t off = ((uint32_t)(nbase + np * 16 + b_r) * 72 + ks * 16 + b_c) * 2;
                uint32_t r4[4];
                LDMX4(r4, sB0 + off);
                bh[np*2][0]   = r4[0]; bh[np*2][1]   = r4[1];
                bh[np*2+1][0] = r4[2]; bh[np*2+1][1] = r4[3];
            }
            #pragma unroll
            for (int mt = 0; mt < MT; mt++)
                #pragma unroll
                for (int nt = 0; nt < NT; nt++)
                    mma_f16(acc[mt][nt], ah[mt], bh[nt]);
        }
    };

    const int NC = K >> 6;
    load_stage(0, 0);
    cp_commit();

    for (int c = 0; c < NC; c++) {
        const int buf = c & 1;
        if (c + 1 < NC) {
            load_stage((c + 1) << 6, buf ^ 1);
            cp_commit();
            cp_wait1();
        } else {
            cp_wait0();
        }
        __syncthreads();
        compute(buf);
        __syncthreads();
    }

    // ---- epilogue: frags -> smem -> coalesced gmem ----
    constexpr int CP = BN + 4;
    float* Cs = (float*)smem;
    const int g = lane >> 2, tg = lane & 3;
    #pragma unroll
    for (int mt = 0; mt < MT; mt++)
        #pragma unroll
        for (int nt = 0; nt < NT; nt++) {
            const int row = mbase + mt * 16 + g;
            const int col = nbase + nt * 8 + tg * 2;
            *(float2*)&Cs[(size_t)row * CP + col]       = make_float2(acc[mt][nt][0], acc[mt][nt][1]);
            *(float2*)&Cs[(size_t)(row + 8) * CP + col] = make_float2(acc[mt][nt][2], acc[mt][nt][3]);
        }
    __syncthreads();

    for (int i4 = tid * 4; i4 < BM * BN; i4 += 1024) {
        const int row = i4 / BN, col = i4 % BN;
        float4 v = *(const float4*)&Cs[(size_t)row * CP + col];
        v.x *= alpha; v.y *= alpha; v.z *= alpha; v.w *= alpha;
        const int m = m0 + row, n = n0 + col;
        if (EPI == 0) {
            *(float4*)&Cf[(size_t)m * ldc + n] = v;
        } else {
            __half2 p0 = __halves2half2(__float2half_rn(v.x), __float2half_rn(v.y));
            __half2 p1 = __halves2half2(__float2half_rn(v.z), __float2half_rn(v.w));
            uint2 u = {*(uint32_t*)&p0, *(uint32_t*)&p1};
            const int s2 = m >> 1, b = m & 1, hh = n >> 6, dk = n & 63;
            const size_t addr = ((size_t)(b * NH + hh) * SQ + s2) * DKH + dk;
            *(uint2*)(Ch + addr) = u;
        }
    }
    (void)z;
}

// ---------------------------------------------------------------------------
// Fused Q/K/V projection: grid.z selects (input, weight, output) triple.
// ---------------------------------------------------------------------------
__global__ void __launch_bounds__(256, 2)
hm_proj(const __half* __restrict__ A0, const __half* __restrict__ A1, const __half* __restrict__ A2,
        const __half* __restrict__ B0, const __half* __restrict__ B1, const __half* __restrict__ B2,
        __half* __restrict__ C0, __half* __restrict__ C1, __half* __restrict__ C2)
{
    extern __shared__ __align__(16) char smem[];
    const int zi = blockIdx.z;
    const __half* A = (zi == 0) ? A0 : (zi == 1) ? A1 : A2;
    const __half* B = (zi == 0) ? B0 : (zi == 1) ? B1 : B2;
    __half*       C = (zi == 0) ? C0 : (zi == 1) ? C1 : C2;
    const int m0 = blockIdx.y * 128, n0 = blockIdx.x * 128;
    gemm_body<128, 128, 2>(A + (size_t)m0 * DM, B + (size_t)n0 * DM,
                           nullptr, C, DM, 0, 1.0f, 0, m0, n0, smem);
}

// ---------------------------------------------------------------------------
// Output projection: out = ctx @ Wo^T (fp32 out)
// ---------------------------------------------------------------------------
__global__ void __launch_bounds__(256, 2)
hm_wo(const __half* __restrict__ A, const __half* __restrict__ B, float* __restrict__ Cf)
{
    extern __shared__ __align__(16) char smem[];
    const int m0 = blockIdx.y * 128, n0 = blockIdx.x * 128;
    gemm_body<128, 128, 0>(A + (size_t)m0 * DM, B + (size_t)n0 * DM,
                           Cf, nullptr, DM, DM, 1.0f, 0, m0, n0, smem);
}

// ---------------------------------------------------------------------------
// Phase A: per-row softmax stats (m, 1/s). Block = (z, 128-row q-tile).
// ---------------------------------------------------------------------------
__global__ void __launch_bounds__(256, 2)
qk_stats(const __half* __restrict__ Q, const __half* __restrict__ K,
         float2* __restrict__ stats)
{
    extern __shared__ __align__(16) char smem[];
    const uint32_t sb = smem_u32(smem);
    const int tid = threadIdx.x, lane = tid & 31, wid = tid >> 5;
    const int z = blockIdx.z, q0 = blockIdx.y * 128;
    const int g = lane >> 2, tg = lane & 3;
    const int wbase = wid * 16;

    const __half* Qg = Q + ((size_t)z * SQ + q0) * DKH;
    const __half* Kg = K + (size_t)z * SQ * DKH;

    const uint32_t qs = sb;
    const uint32_t ks = sb + 128 * 144;

    auto loadK = [&](int kt, int stg) {
        const uint32_t base = ks + (uint32_t)stg * (128 * 144);
        #pragma unroll
        for (int idx = tid; idx < 128 * 8; idx += 256) {
            const int r = idx >> 3, ch = idx & 7;
            cp16(base + (uint32_t)r * 144 + ch * 16,
                 Kg + ((size_t)(kt * 128 + r)) * DKH + ch * 8);
        }
    };

    #pragma unroll
    for (int idx = tid; idx < 128 * 8; idx += 256) {
        const int r = idx >> 3, ch = idx & 7;
        cp16(qs + (uint32_t)r * 144 + ch * 16, Qg + (size_t)r * DKH + ch * 8);
    }
    loadK(0, 0);
    cp_commit();

    const int a_r = lane & 15;
    const int a_c = ((lane >> 4) & 1) << 3;
    const int b_r = (lane & 7) + (((lane >> 4) & 1) << 3);
    const int b_c = ((lane >> 3) & 1) << 3;

    float m0 = -3.4e38f, m1 = -3.4e38f, s0 = 0.f, s1 = 0.f;

    for (int kt = 0; kt < SQ / 128; kt++) {
        const int buf = kt & 1;
        if (kt + 1 < SQ / 128) { loadK(kt + 1, buf ^ 1); cp_commit(); cp_wait1(); }
        else cp_wait0();
        __syncthreads();

        float acc[16][4];
        #pragma unroll
        for (int nt = 0; nt < 16; nt++)
            acc[nt][0] = acc[nt][1] = acc[nt][2] = acc[nt][3] = 0.f;

        const uint32_t kb = ks + (uint32_t)buf * (128 * 144);
        #pragma unroll
        for (int ksx = 0; ksx < 4; ksx++) {
            uint32_t ah[4];
            LDMX4(ah, qs + ((uint32_t)(wbase + a_r) * 72 + ksx * 16 + a_c) * 2);
            uint32_t bh[16][2];
            #pragma unroll
            for (int np = 0; np < 8; np++) {
                uint32_t r4[4];
                LDMX4(r4, kb + ((uint32_t)(np * 16 + b_r) * 72 + ksx * 16 + b_c) * 2);
                bh[np*2][0]   = r4[0]; bh[np*2][1]   = r4[1];
                bh[np*2+1][0] = r4[2]; bh[np*2+1][1] = r4[3];
            }
            #pragma unroll
            for (int nt = 0; nt < 16; nt++) mma_f16(acc[nt], ah, bh[nt]);
        }

        float mx0 = -3.4e38f, mx1 = -3.4e38f;
        #pragma unroll
        for (int nt = 0; nt < 16; nt++) {
            mx0 = fmaxf(mx0, fmaxf(acc[nt][0], acc[nt][1]));
            mx1 = fmaxf(mx1, fmaxf(acc[nt][2], acc[nt][3]));
        }
        mx0 = fmaxf(mx0, __shfl_xor_sync(0xFFFFFFFFu, mx0, 1));
        mx0 = fmaxf(mx0, __shfl_xor_sync(0xFFFFFFFFu, mx0, 2));
        mx1 = fmaxf(mx1, __shfl_xor_sync(0xFFFFFFFFu, mx1, 1));
        mx1 = fmaxf(mx1, __shfl_xor_sync(0xFFFFFFFFu, mx1, 2));
        const float nm0 = fmaxf(m0, mx0 * 0.125f);
        const float nm1 = fmaxf(m1, mx1 * 0.125f);
        float t0 = 0.f, t1 = 0.f;
        #pragma unroll
        for (int nt = 0; nt < 16; nt++) {
            t0 += __expf(acc[nt][0] * 0.125f - nm0) + __expf(acc[nt][1] * 0.125f - nm0);
            t1 += __expf(acc[nt][2] * 0.125f - nm1) + __expf(acc[nt][3] * 0.125f - nm1);
        }
        t0 += __shfl_xor_sync(0xFFFFFFFFu, t0, 1);
        t0 += __shfl_xor_sync(0xFFFFFFFFu, t0, 2);
        t1 += __shfl_xor_sync(0xFFFFFFFFu, t1, 1);
        t1 += __shfl_xor_sync(0xFFFFFFFFu, t1, 2);
        s0 = s0 * __expf(m0 - nm0) + t0;
        s1 = s1 * __expf(m1 - nm1) + t1;
        m0 = nm0; m1 = nm1;

        __syncthreads();
    }

    if (tg == 0) {
        stats[(size_t)z * SQ + q0 + wbase + g]     = make_float2(m0, 1.f / s0);
        stats[(size_t)z * SQ + q0 + wbase + g + 8] = make_float2(m1, 1.f / s1);
    }
}

// ---------------------------------------------------------------------------
// flash_pv: fused probs + PV. Block = (z, 128-row q-tile); loops 16 k-tiles.
// Recomputes scores, p = exp(s/8 - m)*is, repacks p accumulators into fp16
// A-fragments (FA2 repack, shuffle-free), accumulates ctx += p @ V via mma
// against Vt B-frags. Writes ctx fp16 [S,B,D]. No Ph tensor.
// ---------------------------------------------------------------------------
__global__ void __launch_bounds__(256, 1)
flash_pv(const __half* __restrict__ Q, const __half* __restrict__ K,
         const __half* __restrict__ Vt, const float2* __restrict__ stats,
         __half* __restrict__ Ch)
{
    extern __shared__ __align__(16) char smem[];
    const uint32_t sb = smem_u32(smem);
    const int tid = threadIdx.x, lane = tid & 31, wid = tid >> 5;
    const int z = blockIdx.z, q0 = blockIdx.y * 128;
    const int g = lane >> 2, tg = lane & 3;
    const int wbase = wid * 16;

    const __half* Qg = Q  + ((size_t)z * SQ + q0) * DKH;
    const __half* Kg = K  + (size_t)z * SQ * DKH;
    const __half* Vg = Vt + (size_t)z * DKH * SQ;

    const uint32_t qs  = sb;                    // Q tile: 128 x 64h, pitch 144
    const uint32_t st0 = sb + 128 * 144;        // stages
    constexpr int VOFF  = 128 * 144;            // K tile bytes within stage
    constexpr int STAGE = 128 * 144 + 64 * 272; // + Vt tile (64 x 128h, pitch 272)

    auto loadKV = [&](int kt, int stg) {
        const uint32_t base = st0 + (uint32_t)stg * STAGE;
        #pragma unroll
        for (int idx = tid; idx < 128 * 8; idx += 256) {
            const int r = idx >> 3, ch = idx & 7;
            cp16(base + (uint32_t)r * 144 + ch * 16,
                 Kg + ((size_t)(kt * 128 + r)) * DKH + ch * 8);
        }
        #pragma unroll
        for (int idx = tid; idx < 64 * 16; idx += 256) {
            const int r = idx >> 4, ch = idx & 15;
            cp16(base + VOFF + (uint32_t)r * 272 + ch * 16,
                 Vg + (size_t)r * SQ + kt * 128 + ch * 8);
        }
    };

    #pragma unroll
    for (int idx = tid; idx < 128 * 8; idx += 256) {
        const int r = idx >> 3, ch = idx & 7;
        cp16(qs + (uint32_t)r * 144 + ch * 16, Qg + (size_t)r * DKH + ch * 8);
    }
    loadKV(0, 0);
    cp_commit();

    const int a_r = lane & 15;
    const int a_c = ((lane >> 4) & 1) << 3;
    const int b_r = (lane & 7) + (((lane >> 4) & 1) << 3);
    const int b_c = ((lane >> 3) & 1) << 3;

    const float2 sst0 = stats[(size_t)z * SQ + q0 + wbase + g];
    const float2 sst1 = stats[(size_t)z * SQ + q0 + wbase + g + 8];

    float ctx[8][4];
    #pragma unroll
    for (int i = 0; i < 8; i++)
        #pragma unroll
        for (int r = 0; r < 4; r++) ctx[i][r] = 0.f;

    for (int kt = 0; kt < SQ / 128; kt++) {
        const int buf = kt & 1;
        if (kt + 1 < SQ / 128) { loadKV(kt + 1, buf ^ 1); cp_commit(); cp_wait1(); }
        else cp_wait0();
        __syncthreads();

        const uint32_t kb = st0 + (uint32_t)buf * STAGE;
        const uint32_t vb = kb + VOFF;

        // ---- scores tile: 16 rows x 128 cols per warp ----
        float acc[16][4];
        #pragma unroll
        for (int nt = 0; nt < 16; nt++)
            acc[nt][0] = acc[nt][1] = acc[nt][2] = acc[nt][3] = 0.f;

        #pragma unroll
        for (int ksx = 0; ksx < 4; ksx++) {
            uint32_t ah[4];
            LDMX4(ah, qs + ((uint32_t)(wbase + a_r) * 72 + ksx * 16 + a_c) * 2);
            uint32_t bh[16][2];
            #pragma unroll
            for (int np = 0; np < 8; np++) {
                uint32_t r4[4];
                LDMX4(r4, kb + ((uint32_t)(np * 16 + b_r) * 72 + ksx * 16 + b_c) * 2);
                bh[np*2][0]   = r4[0]; bh[np*2][1]   = r4[1];
                bh[np*2+1][0] = r4[2]; bh[np*2+1][1] = r4[3];
            }
            #pragma unroll
            for (int nt = 0; nt < 16; nt++) mma_f16(acc[nt], ah, bh[nt]);
        }

        // ---- p = exp(s/8 - m) * is, packed as fp16 A-fragments ----
        uint32_t pf[16][2];
        #pragma unroll
        for (int nt = 0; nt < 16; nt++) {
            const float p0 = __expf(acc[nt][0] * 0.125f - sst0.x) * sst0.y;
            const float p1 = __expf(acc[nt][1] * 0.125f - sst0.x) * sst0.y;
            const float p2 = __expf(acc[nt][2] * 0.125f - sst1.x) * sst1.y;
            const float p3 = __expf(acc[nt][3] * 0.125f - sst1.x) * sst1.y;
            __half2 u0 = __floats2half2_rn(p0, p1);
            __half2 u1 = __floats2half2_rn(p2, p3);
            pf[nt][0] = *(uint32_t*)&u0;
            pf[nt][1] = *(uint32_t*)&u1;
        }

        // ---- ctx += p @ V  (A = p frags, B = Vt frags from smem) ----
        #pragma unroll
        for (int kc = 0; kc < 8; kc++) {
            uint32_t af[4] = {pf[2*kc][0], pf[2*kc][1], pf[2*kc+1][0], pf[2*kc+1][1]};
            #pragma unroll
            for (int np = 0; np < 4; np++) {
                uint32_t r4[4];
                LDMX4(r4, vb + ((uint32_t)(np * 16 + b_r) * 272 + (kc * 16 + b_c) * 2));
                uint32_t b0[2] = {r4[0], r4[1]};
                uint32_t b1[2] = {r4[2], r4[3]};
                mma_f16(ctx[2*np],     af, b0);
                mma_f16(ctx[2*np + 1], af, b1);
            }
        }
        __syncthreads();
    }

    // ---- epilogue: ctx fp16 -> [S,B,D] ----
    const int b = z >> 4, hh = z & 15;
    const int row0 = q0 + wbase + g;
    #pragma unroll
    for (int nt = 0; nt < 8; nt++) {
        const int col = hh * DKH + nt * 8 + tg * 2;
        __half2 u0 = __floats2half2_rn(ctx[nt][0], ctx[nt][1]);
        __half2 u1 = __floats2half2_rn(ctx[nt][2], ctx[nt][3]);
        *(__half2*)(Ch + ((size_t)row0 * NB + b) * DM + col)       = u0;
        *(__half2*)(Ch + ((size_t)(row0 + 8) * NB + b) * DM + col) = u1;
    }
}

// ---------------------------------------------------------------------------
// mean_only: head-mean of probs (fp32, written once per tile; no Ph store).
// Block = (b, q-tile, k-tile); loops 16 heads with cp.async pipelining.
// ---------------------------------------------------------------------------
__global__ void __launch_bounds__(256, 1)
mean_only(const __half* __restrict__ Q, const __half* __restrict__ K,
          const float2* __restrict__ stats, float* __restrict__ outMean)
{
    extern __shared__ __align__(16) char smem[];
    const uint32_t sb = smem_u32(smem);
    const int tid = threadIdx.x, lane = tid & 31, wid = tid >> 5;
    const int b  = blockIdx.z;
    const int q0 = blockIdx.y * 128, k0 = blockIdx.x * 128;
    const int g = lane >> 2, tg = lane & 3;
    const int wm = wid & 1, wn = wid >> 1;
    const int mbase = wm * 64, nbase = wn * 32;
    constexpr int STG = 2 * 128 * 144;

    const int a_r = lane & 15;
    const int a_c = ((lane >> 4) & 1) << 3;
    const int b_r = (lane & 7) + (((lane >> 4) & 1) << 3);
    const int b_c = ((lane >> 3) & 1) << 3;

    auto load_tiles = [&](int h, int stg) {
        const int z = (b << 4) + h;
        const __half* Qg = Q + ((size_t)z * SQ + q0) * DKH;
        const __half* Kg = K + ((size_t)z * SQ + k0) * DKH;
        const uint32_t base = sb + (uint32_t)stg * STG;
        #pragma unroll
        for (int idx = tid; idx < 128 * 8; idx += 256) {
            const int r = idx >> 3, ch = idx & 7;
            cp16(base + (uint32_t)r * 144 + ch * 16, Qg + (size_t)r * DKH + ch * 8);
            cp16(base + 128 * 144 + (uint32_t)r * 144 + ch * 16, Kg + (size_t)r * DKH + ch * 8);
        }
    };

    float macc[4][4][4];
    #pragma unroll
    for (int i = 0; i < 4; i++)
        #pragma unroll
        for (int j = 0; j < 4; j++)
            #pragma unroll
            for (int r = 0; r < 4; r++) macc[i][j][r] = 0.f;

    load_tiles(0, 0);
    cp_commit();

    for (int h = 0; h < 16; h++) {
        const int st = h & 1;
        if (h + 1 < 16) { load_tiles(h + 1, st ^ 1); cp_commit(); cp_wait1(); }
        else cp_wait0();
        __syncthreads();

        const uint32_t sQ = sb + (uint32_t)st * STG;
        const uint32_t sK = sQ + 128 * 144;

        float acc[4][4][4];
        #pragma unroll
        for (int i = 0; i < 4; i++)
            #pragma unroll
            for (int j = 0; j < 4; j++)
                #pragma unroll
                for (int r = 0; r < 4; r++) acc[i][j][r] = 0.f;

        #pragma unroll
        for (int ksx = 0; ksx < 4; ksx++) {
            uint32_t ah[4][4], bh[4][2];
            #pragma unroll
            for (int mt = 0; mt < 4; mt++) {
                const uint32_t off = ((uint32_t)(mbase + mt * 16 + a_r) * 72 + ksx * 16 + a_c) * 2;
                LDMX4(ah[mt], sQ + off);
            }
            #pragma unroll
            for (int np = 0; np < 2; np++) {
                const uint32_t off = ((uint32_t)(nbase + np * 16 + b_r) * 72 + ksx * 16 + b_c) * 2;
                uint32_t r4[4];
                LDMX4(r4, sK + off);
                bh[np*2][0]   = r4[0]; bh[np*2][1]   = r4[1];
                bh[np*2+1][0] = r4[2]; bh[np*2+1][1] = r4[3];
            }
            #pragma unroll
            for (int mt = 0; mt < 4; mt++)
                #pragma unroll
                for (int nt = 0; nt < 4; nt++)
                    mma_f16(acc[mt][nt], ah[mt], bh[nt]);
        }

        const int z = (b << 4) + h;
        const float2* strow = stats + (size_t)z * SQ + q0;
        #pragma unroll
        for (int mt = 0; mt < 4; mt++) {
            const int r0 = mbase + mt * 16 + g;
            const float2 st0 = strow[r0];
            const float2 st1 = strow[r0 + 8];
            #pragma unroll
            for (int nt = 0; nt < 4; nt++) {
                macc[mt][nt][0] += __expf(acc[mt][nt][0] * 0.125f - st0.x) * st0.y;
                macc[mt][nt][1] += __expf(acc[mt][nt][1] * 0.125f - st0.x) * st0.y;
                macc[mt][nt][2] += __expf(acc[mt][nt][2] * 0.125f - st1.x) * st1.y;
                macc[mt][nt][3] += __expf(acc[mt][nt][3] * 0.125f - st1.x) * st1.y;
            }
        }
        __syncthreads();
    }

    float* om = outMean + (size_t)b * SQ * SQ;
    #pragma unroll
    for (int mt = 0; mt < 4; mt++) {
        const int r0 = mbase + mt * 16 + g;
        #pragma unroll
        for (int nt = 0; nt < 4; nt++) {
            const int col = nbase + nt * 8 + tg * 2;
            *(float2*)&om[(size_t)(q0 + r0) * SQ + k0 + col] =
                make_float2(macc[mt][nt][0] * (1.0f / NH), macc[mt][nt][1] * (1.0f / NH));
            *(float2*)&om[(size_t)(q0 + r0 + 8) * SQ + k0 + col] =
                make_float2(macc[mt][nt][2] * (1.0f / NH), macc[mt][nt][3] * (1.0f / NH));
        }
    }
}

// ---------------------------------------------------------------------------
// fused fp32 -> fp16 conversions
// ---------------------------------------------------------------------------
__global__ void __launch_bounds__(256)
cvt_qkv(const float* __restrict__ a, const float* __restrict__ b2, const float* __restrict__ c,
        __half* __restrict__ oa, __half* __restrict__ ob, __half* __restrict__ oc)
{
    const int zi = blockIdx.z;
    const float* s = zi == 0 ? a : (zi == 1 ? b2 : c);
    __half* d = zi == 0 ? oa : (zi == 1 ? ob : oc);
    const int i = (blockIdx.x * 256 + threadIdx.x) * 4;
    float4 v = *(const float4*)(s + i);
    __half2 p0 = __halves2half2(__float2half_rn(v.x), __float2half_rn(v.y));
    __half2 p1 = __halves2half2(__float2half_rn(v.z), __float2half_rn(v.w));
    uint2 u = {*(uint32_t*)&p0, *(uint32_t*)&p1};
    *(uint2*)(d + i) = u;
}
__global__ void __launch_bounds__(256)
cvt_w(const float* __restrict__ a, const float* __restrict__ b2,
      const float* __restrict__ c, const float* __restrict__ e,
      __half* __restrict__ oa, __half* __restrict__ ob,
      __half* __restrict__ oc, __half* __restrict__ oe)
{
    const int zi = blockIdx.z;
    const float* s = zi == 0 ? a : (zi == 1 ? b2 : (zi == 2 ? c : e));
    __half* d = zi == 0 ? oa : (zi == 1 ? ob : (zi == 2 ? oc : oe));
    const int i = (blockIdx.x * 256 + threadIdx.x) * 4;
    float4 v = *(const float4*)(s + i);
    __half2 p0 = __halves2half2(__float2half_rn(v.x), __float2half_rn(v.y));
    __half2 p1 = __halves2half2(__float2half_rn(v.z), __float2half_rn(v.w));
    uint2 u = {*(uint32_t*)&p0, *(uint32_t*)&p1};
    *(uint2*)(d + i) = u;
}

// ---------------------------------------------------------------------------
// V transpose: [Z, S, 64] -> [Z, 64, S]
// ---------------------------------------------------------------------------
__global__ void __launch_bounds__(256)
v_transpose(const __half* __restrict__ s, __half* __restrict__ d)
{
    __shared__ __half t0[32][33];
    const int z  = blockIdx.z;
    const int s0 = blockIdx.y * 32;
    const int d0 = blockIdx.x * 32;
    const int tx = threadIdx.x, ty = threadIdx.y;
    const size_t zin = (size_t)z * SQ * DKH;
    #pragma unroll
    for (int j = 0; j < 4; j++) {
        const int rs = ty + j * 8;
        t0[rs][tx] = s[zin + (size_t)(s0 + rs) * DKH + d0 + tx];
    }
    __syncthreads();
    const size_t zo = (size_t)z * DKH * SQ;
    #pragma unroll
    for (int j = 0; j < 4; j++) {
        const int rd = ty + j * 8;
        d[zo + (size_t)(d0 + rd) * SQ + s0 + tx] = t0[tx][rd];
    }
}

// ---------------------------------------------------------------------------
extern "C" void kernel_launch(void* const* d_in, const int* in_sizes, int n_in,
                              void* d_out, int out_size)
{
    (void)in_sizes; (void)n_in; (void)out_size;
    const float* q  = (const float*)d_in[0];
    const float* k  = (const float*)d_in[1];
    const float* v  = (const float*)d_in[2];
    const float* Wq = (const float*)d_in[3];
    const float* Wk = (const float*)d_in[4];
    const float* Wv = (const float*)d_in[5];
    const float* Wo = (const float*)d_in[6];
    float* out     = (float*)d_out;
    float* outMean = out + (size_t)MR * DM;

    #define SYM(p, s) void* p; cudaGetSymbolAddress(&p, s)
    SYM(pqx, g_qx); SYM(pkx, g_kx); SYM(pvx, g_vx);
    SYM(pwq, g_wq); SYM(pwk, g_wk); SYM(pwv, g_wv); SYM(pwo, g_wo);
    SYM(pQ, g_Q); SYM(pK, g_K); SYM(pVs, g_Vs); SYM(pVt, g_Vt);
    SYM(pstats, g_stats); SYM(pc, g_c);
    #undef SYM

    const int SMEM_GEMM  = 2 * (128 + 128) * 144;            // 73728
    const int SMEM_STAT  = 3 * 128 * 144;                    // 55296
    const int SMEM_FLASH = 128 * 144 + 2 * (128 * 144 + 64 * 272); // 90112
    const int SMEM_MEAN  = 2 * 2 * 128 * 144;                // 73728
    cudaFuncSetAttribute(hm_proj,   cudaFuncAttributeMaxDynamicSharedMemorySize, SMEM_GEMM);
    cudaFuncSetAttribute(hm_wo,     cudaFuncAttributeMaxDynamicSharedMemorySize, SMEM_GEMM);
    cudaFuncSetAttribute(qk_stats,  cudaFuncAttributeMaxDynamicSharedMemorySize, SMEM_STAT);
    cudaFuncSetAttribute(flash_pv,  cudaFuncAttributeMaxDynamicSharedMemorySize, SMEM_FLASH);
    cudaFuncSetAttribute(mean_only, cudaFuncAttributeMaxDynamicSharedMemorySize, SMEM_MEAN);

    // 1) fp32 -> fp16 conversions
    cvt_qkv<<<dim3(MR * DM / 1024, 1, 3), 256>>>(q, k, v,
        (__half*)pqx, (__half*)pkx, (__half*)pvx);
    cvt_w<<<dim3(DM * DM / 1024, 1, 4), 256>>>(Wq, Wk, Wv, Wo,
        (__half*)pwq, (__half*)pwk, (__half*)pwv, (__half*)pwo);

    // 2) fused Q/K/V projections
    hm_proj<<<dim3(DM / 128, MR / 128, 3), 256, SMEM_GEMM>>>(
        (const __half*)pqx, (const __half*)pkx, (const __half*)pvx,
        (const __half*)pwq, (const __half*)pwk, (const __half*)pwv,
        (__half*)pQ, (__half*)pK, (__half*)pVs);

    // 3) V transpose [Z,S,64] -> [Z,64,S]
    v_transpose<<<dim3(DKH / 32, SQ / 32, NZ), dim3(32, 8)>>>(
        (const __half*)pVs, (__half*)pVt);

    // 4) phase A: softmax row stats (m, 1/s)
    qk_stats<<<dim3(1, SQ / 128, NZ), 256, SMEM_STAT>>>(
        (const __half*)pQ, (const __half*)pK, (float2*)pstats);

    // 5) fused probs + PV -> ctx fp16 (no Ph tensor)
    flash_pv<<<dim3(1, SQ / 128, NZ), 256, SMEM_FLASH>>>(
        (const __half*)pQ, (const __half*)pK, (const __half*)pVt,
        (const float2*)pstats, (__half*)pc);

    // 6) out = ctx @ Wo^T
    hm_wo<<<dim3(DM / 128, MR / 128, 1), 256, SMEM_GEMM>>>(
        (const __half*)pc, (const __half*)pwo, out);

    // 7) head mean (fp32, written once; independent of 5/6)
    mean_only<<<dim3(SQ / 128, SQ / 128, NB), 256, SMEM_MEAN>>>(
        (const __half*)pQ, (const __half*)pK, (const float2*)pstats, outMean);
}

// round 10
// speedup vs baseline: 5.1314x; 1.1650x over previous
#include <cuda_runtime.h>
#include <cuda_fp16.h>
#include <cstdint>

#define SQ  2048
#define NB  2
#define DM  1024
#define NH  16
#define DKH 64
#define MR  4096              // S*B rows
#define NZ  (NB*NH)           // 32 batch*head slices

// ---------------------------------------------------------------------------
// Scratch (__device__ globals: allocation-free)
// ---------------------------------------------------------------------------
__device__ __half g_qx[(size_t)MR*DM], g_kx[(size_t)MR*DM], g_vx[(size_t)MR*DM];
__device__ __half g_wq[(size_t)DM*DM], g_wk[(size_t)DM*DM];
__device__ __half g_wv[(size_t)DM*DM], g_wo[(size_t)DM*DM];
__device__ __half g_Q[(size_t)NZ*SQ*DKH], g_K[(size_t)NZ*SQ*DKH];
__device__ __half g_Vs[(size_t)NZ*SQ*DKH];          // [Z,S,dk]
__device__ __half g_Vt[(size_t)NZ*DKH*SQ];          // [Z,dk,S]
__device__ float2 g_stats[(size_t)NZ*SQ];           // (row max, 1/row sum) — written by flash_pv
__device__ __half g_c [(size_t)MR*DM];              // ctx [S,B,D]

// ---------------------------------------------------------------------------
// PTX helpers (base-arch: mma.sync / ldmatrix / cp.async)
// ---------------------------------------------------------------------------
__device__ __forceinline__ uint32_t smem_u32(const void* p) {
    uint32_t a;
    asm("{ .reg .u64 t; cvta.to.shared.u64 t, %1; cvt.u32.u64 %0, t; }" : "=r"(a) : "l"(p));
    return a;
}
__device__ __forceinline__ void cp16(uint32_t d, const void* s) {
    asm volatile("cp.async.cg.shared.global [%0], [%1], 16;" :: "r"(d), "l"(s));
}
__device__ __forceinline__ void cp_commit() {
    asm volatile("cp.async.commit_group;" ::: "memory");
}
__device__ __forceinline__ void cp_wait1() {
    asm volatile("cp.async.wait_group 1;" ::: "memory");
}
__device__ __forceinline__ void cp_wait0() {
    asm volatile("cp.async.wait_group 0;" ::: "memory");
}
#define LDMX4(r, a) \
    asm volatile("ldmatrix.sync.aligned.m8n8.x4.shared.b16 {%0,%1,%2,%3}, [%4];" \
        : "=r"((r)[0]), "=r"((r)[1]), "=r"((r)[2]), "=r"((r)[3]) : "r"(a))

__device__ __forceinline__ void mma_f16(float* c, const uint32_t* a, const uint32_t* b) {
    asm volatile(
        "mma.sync.aligned.m16n8k16.row.col.f32.f16.f16.f32 "
        "{%0,%1,%2,%3},{%4,%5,%6,%7},{%8,%9},{%0,%1,%2,%3};"
        : "+f"(c[0]), "+f"(c[1]), "+f"(c[2]), "+f"(c[3])
        : "r"(a[0]), "r"(a[1]), "r"(a[2]), "r"(a[3]), "r"(b[0]), "r"(b[1]));
}

// ---------------------------------------------------------------------------
// Shared GEMM body (2-stage cp.async): C = alpha * A(MxK) * B(NxK)^T
// EPI: 0 fp32 row-major; 2 fp16 scatter to [B,H,S,dk].
// ---------------------------------------------------------------------------
template<int BM, int BN, int EPI>
__device__ __forceinline__ void gemm_body(
    const __half* __restrict__ A, const __half* __restrict__ B,
    float* __restrict__ Cf, __half* __restrict__ Ch,
    int K, int ldc, float alpha, int m0, int n0, char* smem)
{
    const uint32_t sb = smem_u32(smem);
    const int tid  = threadIdx.x;
    const int lane = tid & 31;
    const int wid  = tid >> 5;

    constexpr int WGM = 2;
    constexpr int TM  = BM / WGM;
    constexpr int TN  = BN / (8 / WGM);
    constexpr int MT  = TM / 16;
    constexpr int NT  = TN / 8;
    constexpr int STAGE = (BM + BN) * 144;

    const int wm = wid % WGM, wn = wid / WGM;
    const int mbase = wm * TM, nbase = wn * TN;

    float acc[MT][NT][4];
    #pragma unroll
    for (int i = 0; i < MT; i++)
        #pragma unroll
        for (int j = 0; j < NT; j++)
            #pragma unroll
            for (int r = 0; r < 4; r++) acc[i][j][r] = 0.f;

    const int a_r = lane & 15;
    const int a_c = ((lane >> 4) & 1) << 3;
    const int b_r = (lane & 7) + (((lane >> 4) & 1) << 3);
    const int b_c = ((lane >> 3) & 1) << 3;

    auto load_stage = [&](int kc, int stg) {
        const uint32_t base = sb + (uint32_t)stg * STAGE;
        #pragma unroll
        for (int idx = tid; idx < BM * 8; idx += 256) {
            const int r = idx >> 3, ch = idx & 7;
            cp16(base + (uint32_t)r * 144 + ch * 16, A + (size_t)r * K + kc + ch * 8);
        }
        #pragma unroll
        for (int idx = tid; idx < BN * 8; idx += 256) {
            const int r = idx >> 3, ch = idx & 7;
            cp16(base + BM * 144 + (uint32_t)r * 144 + ch * 16, B + (size_t)r * K + kc + ch * 8);
        }
    };

    auto compute = [&](int stg) {
        const uint32_t sA0 = sb + (uint32_t)stg * STAGE;
        const uint32_t sB0 = sA0 + BM * 144;
        #pragma unroll
        for (int ks = 0; ks < 4; ks++) {
            uint32_t ah[MT][4], bh[NT][2];
            #pragma unroll
            for (int mt = 0; mt < MT; mt++) {
                const uint32_t off = ((uint32_t)(mbase + mt * 16 + a_r) * 72 + ks * 16 + a_c) * 2;
                LDMX4(ah[mt], sA0 + off);
            }
            #pragma unroll
            for (int np = 0; np < NT / 2; np++) {
                const uint32_t off = ((uint32_t)(nbase + np * 16 + b_r) * 72 + ks * 16 + b_c) * 2;
                uint32_t r4[4];
                LDMX4(r4, sB0 + off);
                bh[np*2][0]   = r4[0]; bh[np*2][1]   = r4[1];
                bh[np*2+1][0] = r4[2]; bh[np*2+1][1] = r4[3];
            }
            #pragma unroll
            for (int mt = 0; mt < MT; mt++)
                #pragma unroll
                for (int nt = 0; nt < NT; nt++)
                    mma_f16(acc[mt][nt], ah[mt], bh[nt]);
        }
    };

    const int NC = K >> 6;
    load_stage(0, 0);
    cp_commit();

    for (int c = 0; c < NC; c++) {
        const int buf = c & 1;
        if (c + 1 < NC) {
            load_stage((c + 1) << 6, buf ^ 1);
            cp_commit();
            cp_wait1();
        } else {
            cp_wait0();
        }
        __syncthreads();
        compute(buf);
        __syncthreads();
    }

    // ---- epilogue: frags -> smem -> coalesced gmem ----
    constexpr int CP = BN + 4;
    float* Cs = (float*)smem;
    const int g = lane >> 2, tg = lane & 3;
    #pragma unroll
    for (int mt = 0; mt < MT; mt++)
        #pragma unroll
        for (int nt = 0; nt < NT; nt++) {
            const int row = mbase + mt * 16 + g;
            const int col = nbase + nt * 8 + tg * 2;
            *(float2*)&Cs[(size_t)row * CP + col]       = make_float2(acc[mt][nt][0], acc[mt][nt][1]);
            *(float2*)&Cs[(size_t)(row + 8) * CP + col] = make_float2(acc[mt][nt][2], acc[mt][nt][3]);
        }
    __syncthreads();

    for (int i4 = tid * 4; i4 < BM * BN; i4 += 1024) {
        const int row = i4 / BN, col = i4 % BN;
        float4 v = *(const float4*)&Cs[(size_t)row * CP + col];
        v.x *= alpha; v.y *= alpha; v.z *= alpha; v.w *= alpha;
        const int m = m0 + row, n = n0 + col;
        if (EPI == 0) {
            *(float4*)&Cf[(size_t)m * ldc + n] = v;
        } else {
            __half2 p0 = __halves2half2(__float2half_rn(v.x), __float2half_rn(v.y));
            __half2 p1 = __halves2half2(__float2half_rn(v.z), __float2half_rn(v.w));
            uint2 u = {*(uint32_t*)&p0, *(uint32_t*)&p1};
            const int s2 = m >> 1, b = m & 1, hh = n >> 6, dk = n & 63;
            const size_t addr = ((size_t)(b * NH + hh) * SQ + s2) * DKH + dk;
            *(uint2*)(Ch + addr) = u;
        }
    }
}

// ---------------------------------------------------------------------------
// Fused Q/K/V projection: grid.z selects (input, weight, output) triple.
// ---------------------------------------------------------------------------
__global__ void __launch_bounds__(256, 2)
hm_proj(const __half* __restrict__ A0, const __half* __restrict__ A1, const __half* __restrict__ A2,
        const __half* __restrict__ B0, const __half* __restrict__ B1, const __half* __restrict__ B2,
        __half* __restrict__ C0, __half* __restrict__ C1, __half* __restrict__ C2)
{
    extern __shared__ __align__(16) char smem[];
    const int zi = blockIdx.z;
    const __half* A = (zi == 0) ? A0 : (zi == 1) ? A1 : A2;
    const __half* B = (zi == 0) ? B0 : (zi == 1) ? B1 : B2;
    __half*       C = (zi == 0) ? C0 : (zi == 1) ? C1 : C2;
    const int m0 = blockIdx.y * 128, n0 = blockIdx.x * 128;
    gemm_body<128, 128, 2>(A + (size_t)m0 * DM, B + (size_t)n0 * DM,
                           nullptr, C, DM, 0, 1.0f, m0, n0, smem);
}

// ---------------------------------------------------------------------------
// Output projection: out = ctx @ Wo^T (fp32 out)
// ---------------------------------------------------------------------------
__global__ void __launch_bounds__(256, 2)
hm_wo(const __half* __restrict__ A, const __half* __restrict__ B, float* __restrict__ Cf)
{
    extern __shared__ __align__(16) char smem[];
    const int m0 = blockIdx.y * 128, n0 = blockIdx.x * 128;
    gemm_body<128, 128, 0>(A + (size_t)m0 * DM, B + (size_t)n0 * DM,
                           Cf, nullptr, DM, DM, 1.0f, m0, n0, smem);
}

// ---------------------------------------------------------------------------
// flash_pv (ONLINE): fused softmax-stats + probs + PV in one pass.
// Block = (z, 128-row q-tile); loops 16 k-tiles. Per k-tile: scores via mma,
// online (m,s) update with ctx rescale, unnormalized p' -> fp16 A-frags,
// ctx += p' @ V. Final: ctx *= 1/s, write [S,B,D]; write stats for mean_only.
// ---------------------------------------------------------------------------
__global__ void __launch_bounds__(256, 1)
flash_pv(const __half* __restrict__ Q, const __half* __restrict__ K,
         const __half* __restrict__ Vt, float2* __restrict__ stats,
         __half* __restrict__ Ch)
{
    extern __shared__ __align__(16) char smem[];
    const uint32_t sb = smem_u32(smem);
    const int tid = threadIdx.x, lane = tid & 31, wid = tid >> 5;
    const int z = blockIdx.z, q0 = blockIdx.y * 128;
    const int g = lane >> 2, tg = lane & 3;
    const int wbase = wid * 16;

    const __half* Qg = Q  + ((size_t)z * SQ + q0) * DKH;
    const __half* Kg = K  + (size_t)z * SQ * DKH;
    const __half* Vg = Vt + (size_t)z * DKH * SQ;

    const uint32_t qs  = sb;                    // Q tile: 128 x 64h, pitch 144
    const uint32_t st0 = sb + 128 * 144;        // stages
    constexpr int VOFF  = 128 * 144;            // K tile bytes within stage
    constexpr int STAGE = 128 * 144 + 64 * 272; // + Vt tile (64 x 128h, pitch 272)

    auto loadKV = [&](int kt, int stg) {
        const uint32_t base = st0 + (uint32_t)stg * STAGE;
        #pragma unroll
        for (int idx = tid; idx < 128 * 8; idx += 256) {
            const int r = idx >> 3, ch = idx & 7;
            cp16(base + (uint32_t)r * 144 + ch * 16,
                 Kg + ((size_t)(kt * 128 + r)) * DKH + ch * 8);
        }
        #pragma unroll
        for (int idx = tid; idx < 64 * 16; idx += 256) {
            const int r = idx >> 4, ch = idx & 15;
            cp16(base + VOFF + (uint32_t)r * 272 + ch * 16,
                 Vg + (size_t)r * SQ + kt * 128 + ch * 8);
        }
    };

    #pragma unroll
    for (int idx = tid; idx < 128 * 8; idx += 256) {
        const int r = idx >> 3, ch = idx & 7;
        cp16(qs + (uint32_t)r * 144 + ch * 16, Qg + (size_t)r * DKH + ch * 8);
    }
    loadKV(0, 0);
    cp_commit();

    const int a_r = lane & 15;
    const int a_c = ((lane >> 4) & 1) << 3;
    const int b_r = (lane & 7) + (((lane >> 4) & 1) << 3);
    const int b_c = ((lane >> 3) & 1) << 3;

    float m0 = -3.4e38f, m1 = -3.4e38f, s0 = 0.f, s1 = 0.f;

    float ctx[8][4];
    #pragma unroll
    for (int i = 0; i < 8; i++)
        #pragma unroll
        for (int r = 0; r < 4; r++) ctx[i][r] = 0.f;

    for (int kt = 0; kt < SQ / 128; kt++) {
        const int buf = kt & 1;
        if (kt + 1 < SQ / 128) { loadKV(kt + 1, buf ^ 1); cp_commit(); cp_wait1(); }
        else cp_wait0();
        __syncthreads();

        const uint32_t kb = st0 + (uint32_t)buf * STAGE;
        const uint32_t vb = kb + VOFF;

        // ---- scores tile: 16 rows x 128 cols per warp ----
        float acc[16][4];
        #pragma unroll
        for (int nt = 0; nt < 16; nt++)
            acc[nt][0] = acc[nt][1] = acc[nt][2] = acc[nt][3] = 0.f;

        #pragma unroll
        for (int ksx = 0; ksx < 4; ksx++) {
            uint32_t ah[4];
            LDMX4(ah, qs + ((uint32_t)(wbase + a_r) * 72 + ksx * 16 + a_c) * 2);
            uint32_t bh[16][2];
            #pragma unroll
            for (int np = 0; np < 8; np++) {
                uint32_t r4[4];
                LDMX4(r4, kb + ((uint32_t)(np * 16 + b_r) * 72 + ksx * 16 + b_c) * 2);
                bh[np*2][0]   = r4[0]; bh[np*2][1]   = r4[1];
                bh[np*2+1][0] = r4[2]; bh[np*2+1][1] = r4[3];
            }
            #pragma unroll
            for (int nt = 0; nt < 16; nt++) mma_f16(acc[nt], ah, bh[nt]);
        }

        // ---- online (m, s) update ----
        float mx0 = -3.4e38f, mx1 = -3.4e38f;
        #pragma unroll
        for (int nt = 0; nt < 16; nt++) {
            mx0 = fmaxf(mx0, fmaxf(acc[nt][0], acc[nt][1]));
            mx1 = fmaxf(mx1, fmaxf(acc[nt][2], acc[nt][3]));
        }
        mx0 = fmaxf(mx0, __shfl_xor_sync(0xFFFFFFFFu, mx0, 1));
        mx0 = fmaxf(mx0, __shfl_xor_sync(0xFFFFFFFFu, mx0, 2));
        mx1 = fmaxf(mx1, __shfl_xor_sync(0xFFFFFFFFu, mx1, 1));
        mx1 = fmaxf(mx1, __shfl_xor_sync(0xFFFFFFFFu, mx1, 2));
        const float nm0 = fmaxf(m0, mx0 * 0.125f);
        const float nm1 = fmaxf(m1, mx1 * 0.125f);
        const float f0 = __expf(m0 - nm0);
        const float f1 = __expf(m1 - nm1);
        m0 = nm0; m1 = nm1;

        // rescale ctx accumulator
        #pragma unroll
        for (int i = 0; i < 8; i++) {
            ctx[i][0] *= f0; ctx[i][1] *= f0;
            ctx[i][2] *= f1; ctx[i][3] *= f1;
        }

        // ---- p' = exp(s/8 - m), packed as fp16 A-fragments; accumulate sum ----
        uint32_t pf[16][2];
        float t0 = 0.f, t1 = 0.f;
        #pragma unroll
        for (int nt = 0; nt < 16; nt++) {
            const float p0 = __expf(acc[nt][0] * 0.125f - nm0);
            const float p1 = __expf(acc[nt][1] * 0.125f - nm0);
            const float p2 = __expf(acc[nt][2] * 0.125f - nm1);
            const float p3 = __expf(acc[nt][3] * 0.125f - nm1);
            t0 += p0 + p1;
            t1 += p2 + p3;
            __half2 u0 = __floats2half2_rn(p0, p1);
            __half2 u1 = __floats2half2_rn(p2, p3);
            pf[nt][0] = *(uint32_t*)&u0;
            pf[nt][1] = *(uint32_t*)&u1;
        }
        t0 += __shfl_xor_sync(0xFFFFFFFFu, t0, 1);
        t0 += __shfl_xor_sync(0xFFFFFFFFu, t0, 2);
        t1 += __shfl_xor_sync(0xFFFFFFFFu, t1, 1);
        t1 += __shfl_xor_sync(0xFFFFFFFFu, t1, 2);
        s0 = s0 * f0 + t0;
        s1 = s1 * f1 + t1;

        // ---- ctx += p' @ V  (A = p frags, B = Vt frags from smem) ----
        #pragma unroll
        for (int kc = 0; kc < 8; kc++) {
            uint32_t af[4] = {pf[2*kc][0], pf[2*kc][1], pf[2*kc+1][0], pf[2*kc+1][1]};
            #pragma unroll
            for (int np = 0; np < 4; np++) {
                uint32_t r4[4];
                LDMX4(r4, vb + ((uint32_t)(np * 16 + b_r) * 272 + (kc * 16 + b_c) * 2));
                uint32_t b0[2] = {r4[0], r4[1]};
                uint32_t b1[2] = {r4[2], r4[3]};
                mma_f16(ctx[2*np],     af, b0);
                mma_f16(ctx[2*np + 1], af, b1);
            }
        }
        __syncthreads();
    }

    // ---- finalize: normalize by 1/s, write ctx + stats ----
    const float is0 = 1.f / s0;
    const float is1 = 1.f / s1;
    const int b = z >> 4, hh = z & 15;
    const int row0 = q0 + wbase + g;
    #pragma unroll
    for (int nt = 0; nt < 8; nt++) {
        const int col = hh * DKH + nt * 8 + tg * 2;
        __half2 u0 = __floats2half2_rn(ctx[nt][0] * is0, ctx[nt][1] * is0);
        __half2 u1 = __floats2half2_rn(ctx[nt][2] * is1, ctx[nt][3] * is1);
        *(__half2*)(Ch + ((size_t)row0 * NB + b) * DM + col)       = u0;
        *(__half2*)(Ch + ((size_t)(row0 + 8) * NB + b) * DM + col) = u1;
    }
    if (tg == 0) {
        stats[(size_t)z * SQ + row0]     = make_float2(m0, is0);
        stats[(size_t)z * SQ + row0 + 8] = make_float2(m1, is1);
    }
}

// ---------------------------------------------------------------------------
// mean_only: head-mean of probs (fp32, written once per tile).
// Block = (b, q-tile, k-tile); loops 16 heads with cp.async pipelining.
// Uses stats written by flash_pv.
// ---------------------------------------------------------------------------
__global__ void __launch_bounds__(256, 1)
mean_only(const __half* __restrict__ Q, const __half* __restrict__ K,
          const float2* __restrict__ stats, float* __restrict__ outMean)
{
    extern __shared__ __align__(16) char smem[];
    const uint32_t sb = smem_u32(smem);
    const int tid = threadIdx.x, lane = tid & 31, wid = tid >> 5;
    const int b  = blockIdx.z;
    const int q0 = blockIdx.y * 128, k0 = blockIdx.x * 128;
    const int g = lane >> 2, tg = lane & 3;
    const int wm = wid & 1, wn = wid >> 1;
    const int mbase = wm * 64, nbase = wn * 32;
    constexpr int STG = 2 * 128 * 144;

    const int a_r = lane & 15;
    const int a_c = ((lane >> 4) & 1) << 3;
    const int b_r = (lane & 7) + (((lane >> 4) & 1) << 3);
    const int b_c = ((lane >> 3) & 1) << 3;

    auto load_tiles = [&](int h, int stg) {
        const int z = (b << 4) + h;
        const __half* Qg = Q + ((size_t)z * SQ + q0) * DKH;
        const __half* Kg = K + ((size_t)z * SQ + k0) * DKH;
        const uint32_t base = sb + (uint32_t)stg * STG;
        #pragma unroll
        for (int idx = tid; idx < 128 * 8; idx += 256) {
            const int r = idx >> 3, ch = idx & 7;
            cp16(base + (uint32_t)r * 144 + ch * 16, Qg + (size_t)r * DKH + ch * 8);
            cp16(base + 128 * 144 + (uint32_t)r * 144 + ch * 16, Kg + (size_t)r * DKH + ch * 8);
        }
    };

    float macc[4][4][4];
    #pragma unroll
    for (int i = 0; i < 4; i++)
        #pragma unroll
        for (int j = 0; j < 4; j++)
            #pragma unroll
            for (int r = 0; r < 4; r++) macc[i][j][r] = 0.f;

    load_tiles(0, 0);
    cp_commit();

    for (int h = 0; h < 16; h++) {
        const int st = h & 1;
        if (h + 1 < 16) { load_tiles(h + 1, st ^ 1); cp_commit(); cp_wait1(); }
        else cp_wait0();
        __syncthreads();

        const uint32_t sQ = sb + (uint32_t)st * STG;
        const uint32_t sK = sQ + 128 * 144;

        float acc[4][4][4];
        #pragma unroll
        for (int i = 0; i < 4; i++)
            #pragma unroll
            for (int j = 0; j < 4; j++)
                #pragma unroll
                for (int r = 0; r < 4; r++) acc[i][j][r] = 0.f;

        #pragma unroll
        for (int ksx = 0; ksx < 4; ksx++) {
            uint32_t ah[4][4], bh[4][2];
            #pragma unroll
            for (int mt = 0; mt < 4; mt++) {
                const uint32_t off = ((uint32_t)(mbase + mt * 16 + a_r) * 72 + ksx * 16 + a_c) * 2;
                LDMX4(ah[mt], sQ + off);
            }
            #pragma unroll
            for (int np = 0; np < 2; np++) {
                const uint32_t off = ((uint32_t)(nbase + np * 16 + b_r) * 72 + ksx * 16 + b_c) * 2;
                uint32_t r4[4];
                LDMX4(r4, sK + off);
                bh[np*2][0]   = r4[0]; bh[np*2][1]   = r4[1];
                bh[np*2+1][0] = r4[2]; bh[np*2+1][1] = r4[3];
            }
            #pragma unroll
            for (int mt = 0; mt < 4; mt++)
                #pragma unroll
                for (int nt = 0; nt < 4; nt++)
                    mma_f16(acc[mt][nt], ah[mt], bh[nt]);
        }

        const int z = (b << 4) + h;
        const float2* strow = stats + (size_t)z * SQ + q0;
        #pragma unroll
        for (int mt = 0; mt < 4; mt++) {
            const int r0 = mbase + mt * 16 + g;
            const float2 st0 = strow[r0];
            const float2 st1 = strow[r0 + 8];
            #pragma unroll
            for (int nt = 0; nt < 4; nt++) {
                macc[mt][nt][0] += __expf(acc[mt][nt][0] * 0.125f - st0.x) * st0.y;
                macc[mt][nt][1] += __expf(acc[mt][nt][1] * 0.125f - st0.x) * st0.y;
                macc[mt][nt][2] += __expf(acc[mt][nt][2] * 0.125f - st1.x) * st1.y;
                macc[mt][nt][3] += __expf(acc[mt][nt][3] * 0.125f - st1.x) * st1.y;
            }
        }
        __syncthreads();
    }

    float* om = outMean + (size_t)b * SQ * SQ;
    #pragma unroll
    for (int mt = 0; mt < 4; mt++) {
        const int r0 = mbase + mt * 16 + g;
        #pragma unroll
        for (int nt = 0; nt < 4; nt++) {
            const int col = nbase + nt * 8 + tg * 2;
            *(float2*)&om[(size_t)(q0 + r0) * SQ + k0 + col] =
                make_float2(macc[mt][nt][0] * (1.0f / NH), macc[mt][nt][1] * (1.0f / NH));
            *(float2*)&om[(size_t)(q0 + r0 + 8) * SQ + k0 + col] =
                make_float2(macc[mt][nt][2] * (1.0f / NH), macc[mt][nt][3] * (1.0f / NH));
        }
    }
}

// ---------------------------------------------------------------------------
// fused fp32 -> fp16 conversions
// ---------------------------------------------------------------------------
__global__ void __launch_bounds__(256)
cvt_qkv(const float* __restrict__ a, const float* __restrict__ b2, const float* __restrict__ c,
        __half* __restrict__ oa, __half* __restrict__ ob, __half* __restrict__ oc)
{
    const int zi = blockIdx.z;
    const float* s = zi == 0 ? a : (zi == 1 ? b2 : c);
    __half* d = zi == 0 ? oa : (zi == 1 ? ob : oc);
    const int i = (blockIdx.x * 256 + threadIdx.x) * 4;
    float4 v = *(const float4*)(s + i);
    __half2 p0 = __halves2half2(__float2half_rn(v.x), __float2half_rn(v.y));
    __half2 p1 = __halves2half2(__float2half_rn(v.z), __float2half_rn(v.w));
    uint2 u = {*(uint32_t*)&p0, *(uint32_t*)&p1};
    *(uint2*)(d + i) = u;
}
__global__ void __launch_bounds__(256)
cvt_w(const float* __restrict__ a, const float* __restrict__ b2,
      const float* __restrict__ c, const float* __restrict__ e,
      __half* __restrict__ oa, __half* __restrict__ ob,
      __half* __restrict__ oc, __half* __restrict__ oe)
{
    const int zi = blockIdx.z;
    const float* s = zi == 0 ? a : (zi == 1 ? b2 : (zi == 2 ? c : e));
    __half* d = zi == 0 ? oa : (zi == 1 ? ob : (zi == 2 ? oc : oe));
    const int i = (blockIdx.x * 256 + threadIdx.x) * 4;
    float4 v = *(const float4*)(s + i);
    __half2 p0 = __halves2half2(__float2half_rn(v.x), __float2half_rn(v.y));
    __half2 p1 = __halves2half2(__float2half_rn(v.z), __float2half_rn(v.w));
    uint2 u = {*(uint32_t*)&p0, *(uint32_t*)&p1};
    *(uint2*)(d + i) = u;
}

// ---------------------------------------------------------------------------
// V transpose: [Z, S, 64] -> [Z, 64, S]
// ---------------------------------------------------------------------------
__global__ void __launch_bounds__(256)
v_transpose(const __half* __restrict__ s, __half* __restrict__ d)
{
    __shared__ __half t0[32][33];
    const int z  = blockIdx.z;
    const int s0 = blockIdx.y * 32;
    const int d0 = blockIdx.x * 32;
    const int tx = threadIdx.x, ty = threadIdx.y;
    const size_t zin = (size_t)z * SQ * DKH;
    #pragma unroll
    for (int j = 0; j < 4; j++) {
        const int rs = ty + j * 8;
        t0[rs][tx] = s[zin + (size_t)(s0 + rs) * DKH + d0 + tx];
    }
    __syncthreads();
    const size_t zo = (size_t)z * DKH * SQ;
    #pragma unroll
    for (int j = 0; j < 4; j++) {
        const int rd = ty + j * 8;
        d[zo + (size_t)(d0 + rd) * SQ + s0 + tx] = t0[tx][rd];
    }
}

// ---------------------------------------------------------------------------
extern "C" void kernel_launch(void* const* d_in, const int* in_sizes, int n_in,
                              void* d_out, int out_size)
{
    (void)in_sizes; (void)n_in; (void)out_size;
    const float* q  = (const float*)d_in[0];
    const float* k  = (const float*)d_in[1];
    const float* v  = (const float*)d_in[2];
    const float* Wq = (const float*)d_in[3];
    const float* Wk = (const float*)d_in[4];
    const float* Wv = (const float*)d_in[5];
    const float* Wo = (const float*)d_in[6];
    float* out     = (float*)d_out;
    float* outMean = out + (size_t)MR * DM;

    #define SYM(p, s) void* p; cudaGetSymbolAddress(&p, s)
    SYM(pqx, g_qx); SYM(pkx, g_kx); SYM(pvx, g_vx);
    SYM(pwq, g_wq); SYM(pwk, g_wk); SYM(pwv, g_wv); SYM(pwo, g_wo);
    SYM(pQ, g_Q); SYM(pK, g_K); SYM(pVs, g_Vs); SYM(pVt, g_Vt);
    SYM(pstats, g_stats); SYM(pc, g_c);
    #undef SYM

    const int SMEM_GEMM  = 2 * (128 + 128) * 144;                  // 73728
    const int SMEM_FLASH = 128 * 144 + 2 * (128 * 144 + 64 * 272); // 90112
    const int SMEM_MEAN  = 2 * 2 * 128 * 144;                      // 73728
    cudaFuncSetAttribute(hm_proj,   cudaFuncAttributeMaxDynamicSharedMemorySize, SMEM_GEMM);
    cudaFuncSetAttribute(hm_wo,     cudaFuncAttributeMaxDynamicSharedMemorySize, SMEM_GEMM);
    cudaFuncSetAttribute(flash_pv,  cudaFuncAttributeMaxDynamicSharedMemorySize, SMEM_FLASH);
    cudaFuncSetAttribute(mean_only, cudaFuncAttributeMaxDynamicSharedMemorySize, SMEM_MEAN);

    // 1) fp32 -> fp16 conversions
    cvt_qkv<<<dim3(MR * DM / 1024, 1, 3), 256>>>(q, k, v,
        (__half*)pqx, (__half*)pkx, (__half*)pvx);
    cvt_w<<<dim3(DM * DM / 1024, 1, 4), 256>>>(Wq, Wk, Wv, Wo,
        (__half*)pwq, (__half*)pwk, (__half*)pwv, (__half*)pwo);

    // 2) fused Q/K/V projections
    hm_proj<<<dim3(DM / 128, MR / 128, 3), 256, SMEM_GEMM>>>(
        (const __half*)pqx, (const __half*)pkx, (const __half*)pvx,
        (const __half*)pwq, (const __half*)pwk, (const __half*)pwv,
        (__half*)pQ, (__half*)pK, (__half*)pVs);

    // 3) V transpose [Z,S,64] -> [Z,64,S]
    v_transpose<<<dim3(DKH / 32, SQ / 32, NZ), dim3(32, 8)>>>(
        (const __half*)pVs, (__half*)pVt);

    // 4) online flash attention: ctx + stats in one pass
    flash_pv<<<dim3(1, SQ / 128, NZ), 256, SMEM_FLASH>>>(
        (const __half*)pQ, (const __half*)pK, (const __half*)pVt,
        (float2*)pstats, (__half*)pc);

    // 5) out = ctx @ Wo^T
    hm_wo<<<dim3(DM / 128, MR / 128, 1), 256, SMEM_GEMM>>>(
        (const __half*)pc, (const __half*)pwo, out);

    // 6) head mean (fp32, uses stats from flash_pv)
    mean_only<<<dim3(SQ / 128, SQ / 128, NB), 256, SMEM_MEAN>>>(
        (const __half*)pQ, (const __half*)pK, (const float2*)pstats, outMean);
}

// round 11
// speedup vs baseline: 5.3658x; 1.0457x over previous
#include <cuda_runtime.h>
#include <cuda_fp16.h>
#include <cstdint>

#define SQ  2048
#define NB  2
#define DM  1024
#define NH  16
#define DKH 64
#define MR  4096              // S*B rows
#define NZ  (NB*NH)           // 32 batch*head slices

// 0.125 * log2(e): folds the 1/sqrt(dk) scale AND the exp->exp2 conversion
// into the Q projection. Scores come out in log2 domain.
#define QSCALE 0.180336880111124f

// ---------------------------------------------------------------------------
// Scratch (__device__ globals: allocation-free)
// ---------------------------------------------------------------------------
__device__ __half g_qx[(size_t)MR*DM], g_kx[(size_t)MR*DM], g_vx[(size_t)MR*DM];
__device__ __half g_wq[(size_t)DM*DM], g_wk[(size_t)DM*DM];
__device__ __half g_wv[(size_t)DM*DM], g_wo[(size_t)DM*DM];
__device__ __half g_Q[(size_t)NZ*SQ*DKH], g_K[(size_t)NZ*SQ*DKH];
__device__ __half g_Vs[(size_t)NZ*SQ*DKH];          // [Z,S,dk]
__device__ __half g_Vt[(size_t)NZ*DKH*SQ];          // [Z,dk,S]
__device__ float2 g_stats[(size_t)NZ*SQ];           // (log2-domain row max, 1/row sum)
__device__ __half g_c [(size_t)MR*DM];              // ctx [S,B,D]

// ---------------------------------------------------------------------------
// PTX helpers (base-arch: mma.sync / ldmatrix / cp.async)
// ---------------------------------------------------------------------------
__device__ __forceinline__ uint32_t smem_u32(const void* p) {
    uint32_t a;
    asm("{ .reg .u64 t; cvta.to.shared.u64 t, %1; cvt.u32.u64 %0, t; }" : "=r"(a) : "l"(p));
    return a;
}
__device__ __forceinline__ void cp16(uint32_t d, const void* s) {
    asm volatile("cp.async.cg.shared.global [%0], [%1], 16;" :: "r"(d), "l"(s));
}
__device__ __forceinline__ void cp_commit() {
    asm volatile("cp.async.commit_group;" ::: "memory");
}
__device__ __forceinline__ void cp_wait1() {
    asm volatile("cp.async.wait_group 1;" ::: "memory");
}
__device__ __forceinline__ void cp_wait0() {
    asm volatile("cp.async.wait_group 0;" ::: "memory");
}
__device__ __forceinline__ float ex2(float x) {
    float r;
    asm("ex2.approx.f32 %0, %1;" : "=f"(r) : "f"(x));
    return r;
}
#define LDMX4(r, a) \
    asm volatile("ldmatrix.sync.aligned.m8n8.x4.shared.b16 {%0,%1,%2,%3}, [%4];" \
        : "=r"((r)[0]), "=r"((r)[1]), "=r"((r)[2]), "=r"((r)[3]) : "r"(a))

__device__ __forceinline__ void mma_f16(float* c, const uint32_t* a, const uint32_t* b) {
    asm volatile(
        "mma.sync.aligned.m16n8k16.row.col.f32.f16.f16.f32 "
        "{%0,%1,%2,%3},{%4,%5,%6,%7},{%8,%9},{%0,%1,%2,%3};"
        : "+f"(c[0]), "+f"(c[1]), "+f"(c[2]), "+f"(c[3])
        : "r"(a[0]), "r"(a[1]), "r"(a[2]), "r"(a[3]), "r"(b[0]), "r"(b[1]));
}

// ---------------------------------------------------------------------------
// Shared GEMM body (2-stage cp.async): C = alpha * A(MxK) * B(NxK)^T
// EPI: 0 fp32 row-major; 2 fp16 scatter to [B,H,S,dk].
// ---------------------------------------------------------------------------
template<int BM, int BN, int EPI>
__device__ __forceinline__ void gemm_body(
    const __half* __restrict__ A, const __half* __restrict__ B,
    float* __restrict__ Cf, __half* __restrict__ Ch,
    int K, int ldc, float alpha, int m0, int n0, char* smem)
{
    const uint32_t sb = smem_u32(smem);
    const int tid  = threadIdx.x;
    const int lane = tid & 31;
    const int wid  = tid >> 5;

    constexpr int WGM = 2;
    constexpr int TM  = BM / WGM;
    constexpr int TN  = BN / (8 / WGM);
    constexpr int MT  = TM / 16;
    constexpr int NT  = TN / 8;
    constexpr int STAGE = (BM + BN) * 144;

    const int wm = wid % WGM, wn = wid / WGM;
    const int mbase = wm * TM, nbase = wn * TN;

    float acc[MT][NT][4];
    #pragma unroll
    for (int i = 0; i < MT; i++)
        #pragma unroll
        for (int j = 0; j < NT; j++)
            #pragma unroll
            for (int r = 0; r < 4; r++) acc[i][j][r] = 0.f;

    const int a_r = lane & 15;
    const int a_c = ((lane >> 4) & 1) << 3;
    const int b_r = (lane & 7) + (((lane >> 4) & 1) << 3);
    const int b_c = ((lane >> 3) & 1) << 3;

    auto load_stage = [&](int kc, int stg) {
        const uint32_t base = sb + (uint32_t)stg * STAGE;
        #pragma unroll
        for (int idx = tid; idx < BM * 8; idx += 256) {
            const int r = idx >> 3, ch = idx & 7;
            cp16(base + (uint32_t)r * 144 + ch * 16, A + (size_t)r * K + kc + ch * 8);
        }
        #pragma unroll
        for (int idx = tid; idx < BN * 8; idx += 256) {
            const int r = idx >> 3, ch = idx & 7;
            cp16(base + BM * 144 + (uint32_t)r * 144 + ch * 16, B + (size_t)r * K + kc + ch * 8);
        }
    };

    auto compute = [&](int stg) {
        const uint32_t sA0 = sb + (uint32_t)stg * STAGE;
        const uint32_t sB0 = sA0 + BM * 144;
        #pragma unroll
        for (int ks = 0; ks < 4; ks++) {
            uint32_t ah[MT][4], bh[NT][2];
            #pragma unroll
            for (int mt = 0; mt < MT; mt++) {
                const uint32_t off = ((uint32_t)(mbase + mt * 16 + a_r) * 72 + ks * 16 + a_c) * 2;
                LDMX4(ah[mt], sA0 + off);
            }
            #pragma unroll
            for (int np = 0; np < NT / 2; np++) {
                const uint32_t off = ((uint32_t)(nbase + np * 16 + b_r) * 72 + ks * 16 + b_c) * 2;
                uint32_t r4[4];
                LDMX4(r4, sB0 + off);
                bh[np*2][0]   = r4[0]; bh[np*2][1]   = r4[1];
                bh[np*2+1][0] = r4[2]; bh[np*2+1][1] = r4[3];
            }
            #pragma unroll
            for (int mt = 0; mt < MT; mt++)
                #pragma unroll
                for (int nt = 0; nt < NT; nt++)
                    mma_f16(acc[mt][nt], ah[mt], bh[nt]);
        }
    };

    const int NC = K >> 6;
    load_stage(0, 0);
    cp_commit();

    for (int c = 0; c < NC; c++) {
        const int buf = c & 1;
        if (c + 1 < NC) {
            load_stage((c + 1) << 6, buf ^ 1);
            cp_commit();
            cp_wait1();
        } else {
            cp_wait0();
        }
        __syncthreads();
        compute(buf);
        __syncthreads();
    }

    // ---- epilogue: frags -> smem -> coalesced gmem ----
    constexpr int CP = BN + 4;
    float* Cs = (float*)smem;
    const int g = lane >> 2, tg = lane & 3;
    #pragma unroll
    for (int mt = 0; mt < MT; mt++)
        #pragma unroll
        for (int nt = 0; nt < NT; nt++) {
            const int row = mbase + mt * 16 + g;
            const int col = nbase + nt * 8 + tg * 2;
            *(float2*)&Cs[(size_t)row * CP + col]       = make_float2(acc[mt][nt][0], acc[mt][nt][1]);
            *(float2*)&Cs[(size_t)(row + 8) * CP + col] = make_float2(acc[mt][nt][2], acc[mt][nt][3]);
        }
    __syncthreads();

    for (int i4 = tid * 4; i4 < BM * BN; i4 += 1024) {
        const int row = i4 / BN, col = i4 % BN;
        float4 v = *(const float4*)&Cs[(size_t)row * CP + col];
        v.x *= alpha; v.y *= alpha; v.z *= alpha; v.w *= alpha;
        const int m = m0 + row, n = n0 + col;
        if (EPI == 0) {
            *(float4*)&Cf[(size_t)m * ldc + n] = v;
        } else {
            __half2 p0 = __halves2half2(__float2half_rn(v.x), __float2half_rn(v.y));
            __half2 p1 = __halves2half2(__float2half_rn(v.z), __float2half_rn(v.w));
            uint2 u = {*(uint32_t*)&p0, *(uint32_t*)&p1};
            const int s2 = m >> 1, b = m & 1, hh = n >> 6, dk = n & 63;
            const size_t addr = ((size_t)(b * NH + hh) * SQ + s2) * DKH + dk;
            *(uint2*)(Ch + addr) = u;
        }
    }
}

// ---------------------------------------------------------------------------
// Fused Q/K/V projection: grid.z selects (input, weight, output, alpha).
// Q output is pre-scaled by QSCALE (log2-domain scores downstream).
// ---------------------------------------------------------------------------
__global__ void __launch_bounds__(256, 2)
hm_proj(const __half* __restrict__ A0, const __half* __restrict__ A1, const __half* __restrict__ A2,
        const __half* __restrict__ B0, const __half* __restrict__ B1, const __half* __restrict__ B2,
        __half* __restrict__ C0, __half* __restrict__ C1, __half* __restrict__ C2)
{
    extern __shared__ __align__(16) char smem[];
    const int zi = blockIdx.z;
    const __half* A = (zi == 0) ? A0 : (zi == 1) ? A1 : A2;
    const __half* B = (zi == 0) ? B0 : (zi == 1) ? B1 : B2;
    __half*       C = (zi == 0) ? C0 : (zi == 1) ? C1 : C2;
    const float alpha = (zi == 0) ? QSCALE : 1.0f;
    const int m0 = blockIdx.y * 128, n0 = blockIdx.x * 128;
    gemm_body<128, 128, 2>(A + (size_t)m0 * DM, B + (size_t)n0 * DM,
                           nullptr, C, DM, 0, alpha, m0, n0, smem);
}

// ---------------------------------------------------------------------------
// Output projection: out = ctx @ Wo^T (fp32 out)
// ---------------------------------------------------------------------------
__global__ void __launch_bounds__(256, 2)
hm_wo(const __half* __restrict__ A, const __half* __restrict__ B, float* __restrict__ Cf)
{
    extern __shared__ __align__(16) char smem[];
    const int m0 = blockIdx.y * 128, n0 = blockIdx.x * 128;
    gemm_body<128, 128, 0>(A + (size_t)m0 * DM, B + (size_t)n0 * DM,
                           Cf, nullptr, DM, DM, 1.0f, m0, n0, smem);
}

// ---------------------------------------------------------------------------
// flash_pv (ONLINE, halved score tiles for register pressure):
// Block = (z, 128-row q-tile); loops 16 k-tiles; each k-tile processed as
// two 64-col halves (acc[8][4] + pf[8][2] instead of 16-wide) -> ~2 CTAs/SM.
// Scores arrive in log2 domain (Q pre-scaled); ex2 is a single MUFU op.
// Writes ctx fp16 [S,B,D] + (m, 1/s) stats for mean_only.
// ---------------------------------------------------------------------------
__global__ void __launch_bounds__(256, 2)
flash_pv(const __half* __restrict__ Q, const __half* __restrict__ K,
         const __half* __restrict__ Vt, float2* __restrict__ stats,
         __half* __restrict__ Ch)
{
    extern __shared__ __align__(16) char smem[];
    const uint32_t sb = smem_u32(smem);
    const int tid = threadIdx.x, lane = tid & 31, wid = tid >> 5;
    const int z = blockIdx.z, q0 = blockIdx.y * 128;
    const int g = lane >> 2, tg = lane & 3;
    const int wbase = wid * 16;

    const __half* Qg = Q  + ((size_t)z * SQ + q0) * DKH;
    const __half* Kg = K  + (size_t)z * SQ * DKH;
    const __half* Vg = Vt + (size_t)z * DKH * SQ;

    const uint32_t qs  = sb;                    // Q tile: 128 x 64h, pitch 144
    const uint32_t st0 = sb + 128 * 144;        // stages
    constexpr int VOFF  = 128 * 144;            // K tile bytes within stage
    constexpr int STAGE = 128 * 144 + 64 * 272; // + Vt tile (64 x 128h, pitch 272)

    auto loadKV = [&](int kt, int stg) {
        const uint32_t base = st0 + (uint32_t)stg * STAGE;
        #pragma unroll
        for (int idx = tid; idx < 128 * 8; idx += 256) {
            const int r = idx >> 3, ch = idx & 7;
            cp16(base + (uint32_t)r * 144 + ch * 16,
                 Kg + ((size_t)(kt * 128 + r)) * DKH + ch * 8);
        }
        #pragma unroll
        for (int idx = tid; idx < 64 * 16; idx += 256) {
            const int r = idx >> 4, ch = idx & 15;
            cp16(base + VOFF + (uint32_t)r * 272 + ch * 16,
                 Vg + (size_t)r * SQ + kt * 128 + ch * 8);
        }
    };

    #pragma unroll
    for (int idx = tid; idx < 128 * 8; idx += 256) {
        const int r = idx >> 3, ch = idx & 7;
        cp16(qs + (uint32_t)r * 144 + ch * 16, Qg + (size_t)r * DKH + ch * 8);
    }
    loadKV(0, 0);
    cp_commit();

    const int a_r = lane & 15;
    const int a_c = ((lane >> 4) & 1) << 3;
    const int b_r = (lane & 7) + (((lane >> 4) & 1) << 3);
    const int b_c = ((lane >> 3) & 1) << 3;

    float m0 = -3.4e38f, m1 = -3.4e38f, s0 = 0.f, s1 = 0.f;

    float ctx[8][4];
    #pragma unroll
    for (int i = 0; i < 8; i++)
        #pragma unroll
        for (int r = 0; r < 4; r++) ctx[i][r] = 0.f;

    for (int kt = 0; kt < SQ / 128; kt++) {
        const int buf = kt & 1;
        if (kt + 1 < SQ / 128) { loadKV(kt + 1, buf ^ 1); cp_commit(); cp_wait1(); }
        else cp_wait0();
        __syncthreads();

        const uint32_t kb = st0 + (uint32_t)buf * STAGE;
        const uint32_t vb = kb + VOFF;

        #pragma unroll
        for (int half = 0; half < 2; half++) {
            // ---- scores half: 16 rows x 64 cols per warp ----
            float acc[8][4];
            #pragma unroll
            for (int nt = 0; nt < 8; nt++)
                acc[nt][0] = acc[nt][1] = acc[nt][2] = acc[nt][3] = 0.f;

            #pragma unroll
            for (int ksx = 0; ksx < 4; ksx++) {
                uint32_t ah[4];
                LDMX4(ah, qs + ((uint32_t)(wbase + a_r) * 72 + ksx * 16 + a_c) * 2);
                uint32_t bh[8][2];
                #pragma unroll
                for (int np = 0; np < 4; np++) {
                    const int npg = half * 4 + np;
                    uint32_t r4[4];
                    LDMX4(r4, kb + ((uint32_t)(npg * 16 + b_r) * 72 + ksx * 16 + b_c) * 2);
                    bh[np*2][0]   = r4[0]; bh[np*2][1]   = r4[1];
                    bh[np*2+1][0] = r4[2]; bh[np*2+1][1] = r4[3];
                }
                #pragma unroll
                for (int nt = 0; nt < 8; nt++) mma_f16(acc[nt], ah, bh[nt]);
            }

            // ---- online (m, s) update (log2 domain) ----
            float mx0 = -3.4e38f, mx1 = -3.4e38f;
            #pragma unroll
            for (int nt = 0; nt < 8; nt++) {
                mx0 = fmaxf(mx0, fmaxf(acc[nt][0], acc[nt][1]));
                mx1 = fmaxf(mx1, fmaxf(acc[nt][2], acc[nt][3]));
            }
            mx0 = fmaxf(mx0, __shfl_xor_sync(0xFFFFFFFFu, mx0, 1));
            mx0 = fmaxf(mx0, __shfl_xor_sync(0xFFFFFFFFu, mx0, 2));
            mx1 = fmaxf(mx1, __shfl_xor_sync(0xFFFFFFFFu, mx1, 1));
            mx1 = fmaxf(mx1, __shfl_xor_sync(0xFFFFFFFFu, mx1, 2));
            const float nm0 = fmaxf(m0, mx0);
            const float nm1 = fmaxf(m1, mx1);
            const float f0 = ex2(m0 - nm0);
            const float f1 = ex2(m1 - nm1);
            m0 = nm0; m1 = nm1;

            #pragma unroll
            for (int i = 0; i < 8; i++) {
                ctx[i][0] *= f0; ctx[i][1] *= f0;
                ctx[i][2] *= f1; ctx[i][3] *= f1;
            }

            // ---- p' = ex2(s - m), packed as fp16 A-fragments; accumulate sum ----
            uint32_t pf[8][2];
            float t0 = 0.f, t1 = 0.f;
            #pragma unroll
            for (int nt = 0; nt < 8; nt++) {
                const float p0 = ex2(acc[nt][0] - nm0);
                const float p1 = ex2(acc[nt][1] - nm0);
                const float p2 = ex2(acc[nt][2] - nm1);
                const float p3 = ex2(acc[nt][3] - nm1);
                t0 += p0 + p1;
                t1 += p2 + p3;
                __half2 u0 = __floats2half2_rn(p0, p1);
                __half2 u1 = __floats2half2_rn(p2, p3);
                pf[nt][0] = *(uint32_t*)&u0;
                pf[nt][1] = *(uint32_t*)&u1;
            }
            t0 += __shfl_xor_sync(0xFFFFFFFFu, t0, 1);
            t0 += __shfl_xor_sync(0xFFFFFFFFu, t0, 2);
            t1 += __shfl_xor_sync(0xFFFFFFFFu, t1, 1);
            t1 += __shfl_xor_sync(0xFFFFFFFFu, t1, 2);
            s0 = s0 * f0 + t0;
            s1 = s1 * f1 + t1;

            // ---- ctx += p' @ V (k range of this half) ----
            #pragma unroll
            for (int kc = 0; kc < 4; kc++) {
                uint32_t af[4] = {pf[2*kc][0], pf[2*kc][1], pf[2*kc+1][0], pf[2*kc+1][1]};
                const int kk = half * 4 + kc;
                #pragma unroll
                for (int np = 0; np < 4; np++) {
                    uint32_t r4[4];
                    LDMX4(r4, vb + ((uint32_t)(np * 16 + b_r) * 272 + (kk * 16 + b_c) * 2));
                    uint32_t b0[2] = {r4[0], r4[1]};
                    uint32_t b1[2] = {r4[2], r4[3]};
                    mma_f16(ctx[2*np],     af, b0);
                    mma_f16(ctx[2*np + 1], af, b1);
                }
            }
        }
        __syncthreads();
    }

    // ---- finalize: normalize by 1/s, write ctx + stats ----
    const float is0 = 1.f / s0;
    const float is1 = 1.f / s1;
    const int b = z >> 4, hh = z & 15;
    const int row0 = q0 + wbase + g;
    #pragma unroll
    for (int nt = 0; nt < 8; nt++) {
        const int col = hh * DKH + nt * 8 + tg * 2;
        __half2 u0 = __floats2half2_rn(ctx[nt][0] * is0, ctx[nt][1] * is0);
        __half2 u1 = __floats2half2_rn(ctx[nt][2] * is1, ctx[nt][3] * is1);
        *(__half2*)(Ch + ((size_t)row0 * NB + b) * DM + col)       = u0;
        *(__half2*)(Ch + ((size_t)(row0 + 8) * NB + b) * DM + col) = u1;
    }
    if (tg == 0) {
        stats[(size_t)z * SQ + row0]     = make_float2(m0, is0);
        stats[(size_t)z * SQ + row0 + 8] = make_float2(m1, is1);
    }
}

// ---------------------------------------------------------------------------
// mean_only: head-mean of probs. Block = (k-tile 64, q-tile 128, b);
// loops 16 heads with cp.async pipelining. WGM=4 layout -> 64 regs of accum,
// 2 CTAs/SM. Uses log2-domain stats from flash_pv.
// ---------------------------------------------------------------------------
__global__ void __launch_bounds__(256, 2)
mean_only(const __half* __restrict__ Q, const __half* __restrict__ K,
          const float2* __restrict__ stats, float* __restrict__ outMean)
{
    extern __shared__ __align__(16) char smem[];
    const uint32_t sb = smem_u32(smem);
    const int tid = threadIdx.x, lane = tid & 31, wid = tid >> 5;
    const int b  = blockIdx.z;
    const int q0 = blockIdx.y * 128, k0 = blockIdx.x * 64;
    const int g = lane >> 2, tg = lane & 3;
    const int wm = wid & 3, wn = wid >> 2;
    const int mbase = wm * 32, nbase = wn * 32;
    constexpr int STG = (128 + 64) * 144;   // Q tile + K tile per stage

    const int a_r = lane & 15;
    const int a_c = ((lane >> 4) & 1) << 3;
    const int b_r = (lane & 7) + (((lane >> 4) & 1) << 3);
    const int b_c = ((lane >> 3) & 1) << 3;

    auto load_tiles = [&](int h, int stg) {
        const int z = (b << 4) + h;
        const __half* Qg = Q + ((size_t)z * SQ + q0) * DKH;
        const __half* Kg = K + ((size_t)z * SQ + k0) * DKH;
        const uint32_t base = sb + (uint32_t)stg * STG;
        #pragma unroll
        for (int idx = tid; idx < 128 * 8; idx += 256) {
            const int r = idx >> 3, ch = idx & 7;
            cp16(base + (uint32_t)r * 144 + ch * 16, Qg + (size_t)r * DKH + ch * 8);
        }
        #pragma unroll
        for (int idx = tid; idx < 64 * 8; idx += 256) {
            const int r = idx >> 3, ch = idx & 7;
            cp16(base + 128 * 144 + (uint32_t)r * 144 + ch * 16, Kg + (size_t)r * DKH + ch * 8);
        }
    };

    float macc[2][4][4];
    #pragma unroll
    for (int i = 0; i < 2; i++)
        #pragma unroll
        for (int j = 0; j < 4; j++)
            #pragma unroll
            for (int r = 0; r < 4; r++) macc[i][j][r] = 0.f;

    load_tiles(0, 0);
    cp_commit();

    for (int h = 0; h < 16; h++) {
        const int st = h & 1;
        if (h + 1 < 16) { load_tiles(h + 1, st ^ 1); cp_commit(); cp_wait1(); }
        else cp_wait0();
        __syncthreads();

        const uint32_t sQ = sb + (uint32_t)st * STG;
        const uint32_t sK = sQ + 128 * 144;

        float acc[2][4][4];
        #pragma unroll
        for (int i = 0; i < 2; i++)
            #pragma unroll
            for (int j = 0; j < 4; j++)
                #pragma unroll
                for (int r = 0; r < 4; r++) acc[i][j][r] = 0.f;

        #pragma unroll
        for (int ksx = 0; ksx < 4; ksx++) {
            uint32_t ah[2][4], bh[4][2];
            #pragma unroll
            for (int mt = 0; mt < 2; mt++) {
                const uint32_t off = ((uint32_t)(mbase + mt * 16 + a_r) * 72 + ksx * 16 + a_c) * 2;
                LDMX4(ah[mt], sQ + off);
            }
            #pragma unroll
            for (int np = 0; np < 2; np++) {
                const uint32_t off = ((uint32_t)(nbase + np * 16 + b_r) * 72 + ksx * 16 + b_c) * 2;
                uint32_t r4[4];
                LDMX4(r4, sK + off);
                bh[np*2][0]   = r4[0]; bh[np*2][1]   = r4[1];
                bh[np*2+1][0] = r4[2]; bh[np*2+1][1] = r4[3];
            }
            #pragma unroll
            for (int mt = 0; mt < 2; mt++)
                #pragma unroll
                for (int nt = 0; nt < 4; nt++)
                    mma_f16(acc[mt][nt], ah[mt], bh[nt]);
        }

        const int z = (b << 4) + h;
        const float2* strow = stats + (size_t)z * SQ + q0;
        #pragma unroll
        for (int mt = 0; mt < 2; mt++) {
            const int r0 = mbase + mt * 16 + g;
            const float2 st0 = strow[r0];
            const float2 st1 = strow[r0 + 8];
            #pragma unroll
            for (int nt = 0; nt < 4; nt++) {
                macc[mt][nt][0] += ex2(acc[mt][nt][0] - st0.x) * st0.y;
                macc[mt][nt][1] += ex2(acc[mt][nt][1] - st0.x) * st0.y;
                macc[mt][nt][2] += ex2(acc[mt][nt][2] - st1.x) * st1.y;
                macc[mt][nt][3] += ex2(acc[mt][nt][3] - st1.x) * st1.y;
            }
        }
        __syncthreads();
    }

    float* om = outMean + (size_t)b * SQ * SQ;
    #pragma unroll
    for (int mt = 0; mt < 2; mt++) {
        const int r0 = mbase + mt * 16 + g;
        #pragma unroll
        for (int nt = 0; nt < 4; nt++) {
            const int col = nbase + nt * 8 + tg * 2;
            *(float2*)&om[(size_t)(q0 + r0) * SQ + k0 + col] =
                make_float2(macc[mt][nt][0] * (1.0f / NH), macc[mt][nt][1] * (1.0f / NH));
            *(float2*)&om[(size_t)(q0 + r0 + 8) * SQ + k0 + col] =
                make_float2(macc[mt][nt][2] * (1.0f / NH), macc[mt][nt][3] * (1.0f / NH));
        }
    }
}

// ---------------------------------------------------------------------------
// fused fp32 -> fp16 conversions
// ---------------------------------------------------------------------------
__global__ void __launch_bounds__(256)
cvt_qkv(const float* __restrict__ a, const float* __restrict__ b2, const float* __restrict__ c,
        __half* __restrict__ oa, __half* __restrict__ ob, __half* __restrict__ oc)
{
    const int zi = blockIdx.z;
    const float* s = zi == 0 ? a : (zi == 1 ? b2 : c);
    __half* d = zi == 0 ? oa : (zi == 1 ? ob : oc);
    const int i = (blockIdx.x * 256 + threadIdx.x) * 4;
    float4 v = *(const float4*)(s + i);
    __half2 p0 = __halves2half2(__float2half_rn(v.x), __float2half_rn(v.y));
    __half2 p1 = __halves2half2(__float2half_rn(v.z), __float2half_rn(v.w));
    uint2 u = {*(uint32_t*)&p0, *(uint32_t*)&p1};
    *(uint2*)(d + i) = u;
}
__global__ void __launch_bounds__(256)
cvt_w(const float* __restrict__ a, const float* __restrict__ b2,
      const float* __restrict__ c, const float* __restrict__ e,
      __half* __restrict__ oa, __half* __restrict__ ob,
      __half* __restrict__ oc, __half* __restrict__ oe)
{
    const int zi = blockIdx.z;
    const float* s = zi == 0 ? a : (zi == 1 ? b2 : (zi == 2 ? c : e));
    __half* d = zi == 0 ? oa : (zi == 1 ? ob : (zi == 2 ? oc : oe));
    const int i = (blockIdx.x * 256 + threadIdx.x) * 4;
    float4 v = *(const float4*)(s + i);
    __half2 p0 = __halves2half2(__float2half_rn(v.x), __float2half_rn(v.y));
    __half2 p1 = __halves2half2(__float2half_rn(v.z), __float2half_rn(v.w));
    uint2 u = {*(uint32_t*)&p0, *(uint32_t*)&p1};
    *(uint2*)(d + i) = u;
}

// ---------------------------------------------------------------------------
// V transpose: [Z, S, 64] -> [Z, 64, S]
// ---------------------------------------------------------------------------
__global__ void __launch_bounds__(256)
v_transpose(const __half* __restrict__ s, __half* __restrict__ d)
{
    __shared__ __half t0[32][33];
    const int z  = blockIdx.z;
    const int s0 = blockIdx.y * 32;
    const int d0 = blockIdx.x * 32;
    const int tx = threadIdx.x, ty = threadIdx.y;
    const size_t zin = (size_t)z * SQ * DKH;
    #pragma unroll
    for (int j = 0; j < 4; j++) {
        const int rs = ty + j * 8;
        t0[rs][tx] = s[zin + (size_t)(s0 + rs) * DKH + d0 + tx];
    }
    __syncthreads();
    const size_t zo = (size_t)z * DKH * SQ;
    #pragma unroll
    for (int j = 0; j < 4; j++) {
        const int rd = ty + j * 8;
        d[zo + (size_t)(d0 + rd) * SQ + s0 + tx] = t0[tx][rd];
    }
}

// ---------------------------------------------------------------------------
extern "C" void kernel_launch(void* const* d_in, const int* in_sizes, int n_in,
                              void* d_out, int out_size)
{
    (void)in_sizes; (void)n_in; (void)out_size;
    const float* q  = (const float*)d_in[0];
    const float* k  = (const float*)d_in[1];
    const float* v  = (const float*)d_in[2];
    const float* Wq = (const float*)d_in[3];
    const float* Wk = (const float*)d_in[4];
    const float* Wv = (const float*)d_in[5];
    const float* Wo = (const float*)d_in[6];
    float* out     = (float*)d_out;
    float* outMean = out + (size_t)MR * DM;

    #define SYM(p, s) void* p; cudaGetSymbolAddress(&p, s)
    SYM(pqx, g_qx); SYM(pkx, g_kx); SYM(pvx, g_vx);
    SYM(pwq, g_wq); SYM(pwk, g_wk); SYM(pwv, g_wv); SYM(pwo, g_wo);
    SYM(pQ, g_Q); SYM(pK, g_K); SYM(pVs, g_Vs); SYM(pVt, g_Vt);
    SYM(pstats, g_stats); SYM(pc, g_c);
    #undef SYM

    const int SMEM_GEMM  = 2 * (128 + 128) * 144;                  // 73728
    const int SMEM_FLASH = 128 * 144 + 2 * (128 * 144 + 64 * 272); // 90112
    const int SMEM_MEAN  = 2 * (128 + 64) * 144;                   // 55296
    cudaFuncSetAttribute(hm_proj,   cudaFuncAttributeMaxDynamicSharedMemorySize, SMEM_GEMM);
    cudaFuncSetAttribute(hm_wo,     cudaFuncAttributeMaxDynamicSharedMemorySize, SMEM_GEMM);
    cudaFuncSetAttribute(flash_pv,  cudaFuncAttributeMaxDynamicSharedMemorySize, SMEM_FLASH);
    cudaFuncSetAttribute(mean_only, cudaFuncAttributeMaxDynamicSharedMemorySize, SMEM_MEAN);

    // 1) fp32 -> fp16 conversions
    cvt_qkv<<<dim3(MR * DM / 1024, 1, 3), 256>>>(q, k, v,
        (__half*)pqx, (__half*)pkx, (__half*)pvx);
    cvt_w<<<dim3(DM * DM / 1024, 1, 4), 256>>>(Wq, Wk, Wv, Wo,
        (__half*)pwq, (__half*)pwk, (__half*)pwv, (__half*)pwo);

    // 2) fused Q/K/V projections (Q pre-scaled by 0.125*log2e)
    hm_proj<<<dim3(DM / 128, MR / 128, 3), 256, SMEM_GEMM>>>(
        (const __half*)pqx, (const __half*)pkx, (const __half*)pvx,
        (const __half*)pwq, (const __half*)pwk, (const __half*)pwv,
        (__half*)pQ, (__half*)pK, (__half*)pVs);

    // 3) V transpose [Z,S,64] -> [Z,64,S]
    v_transpose<<<dim3(DKH / 32, SQ / 32, NZ), dim3(32, 8)>>>(
        (const __half*)pVs, (__half*)pVt);

    // 4) online flash attention: ctx + stats in one pass
    flash_pv<<<dim3(1, SQ / 128, NZ), 256, SMEM_FLASH>>>(
        (const __half*)pQ, (const __half*)pK, (const __half*)pVt,
        (float2*)pstats, (__half*)pc);

    // 5) out = ctx @ Wo^T
    hm_wo<<<dim3(DM / 128, MR / 128, 1), 256, SMEM_GEMM>>>(
        (const __half*)pc, (const __half*)pwo, out);

    // 6) head mean (fp32, uses stats from flash_pv)
    mean_only<<<dim3(SQ / 64, SQ / 128, NB), 256, SMEM_MEAN>>>(
        (const __half*)pQ, (const __half*)pK, (const float2*)pstats, outMean);
}

// round 12
// speedup vs baseline: 5.6194x; 1.0473x over previous
#include <cuda_runtime.h>
#include <cuda_fp16.h>
#include <cstdint>

#define SQ  2048
#define NB  2
#define DM  1024
#define NH  16
#define DKH 64
#define MR  4096              // S*B rows
#define NZ  (NB*NH)           // 32 batch*head slices

// 0.125 * log2(e): folds the 1/sqrt(dk) scale AND the exp->exp2 conversion
// into the Q projection. Scores come out in log2 domain.
#define QSCALE 0.180336880111124f

// ---------------------------------------------------------------------------
// Scratch (__device__ globals: allocation-free)
// ---------------------------------------------------------------------------
__device__ __half g_qx[(size_t)MR*DM], g_kx[(size_t)MR*DM], g_vx[(size_t)MR*DM];
__device__ __half g_wq[(size_t)DM*DM], g_wk[(size_t)DM*DM];
__device__ __half g_wv[(size_t)DM*DM], g_wo[(size_t)DM*DM];
__device__ __half g_Q[(size_t)NZ*SQ*DKH], g_K[(size_t)NZ*SQ*DKH];
__device__ __half g_Vs[(size_t)NZ*SQ*DKH];          // [Z,S,dk]
__device__ __half g_Vt[(size_t)NZ*DKH*SQ];          // [Z,dk,S]
__device__ float2 g_stats[(size_t)NZ*SQ];           // (log2-domain row max, 1/row sum)
__device__ __half g_c [(size_t)MR*DM];              // ctx [S,B,D]

// ---------------------------------------------------------------------------
// PTX helpers (base-arch: mma.sync / ldmatrix / cp.async)
// ---------------------------------------------------------------------------
__device__ __forceinline__ uint32_t smem_u32(const void* p) {
    uint32_t a;
    asm("{ .reg .u64 t; cvta.to.shared.u64 t, %1; cvt.u32.u64 %0, t; }" : "=r"(a) : "l"(p));
    return a;
}
__device__ __forceinline__ void cp16(uint32_t d, const void* s) {
    asm volatile("cp.async.cg.shared.global [%0], [%1], 16;" :: "r"(d), "l"(s));
}
__device__ __forceinline__ void cp_commit() {
    asm volatile("cp.async.commit_group;" ::: "memory");
}
__device__ __forceinline__ void cp_wait1() {
    asm volatile("cp.async.wait_group 1;" ::: "memory");
}
__device__ __forceinline__ void cp_wait0() {
    asm volatile("cp.async.wait_group 0;" ::: "memory");
}
__device__ __forceinline__ float ex2(float x) {
    float r;
    asm("ex2.approx.f32 %0, %1;" : "=f"(r) : "f"(x));
    return r;
}
#define LDMX4(r, a) \
    asm volatile("ldmatrix.sync.aligned.m8n8.x4.shared.b16 {%0,%1,%2,%3}, [%4];" \
        : "=r"((r)[0]), "=r"((r)[1]), "=r"((r)[2]), "=r"((r)[3]) : "r"(a))

__device__ __forceinline__ void mma_f16(float* c, const uint32_t* a, const uint32_t* b) {
    asm volatile(
        "mma.sync.aligned.m16n8k16.row.col.f32.f16.f16.f32 "
        "{%0,%1,%2,%3},{%4,%5,%6,%7},{%8,%9},{%0,%1,%2,%3};"
        : "+f"(c[0]), "+f"(c[1]), "+f"(c[2]), "+f"(c[3])
        : "r"(a[0]), "r"(a[1]), "r"(a[2]), "r"(a[3]), "r"(b[0]), "r"(b[1]));
}

// ---------------------------------------------------------------------------
// Epilogue (shared): 128x128 fp32 tile staged in smem -> coalesced gmem.
// EPI: 0 fp32 row-major; 2 fp16 scatter to [B,H,S,dk].
// ---------------------------------------------------------------------------
template<int BM, int BN, int EPI>
__device__ __forceinline__ void gemm_epilogue(
    float acc[BM/32][BN/32][4],   // MT x NT x 4 with WGM=2 layout
    float* __restrict__ Cf, __half* __restrict__ Ch,
    int ldc, float alpha, int m0, int n0, char* smem,
    int mbase, int nbase)
{
    constexpr int MT = BM / 32, NT = BN / 32;
    constexpr int CP = BN + 4;
    const int tid = threadIdx.x, lane = tid & 31;
    float* Cs = (float*)smem;
    const int g = lane >> 2, tg = lane & 3;
    #pragma unroll
    for (int mt = 0; mt < MT; mt++)
        #pragma unroll
        for (int nt = 0; nt < NT; nt++) {
            const int row = mbase + mt * 16 + g;
            const int col = nbase + nt * 8 + tg * 2;
            *(float2*)&Cs[(size_t)row * CP + col]       = make_float2(acc[mt][nt][0], acc[mt][nt][1]);
            *(float2*)&Cs[(size_t)(row + 8) * CP + col] = make_float2(acc[mt][nt][2], acc[mt][nt][3]);
        }
    __syncthreads();

    for (int i4 = tid * 4; i4 < BM * BN; i4 += 1024) {
        const int row = i4 / BN, col = i4 % BN;
        float4 v = *(const float4*)&Cs[(size_t)row * CP + col];
        v.x *= alpha; v.y *= alpha; v.z *= alpha; v.w *= alpha;
        const int m = m0 + row, n = n0 + col;
        if (EPI == 0) {
            *(float4*)&Cf[(size_t)m * ldc + n] = v;
        } else {
            __half2 p0 = __halves2half2(__float2half_rn(v.x), __float2half_rn(v.y));
            __half2 p1 = __halves2half2(__float2half_rn(v.z), __float2half_rn(v.w));
            uint2 u = {*(uint32_t*)&p0, *(uint32_t*)&p1};
            const int s2 = m >> 1, b = m & 1, hh = n >> 6, dk = n & 63;
            const size_t addr = ((size_t)(b * NH + hh) * SQ + s2) * DKH + dk;
            *(uint2*)(Ch + addr) = u;
        }
    }
}

// ---------------------------------------------------------------------------
// 2-stage GEMM body: C = alpha * A(MxK) * B(NxK)^T  (used by wo path)
// ---------------------------------------------------------------------------
template<int BM, int BN, int EPI>
__device__ __forceinline__ void gemm_body(
    const __half* __restrict__ A, const __half* __restrict__ B,
    float* __restrict__ Cf, __half* __restrict__ Ch,
    int K, int ldc, float alpha, int m0, int n0, char* smem)
{
    const uint32_t sb = smem_u32(smem);
    const int tid  = threadIdx.x;
    const int lane = tid & 31;
    const int wid  = tid >> 5;

    constexpr int MT = BM / 32, NT = BN / 32;
    constexpr int STAGE = (BM + BN) * 144;

    const int wm = wid % 2, wn = wid / 2;
    const int mbase = wm * (BM / 2), nbase = wn * (BN / 4);

    float acc[MT][NT][4];
    #pragma unroll
    for (int i = 0; i < MT; i++)
        #pragma unroll
        for (int j = 0; j < NT; j++)
            #pragma unroll
            for (int r = 0; r < 4; r++) acc[i][j][r] = 0.f;

    const int a_r = lane & 15;
    const int a_c = ((lane >> 4) & 1) << 3;
    const int b_r = (lane & 7) + (((lane >> 4) & 1) << 3);
    const int b_c = ((lane >> 3) & 1) << 3;

    auto load_stage = [&](int kc, int stg) {
        const uint32_t base = sb + (uint32_t)stg * STAGE;
        #pragma unroll
        for (int idx = tid; idx < BM * 8; idx += 256) {
            const int r = idx >> 3, ch = idx & 7;
            cp16(base + (uint32_t)r * 144 + ch * 16, A + (size_t)r * K + kc + ch * 8);
        }
        #pragma unroll
        for (int idx = tid; idx < BN * 8; idx += 256) {
            const int r = idx >> 3, ch = idx & 7;
            cp16(base + BM * 144 + (uint32_t)r * 144 + ch * 16, B + (size_t)r * K + kc + ch * 8);
        }
    };

    auto compute = [&](int stg) {
        const uint32_t sA0 = sb + (uint32_t)stg * STAGE;
        const uint32_t sB0 = sA0 + BM * 144;
        #pragma unroll
        for (int ks = 0; ks < 4; ks++) {
            uint32_t ah[MT][4], bh[NT][2];
            #pragma unroll
            for (int mt = 0; mt < MT; mt++) {
                const uint32_t off = ((uint32_t)(mbase + mt * 16 + a_r) * 72 + ks * 16 + a_c) * 2;
                LDMX4(ah[mt], sA0 + off);
            }
            #pragma unroll
            for (int np = 0; np < NT / 2; np++) {
                const uint32_t off = ((uint32_t)(nbase + np * 16 + b_r) * 72 + ks * 16 + b_c) * 2;
                uint32_t r4[4];
                LDMX4(r4, sB0 + off);
                bh[np*2][0]   = r4[0]; bh[np*2][1]   = r4[1];
                bh[np*2+1][0] = r4[2]; bh[np*2+1][1] = r4[3];
            }
            #pragma unroll
            for (int mt = 0; mt < MT; mt++)
                #pragma unroll
                for (int nt = 0; nt < NT; nt++)
                    mma_f16(acc[mt][nt], ah[mt], bh[nt]);
        }
    };

    const int NC = K >> 6;
    load_stage(0, 0);
    cp_commit();

    for (int c = 0; c < NC; c++) {
        const int buf = c & 1;
        if (c + 1 < NC) {
            load_stage((c + 1) << 6, buf ^ 1);
            cp_commit();
            cp_wait1();
        } else {
            cp_wait0();
        }
        __syncthreads();
        compute(buf);
        __syncthreads();
    }

    gemm_epilogue<BM, BN, EPI>(acc, Cf, Ch, ldc, alpha, m0, n0, smem, mbase, nbase);
}

// ---------------------------------------------------------------------------
// 3-stage GEMM body (pipelined, one sync per chunk) — used by projections.
// ---------------------------------------------------------------------------
template<int BM, int BN, int EPI>
__device__ __forceinline__ void gemm_body3(
    const __half* __restrict__ A, const __half* __restrict__ B,
    float* __restrict__ Cf, __half* __restrict__ Ch,
    int K, int ldc, float alpha, int m0, int n0, char* smem)
{
    const uint32_t sb = smem_u32(smem);
    const int tid  = threadIdx.x;
    const int lane = tid & 31;
    const int wid  = tid >> 5;

    constexpr int MT = BM / 32, NT = BN / 32;
    constexpr int STAGE = (BM + BN) * 144;

    const int wm = wid % 2, wn = wid / 2;
    const int mbase = wm * (BM / 2), nbase = wn * (BN / 4);

    float acc[MT][NT][4];
    #pragma unroll
    for (int i = 0; i < MT; i++)
        #pragma unroll
        for (int j = 0; j < NT; j++)
            #pragma unroll
            for (int r = 0; r < 4; r++) acc[i][j][r] = 0.f;

    const int a_r = lane & 15;
    const int a_c = ((lane >> 4) & 1) << 3;
    const int b_r = (lane & 7) + (((lane >> 4) & 1) << 3);
    const int b_c = ((lane >> 3) & 1) << 3;

    auto load_stage = [&](int kc, int stg) {
        const uint32_t base = sb + (uint32_t)stg * STAGE;
        #pragma unroll
        for (int idx = tid; idx < BM * 8; idx += 256) {
            const int r = idx >> 3, ch = idx & 7;
            cp16(base + (uint32_t)r * 144 + ch * 16, A + (size_t)r * K + kc + ch * 8);
        }
        #pragma unroll
        for (int idx = tid; idx < BN * 8; idx += 256) {
            const int r = idx >> 3, ch = idx & 7;
            cp16(base + BM * 144 + (uint32_t)r * 144 + ch * 16, B + (size_t)r * K + kc + ch * 8);
        }
    };

    const int NC = K >> 6;
    load_stage(0, 0);  cp_commit();
    load_stage(64, 1); cp_commit();

    for (int c = 0; c < NC; c++) {
        if (c + 1 < NC) cp_wait1(); else cp_wait0();
        __syncthreads();
        if (c + 2 < NC) { load_stage((c + 2) << 6, (c + 2) % 3); cp_commit(); }

        const uint32_t sA0 = sb + (uint32_t)(c % 3) * STAGE;
        const uint32_t sB0 = sA0 + BM * 144;
        #pragma unroll
        for (int ks = 0; ks < 4; ks++) {
            uint32_t ah[MT][4], bh[NT][2];
            #pragma unroll
            for (int mt = 0; mt < MT; mt++) {
                const uint32_t off = ((uint32_t)(mbase + mt * 16 + a_r) * 72 + ks * 16 + a_c) * 2;
                LDMX4(ah[mt], sA0 + off);
            }
            #pragma unroll
            for (int np = 0; np < NT / 2; np++) {
                const uint32_t off = ((uint32_t)(nbase + np * 16 + b_r) * 72 + ks * 16 + b_c) * 2;
                uint32_t r4[4];
                LDMX4(r4, sB0 + off);
                bh[np*2][0]   = r4[0]; bh[np*2][1]   = r4[1];
                bh[np*2+1][0] = r4[2]; bh[np*2+1][1] = r4[3];
            }
            #pragma unroll
            for (int mt = 0; mt < MT; mt++)
                #pragma unroll
                for (int nt = 0; nt < NT; nt++)
                    mma_f16(acc[mt][nt], ah[mt], bh[nt]);
        }
    }
    __syncthreads();

    gemm_epilogue<BM, BN, EPI>(acc, Cf, Ch, ldc, alpha, m0, n0, smem, mbase, nbase);
}

// ---------------------------------------------------------------------------
// Fused Q/K/V projection (3-stage): grid.z selects (input, weight, output).
// Q output pre-scaled by QSCALE (log2-domain scores downstream).
// ---------------------------------------------------------------------------
__global__ void __launch_bounds__(256, 2)
hm_proj(const __half* __restrict__ A0, const __half* __restrict__ A1, const __half* __restrict__ A2,
        const __half* __restrict__ B0, const __half* __restrict__ B1, const __half* __restrict__ B2,
        __half* __restrict__ C0, __half* __restrict__ C1, __half* __restrict__ C2)
{
    extern __shared__ __align__(16) char smem[];
    const int zi = blockIdx.z;
    const __half* A = (zi == 0) ? A0 : (zi == 1) ? A1 : A2;
    const __half* B = (zi == 0) ? B0 : (zi == 1) ? B1 : B2;
    __half*       C = (zi == 0) ? C0 : (zi == 1) ? C1 : C2;
    const float alpha = (zi == 0) ? QSCALE : 1.0f;
    const int m0 = blockIdx.y * 128, n0 = blockIdx.x * 128;
    gemm_body3<128, 128, 2>(A + (size_t)m0 * DM, B + (size_t)n0 * DM,
                            nullptr, C, DM, 0, alpha, m0, n0, smem);
}

// ---------------------------------------------------------------------------
// flash_pv (ONLINE, halved score tiles): unchanged from R11 (passing).
// ---------------------------------------------------------------------------
__global__ void __launch_bounds__(256, 2)
flash_pv(const __half* __restrict__ Q, const __half* __restrict__ K,
         const __half* __restrict__ Vt, float2* __restrict__ stats,
         __half* __restrict__ Ch)
{
    extern __shared__ __align__(16) char smem[];
    const uint32_t sb = smem_u32(smem);
    const int tid = threadIdx.x, lane = tid & 31, wid = tid >> 5;
    const int z = blockIdx.z, q0 = blockIdx.y * 128;
    const int g = lane >> 2, tg = lane & 3;
    const int wbase = wid * 16;

    const __half* Qg = Q  + ((size_t)z * SQ + q0) * DKH;
    const __half* Kg = K  + (size_t)z * SQ * DKH;
    const __half* Vg = Vt + (size_t)z * DKH * SQ;

    const uint32_t qs  = sb;
    const uint32_t st0 = sb + 128 * 144;
    constexpr int VOFF  = 128 * 144;
    constexpr int STAGE = 128 * 144 + 64 * 272;

    auto loadKV = [&](int kt, int stg) {
        const uint32_t base = st0 + (uint32_t)stg * STAGE;
        #pragma unroll
        for (int idx = tid; idx < 128 * 8; idx += 256) {
            const int r = idx >> 3, ch = idx & 7;
            cp16(base + (uint32_t)r * 144 + ch * 16,
                 Kg + ((size_t)(kt * 128 + r)) * DKH + ch * 8);
        }
        #pragma unroll
        for (int idx = tid; idx < 64 * 16; idx += 256) {
            const int r = idx >> 4, ch = idx & 15;
            cp16(base + VOFF + (uint32_t)r * 272 + ch * 16,
                 Vg + (size_t)r * SQ + kt * 128 + ch * 8);
        }
    };

    #pragma unroll
    for (int idx = tid; idx < 128 * 8; idx += 256) {
        const int r = idx >> 3, ch = idx & 7;
        cp16(qs + (uint32_t)r * 144 + ch * 16, Qg + (size_t)r * DKH + ch * 8);
    }
    loadKV(0, 0);
    cp_commit();

    const int a_r = lane & 15;
    const int a_c = ((lane >> 4) & 1) << 3;
    const int b_r = (lane & 7) + (((lane >> 4) & 1) << 3);
    const int b_c = ((lane >> 3) & 1) << 3;

    float m0 = -3.4e38f, m1 = -3.4e38f, s0 = 0.f, s1 = 0.f;

    float ctx[8][4];
    #pragma unroll
    for (int i = 0; i < 8; i++)
        #pragma unroll
        for (int r = 0; r < 4; r++) ctx[i][r] = 0.f;

    for (int kt = 0; kt < SQ / 128; kt++) {
        const int buf = kt & 1;
        if (kt + 1 < SQ / 128) { loadKV(kt + 1, buf ^ 1); cp_commit(); cp_wait1(); }
        else cp_wait0();
        __syncthreads();

        const uint32_t kb = st0 + (uint32_t)buf * STAGE;
        const uint32_t vb = kb + VOFF;

        #pragma unroll
        for (int half = 0; half < 2; half++) {
            float acc[8][4];
            #pragma unroll
            for (int nt = 0; nt < 8; nt++)
                acc[nt][0] = acc[nt][1] = acc[nt][2] = acc[nt][3] = 0.f;

            #pragma unroll
            for (int ksx = 0; ksx < 4; ksx++) {
                uint32_t ah[4];
                LDMX4(ah, qs + ((uint32_t)(wbase + a_r) * 72 + ksx * 16 + a_c) * 2);
                uint32_t bh[8][2];
                #pragma unroll
                for (int np = 0; np < 4; np++) {
                    const int npg = half * 4 + np;
                    uint32_t r4[4];
                    LDMX4(r4, kb + ((uint32_t)(npg * 16 + b_r) * 72 + ksx * 16 + b_c) * 2);
                    bh[np*2][0]   = r4[0]; bh[np*2][1]   = r4[1];
                    bh[np*2+1][0] = r4[2]; bh[np*2+1][1] = r4[3];
                }
                #pragma unroll
                for (int nt = 0; nt < 8; nt++) mma_f16(acc[nt], ah, bh[nt]);
            }

            float mx0 = -3.4e38f, mx1 = -3.4e38f;
            #pragma unroll
            for (int nt = 0; nt < 8; nt++) {
                mx0 = fmaxf(mx0, fmaxf(acc[nt][0], acc[nt][1]));
                mx1 = fmaxf(mx1, fmaxf(acc[nt][2], acc[nt][3]));
            }
            mx0 = fmaxf(mx0, __shfl_xor_sync(0xFFFFFFFFu, mx0, 1));
            mx0 = fmaxf(mx0, __shfl_xor_sync(0xFFFFFFFFu, mx0, 2));
            mx1 = fmaxf(mx1, __shfl_xor_sync(0xFFFFFFFFu, mx1, 1));
            mx1 = fmaxf(mx1, __shfl_xor_sync(0xFFFFFFFFu, mx1, 2));
            const float nm0 = fmaxf(m0, mx0);
            const float nm1 = fmaxf(m1, mx1);
            const float f0 = ex2(m0 - nm0);
            const float f1 = ex2(m1 - nm1);
            m0 = nm0; m1 = nm1;

            #pragma unroll
            for (int i = 0; i < 8; i++) {
                ctx[i][0] *= f0; ctx[i][1] *= f0;
                ctx[i][2] *= f1; ctx[i][3] *= f1;
            }

            uint32_t pf[8][2];
            float t0 = 0.f, t1 = 0.f;
            #pragma unroll
            for (int nt = 0; nt < 8; nt++) {
                const float p0 = ex2(acc[nt][0] - nm0);
                const float p1 = ex2(acc[nt][1] - nm0);
                const float p2 = ex2(acc[nt][2] - nm1);
                const float p3 = ex2(acc[nt][3] - nm1);
                t0 += p0 + p1;
                t1 += p2 + p3;
                __half2 u0 = __floats2half2_rn(p0, p1);
                __half2 u1 = __floats2half2_rn(p2, p3);
                pf[nt][0] = *(uint32_t*)&u0;
                pf[nt][1] = *(uint32_t*)&u1;
            }
            t0 += __shfl_xor_sync(0xFFFFFFFFu, t0, 1);
            t0 += __shfl_xor_sync(0xFFFFFFFFu, t0, 2);
            t1 += __shfl_xor_sync(0xFFFFFFFFu, t1, 1);
            t1 += __shfl_xor_sync(0xFFFFFFFFu, t1, 2);
            s0 = s0 * f0 + t0;
            s1 = s1 * f1 + t1;

            #pragma unroll
            for (int kc = 0; kc < 4; kc++) {
                uint32_t af[4] = {pf[2*kc][0], pf[2*kc][1], pf[2*kc+1][0], pf[2*kc+1][1]};
                const int kk = half * 4 + kc;
                #pragma unroll
                for (int np = 0; np < 4; np++) {
                    uint32_t r4[4];
                    LDMX4(r4, vb + ((uint32_t)(np * 16 + b_r) * 272 + (kk * 16 + b_c) * 2));
                    uint32_t b0[2] = {r4[0], r4[1]};
                    uint32_t b1[2] = {r4[2], r4[3]};
                    mma_f16(ctx[2*np],     af, b0);
                    mma_f16(ctx[2*np + 1], af, b1);
                }
            }
        }
        __syncthreads();
    }

    const float is0 = 1.f / s0;
    const float is1 = 1.f / s1;
    const int b = z >> 4, hh = z & 15;
    const int row0 = q0 + wbase + g;
    #pragma unroll
    for (int nt = 0; nt < 8; nt++) {
        const int col = hh * DKH + nt * 8 + tg * 2;
        __half2 u0 = __floats2half2_rn(ctx[nt][0] * is0, ctx[nt][1] * is0);
        __half2 u1 = __floats2half2_rn(ctx[nt][2] * is1, ctx[nt][3] * is1);
        *(__half2*)(Ch + ((size_t)row0 * NB + b) * DM + col)       = u0;
        *(__half2*)(Ch + ((size_t)(row0 + 8) * NB + b) * DM + col) = u1;
    }
    if (tg == 0) {
        stats[(size_t)z * SQ + row0]     = make_float2(m0, is0);
        stats[(size_t)z * SQ + row0 + 8] = make_float2(m1, is1);
    }
}

// ---------------------------------------------------------------------------
// mean body (device): head-mean of probs for one (b, q-tile 128, k-tile 64).
// ---------------------------------------------------------------------------
__device__ __forceinline__ void mean_body(
    const __half* __restrict__ Q, const __half* __restrict__ K,
    const float2* __restrict__ stats, float* __restrict__ outMean,
    int b, int q0, int k0, char* smem)
{
    const uint32_t sb = smem_u32(smem);
    const int tid = threadIdx.x, lane = tid & 31, wid = tid >> 5;
    const int g = lane >> 2, tg = lane & 3;
    const int wm = wid & 3, wn = wid >> 2;
    const int mbase = wm * 32, nbase = wn * 32;
    constexpr int STG = (128 + 64) * 144;

    const int a_r = lane & 15;
    const int a_c = ((lane >> 4) & 1) << 3;
    const int b_r = (lane & 7) + (((lane >> 4) & 1) << 3);
    const int b_c = ((lane >> 3) & 1) << 3;

    auto load_tiles = [&](int h, int stg) {
        const int z = (b << 4) + h;
        const __half* Qg = Q + ((size_t)z * SQ + q0) * DKH;
        const __half* Kg = K + ((size_t)z * SQ + k0) * DKH;
        const uint32_t base = sb + (uint32_t)stg * STG;
        #pragma unroll
        for (int idx = tid; idx < 128 * 8; idx += 256) {
            const int r = idx >> 3, ch = idx & 7;
            cp16(base + (uint32_t)r * 144 + ch * 16, Qg + (size_t)r * DKH + ch * 8);
        }
        #pragma unroll
        for (int idx = tid; idx < 64 * 8; idx += 256) {
            const int r = idx >> 3, ch = idx & 7;
            cp16(base + 128 * 144 + (uint32_t)r * 144 + ch * 16, Kg + (size_t)r * DKH + ch * 8);
        }
    };

    float macc[2][4][4];
    #pragma unroll
    for (int i = 0; i < 2; i++)
        #pragma unroll
        for (int j = 0; j < 4; j++)
            #pragma unroll
            for (int r = 0; r < 4; r++) macc[i][j][r] = 0.f;

    load_tiles(0, 0);
    cp_commit();

    for (int h = 0; h < 16; h++) {
        const int st = h & 1;
        if (h + 1 < 16) { load_tiles(h + 1, st ^ 1); cp_commit(); cp_wait1(); }
        else cp_wait0();
        __syncthreads();

        const uint32_t sQ = sb + (uint32_t)st * STG;
        const uint32_t sK = sQ + 128 * 144;

        float acc[2][4][4];
        #pragma unroll
        for (int i = 0; i < 2; i++)
            #pragma unroll
            for (int j = 0; j < 4; j++)
                #pragma unroll
                for (int r = 0; r < 4; r++) acc[i][j][r] = 0.f;

        #pragma unroll
        for (int ksx = 0; ksx < 4; ksx++) {
            uint32_t ah[2][4], bh[4][2];
            #pragma unroll
            for (int mt = 0; mt < 2; mt++) {
                const uint32_t off = ((uint32_t)(mbase + mt * 16 + a_r) * 72 + ksx * 16 + a_c) * 2;
                LDMX4(ah[mt], sQ + off);
            }
            #pragma unroll
            for (int np = 0; np < 2; np++) {
                const uint32_t off = ((uint32_t)(nbase + np * 16 + b_r) * 72 + ksx * 16 + b_c) * 2;
                uint32_t r4[4];
                LDMX4(r4, sK + off);
                bh[np*2][0]   = r4[0]; bh[np*2][1]   = r4[1];
                bh[np*2+1][0] = r4[2]; bh[np*2+1][1] = r4[3];
            }
            #pragma unroll
            for (int mt = 0; mt < 2; mt++)
                #pragma unroll
                for (int nt = 0; nt < 4; nt++)
                    mma_f16(acc[mt][nt], ah[mt], bh[nt]);
        }

        const int z = (b << 4) + h;
        const float2* strow = stats + (size_t)z * SQ + q0;
        #pragma unroll
        for (int mt = 0; mt < 2; mt++) {
            const int r0 = mbase + mt * 16 + g;
            const float2 st0 = strow[r0];
            const float2 st1 = strow[r0 + 8];
            #pragma unroll
            for (int nt = 0; nt < 4; nt++) {
                macc[mt][nt][0] += ex2(acc[mt][nt][0] - st0.x) * st0.y;
                macc[mt][nt][1] += ex2(acc[mt][nt][1] - st0.x) * st0.y;
                macc[mt][nt][2] += ex2(acc[mt][nt][2] - st1.x) * st1.y;
                macc[mt][nt][3] += ex2(acc[mt][nt][3] - st1.x) * st1.y;
            }
        }
        __syncthreads();
    }

    float* om = outMean + (size_t)b * SQ * SQ;
    #pragma unroll
    for (int mt = 0; mt < 2; mt++) {
        const int r0 = mbase + mt * 16 + g;
        #pragma unroll
        for (int nt = 0; nt < 4; nt++) {
            const int col = nbase + nt * 8 + tg * 2;
            *(float2*)&om[(size_t)(q0 + r0) * SQ + k0 + col] =
                make_float2(macc[mt][nt][0] * (1.0f / NH), macc[mt][nt][1] * (1.0f / NH));
            *(float2*)&om[(size_t)(q0 + r0 + 8) * SQ + k0 + col] =
                make_float2(macc[mt][nt][2] * (1.0f / NH), macc[mt][nt][3] * (1.0f / NH));
        }
    }
}

// ---------------------------------------------------------------------------
// Merged wo + mean launch: z in {0,1} -> mean tiles; z == 2 -> Wo GEMM tiles.
// Both paths independent consumers of flash_pv outputs -> true concurrency.
// ---------------------------------------------------------------------------
__global__ void __launch_bounds__(256, 2)
wo_mean(const __half* __restrict__ ctx, const __half* __restrict__ Wo,
        float* __restrict__ out,
        const __half* __restrict__ Q, const __half* __restrict__ K,
        const float2* __restrict__ stats, float* __restrict__ outMean)
{
    extern __shared__ __align__(16) char smem[];
    const int z = blockIdx.z;
    if (z < NB) {
        mean_body(Q, K, stats, outMean, z, blockIdx.y * 128, blockIdx.x * 64, smem);
    } else {
        const int idx = blockIdx.y * 32 + blockIdx.x;
        if (idx >= (MR / 128) * (DM / 128)) return;
        const int m0 = (idx >> 3) * 128, n0 = (idx & 7) * 128;
        gemm_body<128, 128, 0>(ctx + (size_t)m0 * DM, Wo + (size_t)n0 * DM,
                               out, nullptr, DM, DM, 1.0f, m0, n0, smem);
    }
}

// ---------------------------------------------------------------------------
// fused fp32 -> fp16 conversion (7 segments via grid.z)
// ---------------------------------------------------------------------------
__global__ void __launch_bounds__(256)
cvt_all(const float* __restrict__ i0, const float* __restrict__ i1, const float* __restrict__ i2,
        const float* __restrict__ i3, const float* __restrict__ i4, const float* __restrict__ i5,
        const float* __restrict__ i6,
        __half* __restrict__ o0, __half* __restrict__ o1, __half* __restrict__ o2,
        __half* __restrict__ o3, __half* __restrict__ o4, __half* __restrict__ o5,
        __half* __restrict__ o6)
{
    const int zi = blockIdx.z;
    const float* s;
    __half* d;
    int n;
    switch (zi) {
        case 0: s = i0; d = o0; n = MR * DM; break;
        case 1: s = i1; d = o1; n = MR * DM; break;
        case 2: s = i2; d = o2; n = MR * DM; break;
        case 3: s = i3; d = o3; n = DM * DM; break;
        case 4: s = i4; d = o4; n = DM * DM; break;
        case 5: s = i5; d = o5; n = DM * DM; break;
        default: s = i6; d = o6; n = DM * DM; break;
    }
    const int i = (blockIdx.x * 256 + threadIdx.x) * 4;
    if (i >= n) return;
    float4 v = *(const float4*)(s + i);
    __half2 p0 = __halves2half2(__float2half_rn(v.x), __float2half_rn(v.y));
    __half2 p1 = __halves2half2(__float2half_rn(v.z), __float2half_rn(v.w));
    uint2 u = {*(uint32_t*)&p0, *(uint32_t*)&p1};
    *(uint2*)(d + i) = u;
}

// ---------------------------------------------------------------------------
// V transpose: [Z, S, 64] -> [Z, 64, S]
// ---------------------------------------------------------------------------
__global__ void __launch_bounds__(256)
v_transpose(const __half* __restrict__ s, __half* __restrict__ d)
{
    __shared__ __half t0[32][33];
    const int z  = blockIdx.z;
    const int s0 = blockIdx.y * 32;
    const int d0 = blockIdx.x * 32;
    const int tx = threadIdx.x, ty = threadIdx.y;
    const size_t zin = (size_t)z * SQ * DKH;
    #pragma unroll
    for (int j = 0; j < 4; j++) {
        const int rs = ty + j * 8;
        t0[rs][tx] = s[zin + (size_t)(s0 + rs) * DKH + d0 + tx];
    }
    __syncthreads();
    const size_t zo = (size_t)z * DKH * SQ;
    #pragma unroll
    for (int j = 0; j < 4; j++) {
        const int rd = ty + j * 8;
        d[zo + (size_t)(d0 + rd) * SQ + s0 + tx] = t0[tx][rd];
    }
}

// ---------------------------------------------------------------------------
extern "C" void kernel_launch(void* const* d_in, const int* in_sizes, int n_in,
                              void* d_out, int out_size)
{
    (void)in_sizes; (void)n_in; (void)out_size;
    const float* q  = (const float*)d_in[0];
    const float* k  = (const float*)d_in[1];
    const float* v  = (const float*)d_in[2];
    const float* Wq = (const float*)d_in[3];
    const float* Wk = (const float*)d_in[4];
    const float* Wv = (const float*)d_in[5];
    const float* Wo = (const float*)d_in[6];
    float* out     = (float*)d_out;
    float* outMean = out + (size_t)MR * DM;

    #define SYM(p, s) void* p; cudaGetSymbolAddress(&p, s)
    SYM(pqx, g_qx); SYM(pkx, g_kx); SYM(pvx, g_vx);
    SYM(pwq, g_wq); SYM(pwk, g_wk); SYM(pwv, g_wv); SYM(pwo, g_wo);
    SYM(pQ, g_Q); SYM(pK, g_K); SYM(pVs, g_Vs); SYM(pVt, g_Vt);
    SYM(pstats, g_stats); SYM(pc, g_c);
    #undef SYM

    const int SMEM_PROJ  = 3 * (128 + 128) * 144;                  // 110592
    const int SMEM_FLASH = 128 * 144 + 2 * (128 * 144 + 64 * 272); // 90112
    const int SMEM_WOME  = 2 * (128 + 128) * 144;                  // 73728 (max of both paths)
    cudaFuncSetAttribute(hm_proj,   cudaFuncAttributeMaxDynamicSharedMemorySize, SMEM_PROJ);
    cudaFuncSetAttribute(flash_pv,  cudaFuncAttributeMaxDynamicSharedMemorySize, SMEM_FLASH);
    cudaFuncSetAttribute(wo_mean,   cudaFuncAttributeMaxDynamicSharedMemorySize, SMEM_WOME);

    // 1) fp32 -> fp16 conversions (single launch, 7 segments)
    cvt_all<<<dim3(MR * DM / 1024, 1, 7), 256>>>(
        q, k, v, Wq, Wk, Wv, Wo,
        (__half*)pqx, (__half*)pkx, (__half*)pvx,
        (__half*)pwq, (__half*)pwk, (__half*)pwv, (__half*)pwo);

    // 2) fused Q/K/V projections (3-stage pipeline; Q pre-scaled)
    hm_proj<<<dim3(DM / 128, MR / 128, 3), 256, SMEM_PROJ>>>(
        (const __half*)pqx, (const __half*)pkx, (const __half*)pvx,
        (const __half*)pwq, (const __half*)pwk, (const __half*)pwv,
        (__half*)pQ, (__half*)pK, (__half*)pVs);

    // 3) V transpose [Z,S,64] -> [Z,64,S]
    v_transpose<<<dim3(DKH / 32, SQ / 32, NZ), dim3(32, 8)>>>(
        (const __half*)pVs, (__half*)pVt);

    // 4) online flash attention: ctx + stats in one pass
    flash_pv<<<dim3(1, SQ / 128, NZ), 256, SMEM_FLASH>>>(
        (const __half*)pQ, (const __half*)pK, (const __half*)pVt,
        (float2*)pstats, (__half*)pc);

    // 5) merged: out = ctx @ Wo^T  (z=2)  +  head mean (z=0,1), concurrent
    wo_mean<<<dim3(SQ / 64, SQ / 128, NB + 1), 256, SMEM_WOME>>>(
        (const __half*)pc, (const __half*)pwo, out,
        (const __half*)pQ, (const __half*)pK, (const float2*)pstats, outMean);
}

// round 14
// speedup vs baseline: 5.6527x; 1.0059x over previous
#include <cuda_runtime.h>
#include <cuda_fp16.h>
#include <cstdint>

#define SQ  2048
#define NB  2
#define DM  1024
#define NH  16
#define DKH 64
#define MR  4096              // S*B rows
#define NZ  (NB*NH)           // 32 batch*head slices

// 0.125 * log2(e): folds the 1/sqrt(dk) scale AND the exp->exp2 conversion
// into the Q projection. Scores come out in log2 domain.
#define QSCALE 0.180336880111124f

// ---------------------------------------------------------------------------
// Scratch (__device__ globals: allocation-free)
// ---------------------------------------------------------------------------
__device__ __half g_qx[(size_t)MR*DM], g_kx[(size_t)MR*DM], g_vx[(size_t)MR*DM];
__device__ __half g_wq[(size_t)DM*DM], g_wk[(size_t)DM*DM];
__device__ __half g_wv[(size_t)DM*DM], g_wo[(size_t)DM*DM];
__device__ __half g_Q[(size_t)NZ*SQ*DKH], g_K[(size_t)NZ*SQ*DKH];
__device__ __half g_Vt[(size_t)NZ*DKH*SQ];          // [Z,dk,S] (written directly by proj)
__device__ float2 g_stats[(size_t)NZ*SQ];           // (log2-domain row max, 1/row sum)
__device__ __half g_c [(size_t)MR*DM];              // ctx [S,B,D]

// ---------------------------------------------------------------------------
// PTX helpers (base-arch: mma.sync / ldmatrix / cp.async)
// ---------------------------------------------------------------------------
__device__ __forceinline__ uint32_t smem_u32(const void* p) {
    uint32_t a;
    asm("{ .reg .u64 t; cvta.to.shared.u64 t, %1; cvt.u32.u64 %0, t; }" : "=r"(a) : "l"(p));
    return a;
}
__device__ __forceinline__ void cp16(uint32_t d, const void* s) {
    asm volatile("cp.async.cg.shared.global [%0], [%1], 16;" :: "r"(d), "l"(s));
}
__device__ __forceinline__ void cp_commit() {
    asm volatile("cp.async.commit_group;" ::: "memory");
}
__device__ __forceinline__ void cp_wait1() {
    asm volatile("cp.async.wait_group 1;" ::: "memory");
}
__device__ __forceinline__ void cp_wait0() {
    asm volatile("cp.async.wait_group 0;" ::: "memory");
}
__device__ __forceinline__ float ex2(float x) {
    float r;
    asm("ex2.approx.f32 %0, %1;" : "=f"(r) : "f"(x));
    return r;
}
#define LDMX4(r, a) \
    asm volatile("ldmatrix.sync.aligned.m8n8.x4.shared.b16 {%0,%1,%2,%3}, [%4];" \
        : "=r"((r)[0]), "=r"((r)[1]), "=r"((r)[2]), "=r"((r)[3]) : "r"(a))

__device__ __forceinline__ void mma_f16(float* c, const uint32_t* a, const uint32_t* b) {
    asm volatile(
        "mma.sync.aligned.m16n8k16.row.col.f32.f16.f16.f32 "
        "{%0,%1,%2,%3},{%4,%5,%6,%7},{%8,%9},{%0,%1,%2,%3};"
        : "+f"(c[0]), "+f"(c[1]), "+f"(c[2]), "+f"(c[3])
        : "r"(a[0]), "r"(a[1]), "r"(a[2]), "r"(a[3]), "r"(b[0]), "r"(b[1]));
}

// ---------------------------------------------------------------------------
// Epilogue: 128x128 fp32 tile staged in smem -> gmem.
// EPI: 0 fp32 row-major; 2 fp16 scatter to [B,H,S,dk] (Q/K proj);
//      4 fp16 transposed write to Vt [Z,dk,S] (V proj, coalesced along s).
// ---------------------------------------------------------------------------
template<int BM, int BN, int EPI>
__device__ __forceinline__ void gemm_epilogue(
    float acc[BM/32][BN/32][4],
    float* __restrict__ Cf, __half* __restrict__ Ch,
    int ldc, float alpha, int m0, int n0, char* smem,
    int mbase, int nbase)
{
    constexpr int MT = BM / 32, NT = BN / 32;
    constexpr int CP = BN + 4;
    const int tid = threadIdx.x, lane = tid & 31;
    float* Cs = (float*)smem;
    const int g = lane >> 2, tg = lane & 3;
    #pragma unroll
    for (int mt = 0; mt < MT; mt++)
        #pragma unroll
        for (int nt = 0; nt < NT; nt++) {
            const int row = mbase + mt * 16 + g;
            const int col = nbase + nt * 8 + tg * 2;
            *(float2*)&Cs[(size_t)row * CP + col]       = make_float2(acc[mt][nt][0], acc[mt][nt][1]);
            *(float2*)&Cs[(size_t)(row + 8) * CP + col] = make_float2(acc[mt][nt][2], acc[mt][nt][3]);
        }
    __syncthreads();

    if (EPI == 4) {
        // Vt[z = b*NH+h][dk][s]: warp w owns 16 cols; lane l owns s-pair (2l, 2l+1).
        // Row m = m0+row encodes (s,b) as m = 2s+b, so rows {4l+b, 4l+2+b}
        // give lane l the s-pair (m0/2 + 2l, m0/2 + 2l + 1) for each b.
        const int w = tid >> 5;
        const int s0 = m0 >> 1;
        #pragma unroll
        for (int nn = 0; nn < 16; nn++) {
            const int col = w * 16 + nn;
            const int n = n0 + col;
            const int hh = n >> 6, dk = n & 63;
            #pragma unroll
            for (int b = 0; b < NB; b++) {
                const float v0 = Cs[(size_t)(4 * lane + b) * CP + col] * alpha;
                const float v1 = Cs[(size_t)(4 * lane + 2 + b) * CP + col] * alpha;
                __half2 u = __floats2half2_rn(v0, v1);
                *(__half2*)(Ch + (((size_t)(b * NH + hh) * DKH + dk) * SQ + s0 + 2 * lane)) = u;
            }
        }
        return;
    }

    for (int i4 = tid * 4; i4 < BM * BN; i4 += 1024) {
        const int row = i4 / BN, col = i4 % BN;
        float4 v = *(const float4*)&Cs[(size_t)row * CP + col];
        v.x *= alpha; v.y *= alpha; v.z *= alpha; v.w *= alpha;
        const int m = m0 + row, n = n0 + col;
        if (EPI == 0) {
            *(float4*)&Cf[(size_t)m * ldc + n] = v;
        } else {
            __half2 p0 = __halves2half2(__float2half_rn(v.x), __float2half_rn(v.y));
            __half2 p1 = __halves2half2(__float2half_rn(v.z), __float2half_rn(v.w));
            uint2 u = {*(uint32_t*)&p0, *(uint32_t*)&p1};
            const int s2 = m >> 1, b = m & 1, hh = n >> 6, dk = n & 63;
            const size_t addr = ((size_t)(b * NH + hh) * SQ + s2) * DKH + dk;
            *(uint2*)(Ch + addr) = u;
        }
    }
}

// ---------------------------------------------------------------------------
// 3-stage GEMM body (pipelined, one sync per chunk).
// ---------------------------------------------------------------------------
template<int BM, int BN, int EPI>
__device__ __forceinline__ void gemm_body3(
    const __half* __restrict__ A, const __half* __restrict__ B,
    float* __restrict__ Cf, __half* __restrict__ Ch,
    int K, int ldc, float alpha, int m0, int n0, char* smem)
{
    const uint32_t sb = smem_u32(smem);
    const int tid  = threadIdx.x;
    const int lane = tid & 31;
    const int wid  = tid >> 5;

    constexpr int MT = BM / 32, NT = BN / 32;
    constexpr int STAGE = (BM + BN) * 144;

    const int wm = wid % 2, wn = wid / 2;
    const int mbase = wm * (BM / 2), nbase = wn * (BN / 4);

    float acc[MT][NT][4];
    #pragma unroll
    for (int i = 0; i < MT; i++)
        #pragma unroll
        for (int j = 0; j < NT; j++)
            #pragma unroll
            for (int r = 0; r < 4; r++) acc[i][j][r] = 0.f;

    const int a_r = lane & 15;
    const int a_c = ((lane >> 4) & 1) << 3;
    const int b_r = (lane & 7) + (((lane >> 4) & 1) << 3);
    const int b_c = ((lane >> 3) & 1) << 3;

    auto load_stage = [&](int kc, int stg) {
        const uint32_t base = sb + (uint32_t)stg * STAGE;
        #pragma unroll
        for (int idx = tid; idx < BM * 8; idx += 256) {
            const int r = idx >> 3, ch = idx & 7;
            cp16(base + (uint32_t)r * 144 + ch * 16, A + (size_t)r * K + kc + ch * 8);
        }
        #pragma unroll
        for (int idx = tid; idx < BN * 8; idx += 256) {
            const int r = idx >> 3, ch = idx & 7;
            cp16(base + BM * 144 + (uint32_t)r * 144 + ch * 16, B + (size_t)r * K + kc + ch * 8);
        }
    };

    const int NC = K >> 6;
    load_stage(0, 0);  cp_commit();
    load_stage(64, 1); cp_commit();

    for (int c = 0; c < NC; c++) {
        if (c + 1 < NC) cp_wait1(); else cp_wait0();
        __syncthreads();
        if (c + 2 < NC) { load_stage((c + 2) << 6, (c + 2) % 3); cp_commit(); }

        const uint32_t sA0 = sb + (uint32_t)(c % 3) * STAGE;
        const uint32_t sB0 = sA0 + BM * 144;
        #pragma unroll
        for (int ks = 0; ks < 4; ks++) {
            uint32_t ah[MT][4], bh[NT][2];
            #pragma unroll
            for (int mt = 0; mt < MT; mt++) {
                const uint32_t off = ((uint32_t)(mbase + mt * 16 + a_r) * 72 + ks * 16 + a_c) * 2;
                LDMX4(ah[mt], sA0 + off);
            }
            #pragma unroll
            for (int np = 0; np < NT / 2; np++) {
                const uint32_t off = ((uint32_t)(nbase + np * 16 + b_r) * 72 + ks * 16 + b_c) * 2;
                uint32_t r4[4];
                LDMX4(r4, sB0 + off);
                bh[np*2][0]   = r4[0]; bh[np*2][1]   = r4[1];
                bh[np*2+1][0] = r4[2]; bh[np*2+1][1] = r4[3];
            }
            #pragma unroll
            for (int mt = 0; mt < MT; mt++)
                #pragma unroll
                for (int nt = 0; nt < NT; nt++)
                    mma_f16(acc[mt][nt], ah[mt], bh[nt]);
        }
    }
    __syncthreads();

    gemm_epilogue<BM, BN, EPI>(acc, Cf, Ch, ldc, alpha, m0, n0, smem, mbase, nbase);
}

// ---------------------------------------------------------------------------
// Fused Q/K/V projection (3-stage): grid.z selects (input, weight, output).
// Q pre-scaled by QSCALE; V written transposed to Vt [Z,dk,S] (EPI=4).
// ---------------------------------------------------------------------------
__global__ void __launch_bounds__(256, 2)
hm_proj(const __half* __restrict__ A0, const __half* __restrict__ A1, const __half* __restrict__ A2,
        const __half* __restrict__ B0, const __half* __restrict__ B1, const __half* __restrict__ B2,
        __half* __restrict__ C0, __half* __restrict__ C1, __half* __restrict__ C2)
{
    extern __shared__ __align__(16) char smem[];
    const int zi = blockIdx.z;
    const int m0 = blockIdx.y * 128, n0 = blockIdx.x * 128;
    if (zi == 0) {
        gemm_body3<128, 128, 2>(A0 + (size_t)m0 * DM, B0 + (size_t)n0 * DM,
                                nullptr, C0, DM, 0, QSCALE, m0, n0, smem);
    } else if (zi == 1) {
        gemm_body3<128, 128, 2>(A1 + (size_t)m0 * DM, B1 + (size_t)n0 * DM,
                                nullptr, C1, DM, 0, 1.0f, m0, n0, smem);
    } else {
        gemm_body3<128, 128, 4>(A2 + (size_t)m0 * DM, B2 + (size_t)n0 * DM,
                                nullptr, C2, DM, 0, 1.0f, m0, n0, smem);
    }
}

// ---------------------------------------------------------------------------
// flash_pv (ONLINE, halved score tiles): unchanged from R12 (passing).
// ---------------------------------------------------------------------------
__global__ void __launch_bounds__(256, 2)
flash_pv(const __half* __restrict__ Q, const __half* __restrict__ K,
         const __half* __restrict__ Vt, float2* __restrict__ stats,
         __half* __restrict__ Ch)
{
    extern __shared__ __align__(16) char smem[];
    const uint32_t sb = smem_u32(smem);
    const int tid = threadIdx.x, lane = tid & 31, wid = tid >> 5;
    const int z = blockIdx.z, q0 = blockIdx.y * 128;
    const int g = lane >> 2, tg = lane & 3;
    const int wbase = wid * 16;

    const __half* Qg = Q  + ((size_t)z * SQ + q0) * DKH;
    const __half* Kg = K  + (size_t)z * SQ * DKH;
    const __half* Vg = Vt + (size_t)z * DKH * SQ;

    const uint32_t qs  = sb;
    const uint32_t st0 = sb + 128 * 144;
    constexpr int VOFF  = 128 * 144;
    constexpr int STAGE = 128 * 144 + 64 * 272;

    auto loadKV = [&](int kt, int stg) {
        const uint32_t base = st0 + (uint32_t)stg * STAGE;
        #pragma unroll
        for (int idx = tid; idx < 128 * 8; idx += 256) {
            const int r = idx >> 3, ch = idx & 7;
            cp16(base + (uint32_t)r * 144 + ch * 16,
                 Kg + ((size_t)(kt * 128 + r)) * DKH + ch * 8);
        }
        #pragma unroll
        for (int idx = tid; idx < 64 * 16; idx += 256) {
            const int r = idx >> 4, ch = idx & 15;
            cp16(base + VOFF + (uint32_t)r * 272 + ch * 16,
                 Vg + (size_t)r * SQ + kt * 128 + ch * 8);
        }
    };

    #pragma unroll
    for (int idx = tid; idx < 128 * 8; idx += 256) {
        const int r = idx >> 3, ch = idx & 7;
        cp16(qs + (uint32_t)r * 144 + ch * 16, Qg + (size_t)r * DKH + ch * 8);
    }
    loadKV(0, 0);
    cp_commit();

    const int a_r = lane & 15;
    const int a_c = ((lane >> 4) & 1) << 3;
    const int b_r = (lane & 7) + (((lane >> 4) & 1) << 3);
    const int b_c = ((lane >> 3) & 1) << 3;

    float m0 = -3.4e38f, m1 = -3.4e38f, s0 = 0.f, s1 = 0.f;

    float ctx[8][4];
    #pragma unroll
    for (int i = 0; i < 8; i++)
        #pragma unroll
        for (int r = 0; r < 4; r++) ctx[i][r] = 0.f;

    for (int kt = 0; kt < SQ / 128; kt++) {
        const int buf = kt & 1;
        if (kt + 1 < SQ / 128) { loadKV(kt + 1, buf ^ 1); cp_commit(); cp_wait1(); }
        else cp_wait0();
        __syncthreads();

        const uint32_t kb = st0 + (uint32_t)buf * STAGE;
        const uint32_t vb = kb + VOFF;

        #pragma unroll
        for (int half = 0; half < 2; half++) {
            float acc[8][4];
            #pragma unroll
            for (int nt = 0; nt < 8; nt++)
                acc[nt][0] = acc[nt][1] = acc[nt][2] = acc[nt][3] = 0.f;

            #pragma unroll
            for (int ksx = 0; ksx < 4; ksx++) {
                uint32_t ah[4];
                LDMX4(ah, qs + ((uint32_t)(wbase + a_r) * 72 + ksx * 16 + a_c) * 2);
                uint32_t bh[8][2];
                #pragma unroll
                for (int np = 0; np < 4; np++) {
                    const int npg = half * 4 + np;
                    uint32_t r4[4];
                    LDMX4(r4, kb + ((uint32_t)(npg * 16 + b_r) * 72 + ksx * 16 + b_c) * 2);
                    bh[np*2][0]   = r4[0]; bh[np*2][1]   = r4[1];
                    bh[np*2+1][0] = r4[2]; bh[np*2+1][1] = r4[3];
                }
                #pragma unroll
                for (int nt = 0; nt < 8; nt++) mma_f16(acc[nt], ah, bh[nt]);
            }

            float mx0 = -3.4e38f, mx1 = -3.4e38f;
            #pragma unroll
            for (int nt = 0; nt < 8; nt++) {
                mx0 = fmaxf(mx0, fmaxf(acc[nt][0], acc[nt][1]));
                mx1 = fmaxf(mx1, fmaxf(acc[nt][2], acc[nt][3]));
            }
            mx0 = fmaxf(mx0, __shfl_xor_sync(0xFFFFFFFFu, mx0, 1));
            mx0 = fmaxf(mx0, __shfl_xor_sync(0xFFFFFFFFu, mx0, 2));
            mx1 = fmaxf(mx1, __shfl_xor_sync(0xFFFFFFFFu, mx1, 1));
            mx1 = fmaxf(mx1, __shfl_xor_sync(0xFFFFFFFFu, mx1, 2));
            const float nm0 = fmaxf(m0, mx0);
            const float nm1 = fmaxf(m1, mx1);
            const float f0 = ex2(m0 - nm0);
            const float f1 = ex2(m1 - nm1);
            m0 = nm0; m1 = nm1;

            #pragma unroll
            for (int i = 0; i < 8; i++) {
                ctx[i][0] *= f0; ctx[i][1] *= f0;
                ctx[i][2] *= f1; ctx[i][3] *= f1;
            }

            uint32_t pf[8][2];
            float t0 = 0.f, t1 = 0.f;
            #pragma unroll
            for (int nt = 0; nt < 8; nt++) {
                const float p0 = ex2(acc[nt][0] - nm0);
                const float p1 = ex2(acc[nt][1] - nm0);
                const float p2 = ex2(acc[nt][2] - nm1);
                const float p3 = ex2(acc[nt][3] - nm1);
                t0 += p0 + p1;
                t1 += p2 + p3;
                __half2 u0 = __floats2half2_rn(p0, p1);
                __half2 u1 = __floats2half2_rn(p2, p3);
                pf[nt][0] = *(uint32_t*)&u0;
                pf[nt][1] = *(uint32_t*)&u1;
            }
            t0 += __shfl_xor_sync(0xFFFFFFFFu, t0, 1);
            t0 += __shfl_xor_sync(0xFFFFFFFFu, t0, 2);
            t1 += __shfl_xor_sync(0xFFFFFFFFu, t1, 1);
            t1 += __shfl_xor_sync(0xFFFFFFFFu, t1, 2);
            s0 = s0 * f0 + t0;
            s1 = s1 * f1 + t1;

            #pragma unroll
            for (int kc = 0; kc < 4; kc++) {
                uint32_t af[4] = {pf[2*kc][0], pf[2*kc][1], pf[2*kc+1][0], pf[2*kc+1][1]};
                const int kk = half * 4 + kc;
                #pragma unroll
                for (int np = 0; np < 4; np++) {
                    uint32_t r4[4];
                    LDMX4(r4, vb + ((uint32_t)(np * 16 + b_r) * 272 + (kk * 16 + b_c) * 2));
                    uint32_t b0[2] = {r4[0], r4[1]};
                    uint32_t b1[2] = {r4[2], r4[3]};
                    mma_f16(ctx[2*np],     af, b0);
                    mma_f16(ctx[2*np + 1], af, b1);
                }
            }
        }
        __syncthreads();
    }

    const float is0 = 1.f / s0;
    const float is1 = 1.f / s1;
    const int b = z >> 4, hh = z & 15;
    const int row0 = q0 + wbase + g;
    #pragma unroll
    for (int nt = 0; nt < 8; nt++) {
        const int col = hh * DKH + nt * 8 + tg * 2;
        __half2 u0 = __floats2half2_rn(ctx[nt][0] * is0, ctx[nt][1] * is0);
        __half2 u1 = __floats2half2_rn(ctx[nt][2] * is1, ctx[nt][3] * is1);
        *(__half2*)(Ch + ((size_t)row0 * NB + b) * DM + col)       = u0;
        *(__half2*)(Ch + ((size_t)(row0 + 8) * NB + b) * DM + col) = u1;
    }
    if (tg == 0) {
        stats[(size_t)z * SQ + row0]     = make_float2(m0, is0);
        stats[(size_t)z * SQ + row0 + 8] = make_float2(m1, is1);
    }
}

// ---------------------------------------------------------------------------
// mean body (device): head-mean of probs for one (b, q-tile 128, k-tile 64).
// ---------------------------------------------------------------------------
__device__ __forceinline__ void mean_body(
    const __half* __restrict__ Q, const __half* __restrict__ K,
    const float2* __restrict__ stats, float* __restrict__ outMean,
    int b, int q0, int k0, char* smem)
{
    const uint32_t sb = smem_u32(smem);
    const int tid = threadIdx.x, lane = tid & 31, wid = tid >> 5;
    const int g = lane >> 2, tg = lane & 3;
    const int wm = wid & 3, wn = wid >> 2;
    const int mbase = wm * 32, nbase = wn * 32;
    constexpr int STG = (128 + 64) * 144;

    const int a_r = lane & 15;
    const int a_c = ((lane >> 4) & 1) << 3;
    const int b_r = (lane & 7) + (((lane >> 4) & 1) << 3);
    const int b_c = ((lane >> 3) & 1) << 3;

    auto load_tiles = [&](int h, int stg) {
        const int z = (b << 4) + h;
        const __half* Qg = Q + ((size_t)z * SQ + q0) * DKH;
        const __half* Kg = K + ((size_t)z * SQ + k0) * DKH;
        const uint32_t base = sb + (uint32_t)stg * STG;
        #pragma unroll
        for (int idx = tid; idx < 128 * 8; idx += 256) {
            const int r = idx >> 3, ch = idx & 7;
            cp16(base + (uint32_t)r * 144 + ch * 16, Qg + (size_t)r * DKH + ch * 8);
        }
        #pragma unroll
        for (int idx = tid; idx < 64 * 8; idx += 256) {
            const int r = idx >> 3, ch = idx & 7;
            cp16(base + 128 * 144 + (uint32_t)r * 144 + ch * 16, Kg + (size_t)r * DKH + ch * 8);
        }
    };

    float macc[2][4][4];
    #pragma unroll
    for (int i = 0; i < 2; i++)
        #pragma unroll
        for (int j = 0; j < 4; j++)
            #pragma unroll
            for (int r = 0; r < 4; r++) macc[i][j][r] = 0.f;

    load_tiles(0, 0);
    cp_commit();

    for (int h = 0; h < 16; h++) {
        const int st = h & 1;
        if (h + 1 < 16) { load_tiles(h + 1, st ^ 1); cp_commit(); cp_wait1(); }
        else cp_wait0();
        __syncthreads();

        const uint32_t sQ = sb + (uint32_t)st * STG;
        const uint32_t sK = sQ + 128 * 144;

        float acc[2][4][4];
        #pragma unroll
        for (int i = 0; i < 2; i++)
            #pragma unroll
            for (int j = 0; j < 4; j++)
                #pragma unroll
                for (int r = 0; r < 4; r++) acc[i][j][r] = 0.f;

        #pragma unroll
        for (int ksx = 0; ksx < 4; ksx++) {
            uint32_t ah[2][4], bh[4][2];
            #pragma unroll
            for (int mt = 0; mt < 2; mt++) {
                const uint32_t off = ((uint32_t)(mbase + mt * 16 + a_r) * 72 + ksx * 16 + a_c) * 2;
                LDMX4(ah[mt], sQ + off);
            }
            #pragma unroll
            for (int np = 0; np < 2; np++) {
                const uint32_t off = ((uint32_t)(nbase + np * 16 + b_r) * 72 + ksx * 16 + b_c) * 2;
                uint32_t r4[4];
                LDMX4(r4, sK + off);
                bh[np*2][0]   = r4[0]; bh[np*2][1]   = r4[1];
                bh[np*2+1][0] = r4[2]; bh[np*2+1][1] = r4[3];
            }
            #pragma unroll
            for (int mt = 0; mt < 2; mt++)
                #pragma unroll
                for (int nt = 0; nt < 4; nt++)
                    mma_f16(acc[mt][nt], ah[mt], bh[nt]);
        }

        const int z = (b << 4) + h;
        const float2* strow = stats + (size_t)z * SQ + q0;
        #pragma unroll
        for (int mt = 0; mt < 2; mt++) {
            const int r0 = mbase + mt * 16 + g;
            const float2 st0 = strow[r0];
            const float2 st1 = strow[r0 + 8];
            #pragma unroll
            for (int nt = 0; nt < 4; nt++) {
                macc[mt][nt][0] += ex2(acc[mt][nt][0] - st0.x) * st0.y;
                macc[mt][nt][1] += ex2(acc[mt][nt][1] - st0.x) * st0.y;
                macc[mt][nt][2] += ex2(acc[mt][nt][2] - st1.x) * st1.y;
                macc[mt][nt][3] += ex2(acc[mt][nt][3] - st1.x) * st1.y;
            }
        }
        __syncthreads();
    }

    float* om = outMean + (size_t)b * SQ * SQ;
    #pragma unroll
    for (int mt = 0; mt < 2; mt++) {
        const int r0 = mbase + mt * 16 + g;
        #pragma unroll
        for (int nt = 0; nt < 4; nt++) {
            const int col = nbase + nt * 8 + tg * 2;
            *(float2*)&om[(size_t)(q0 + r0) * SQ + k0 + col] =
                make_float2(macc[mt][nt][0] * (1.0f / NH), macc[mt][nt][1] * (1.0f / NH));
            *(float2*)&om[(size_t)(q0 + r0 + 8) * SQ + k0 + col] =
                make_float2(macc[mt][nt][2] * (1.0f / NH), macc[mt][nt][3] * (1.0f / NH));
        }
    }
}

// ---------------------------------------------------------------------------
// Merged wo + mean launch: z in {0,1} -> mean tiles; z == 2 -> Wo GEMM tiles.
// ---------------------------------------------------------------------------
__global__ void __launch_bounds__(256, 2)
wo_mean(const __half* __restrict__ ctx, const __half* __restrict__ Wo,
        float* __restrict__ out,
        const __half* __restrict__ Q, const __half* __restrict__ K,
        const float2* __restrict__ stats, float* __restrict__ outMean)
{
    extern __shared__ __align__(16) char smem[];
    const int z = blockIdx.z;
    if (z < NB) {
        mean_body(Q, K, stats, outMean, z, blockIdx.y * 128, blockIdx.x * 64, smem);
    } else {
        const int idx = blockIdx.y * 32 + blockIdx.x;
        if (idx >= (MR / 128) * (DM / 128)) return;
        const int m0 = (idx >> 3) * 128, n0 = (idx & 7) * 128;
        gemm_body3<128, 128, 0>(ctx + (size_t)m0 * DM, Wo + (size_t)n0 * DM,
                                out, nullptr, DM, DM, 1.0f, m0, n0, smem);
    }
}

// ---------------------------------------------------------------------------
// fused fp32 -> fp16 conversion (7 segments via grid.z)
// ---------------------------------------------------------------------------
__global__ void __launch_bounds__(256)
cvt_all(const float* __restrict__ i0, const float* __restrict__ i1, const float* __restrict__ i2,
        const float* __restrict__ i3, const float* __restrict__ i4, const float* __restrict__ i5,
        const float* __restrict__ i6,
        __half* __restrict__ o0, __half* __restrict__ o1, __half* __restrict__ o2,
        __half* __restrict__ o3, __half* __restrict__ o4, __half* __restrict__ o5,
        __half* __restrict__ o6)
{
    const int zi = blockIdx.z;
    const float* s;
    __half* d;
    int n;
    switch (zi) {
        case 0: s = i0; d = o0; n = MR * DM; break;
        case 1: s = i1; d = o1; n = MR * DM; break;
        case 2: s = i2; d = o2; n = MR * DM; break;
        case 3: s = i3; d = o3; n = DM * DM; break;
        case 4: s = i4; d = o4; n = DM * DM; break;
        case 5: s = i5; d = o5; n = DM * DM; break;
        default: s = i6; d = o6; n = DM * DM; break;
    }
    const int i = (blockIdx.x * 256 + threadIdx.x) * 4;
    if (i >= n) return;
    float4 v = *(const float4*)(s + i);
    __half2 p0 = __halves2half2(__float2half_rn(v.x), __float2half_rn(v.y));
    __half2 p1 = __halves2half2(__float2half_rn(v.z), __float2half_rn(v.w));
    uint2 u = {*(uint32_t*)&p0, *(uint32_t*)&p1};
    *(uint2*)(d + i) = u;
}

// ---------------------------------------------------------------------------
extern "C" void kernel_launch(void* const* d_in, const int* in_sizes, int n_in,
                              void* d_out, int out_size)
{
    (void)in_sizes; (void)n_in; (void)out_size;
    const float* q  = (const float*)d_in[0];
    const float* k  = (const float*)d_in[1];
    const float* v  = (const float*)d_in[2];
    const float* Wq = (const float*)d_in[3];
    const float* Wk = (const float*)d_in[4];
    const float* Wv = (const float*)d_in[5];
    const float* Wo = (const float*)d_in[6];
    float* out     = (float*)d_out;
    float* outMean = out + (size_t)MR * DM;

    #define SYM(p, s) void* p; cudaGetSymbolAddress(&p, s)
    SYM(pqx, g_qx); SYM(pkx, g_kx); SYM(pvx, g_vx);
    SYM(pwq, g_wq); SYM(pwk, g_wk); SYM(pwv, g_wv); SYM(pwo, g_wo);
    SYM(pQ, g_Q); SYM(pK, g_K); SYM(pVt, g_Vt);
    SYM(pstats, g_stats); SYM(pc, g_c);
    #undef SYM

    const int SMEM_PROJ  = 3 * (128 + 128) * 144;                  // 110592
    const int SMEM_FLASH = 128 * 144 + 2 * (128 * 144 + 64 * 272); // 90112
    const int SMEM_WOME  = 3 * (128 + 128) * 144;                  // 110592 (wo 3-stage; mean needs 55296)
    cudaFuncSetAttribute(hm_proj,   cudaFuncAttributeMaxDynamicSharedMemorySize, SMEM_PROJ);
    cudaFuncSetAttribute(flash_pv,  cudaFuncAttributeMaxDynamicSharedMemorySize, SMEM_FLASH);
    cudaFuncSetAttribute(wo_mean,   cudaFuncAttributeMaxDynamicSharedMemorySize, SMEM_WOME);

    // 1) fp32 -> fp16 conversions (single launch, 7 segments)
    cvt_all<<<dim3(MR * DM / 1024, 1, 7), 256>>>(
        q, k, v, Wq, Wk, Wv, Wo,
        (__half*)pqx, (__half*)pkx, (__half*)pvx,
        (__half*)pwq, (__half*)pwk, (__half*)pwv, (__half*)pwo);

    // 2) fused Q/K/V projections (3-stage; Q pre-scaled; V written to Vt directly)
    hm_proj<<<dim3(DM / 128, MR / 128, 3), 256, SMEM_PROJ>>>(
        (const __half*)pqx, (const __half*)pkx, (const __half*)pvx,
        (const __half*)pwq, (const __half*)pwk, (const __half*)pwv,
        (__half*)pQ, (__half*)pK, (__half*)pVt);

    // 3) online flash attention: ctx + stats in one pass
    flash_pv<<<dim3(1, SQ / 128, NZ), 256, SMEM_FLASH>>>(
        (const __half*)pQ, (const __half*)pK, (const __half*)pVt,
        (float2*)pstats, (__half*)pc);

    // 4) merged: out = ctx @ Wo^T  (z=2)  +  head mean (z=0,1), concurrent
    wo_mean<<<dim3(SQ / 64, SQ / 128, NB + 1), 256, SMEM_WOME>>>(
        (const __half*)pc, (const __half*)pwo, out,
        (const __half*)pQ, (const __half*)pK, (const float2*)pstats, outMean);
}